// round 1
// baseline (speedup 1.0000x reference)
#include <cuda_runtime.h>
#include <math.h>

// ---------------- problem constants ----------------
#define NMAX 20000
#define EMAX 320000
#define DIM 256
#define HEADS 8
#define HDIM 32

// ---------------- scratch (static device globals; no allocation) ----------------
__device__ float g_h0[NMAX * 32];
__device__ float g_xl[NMAX * DIM];
__device__ float g_xr[NMAX * DIM];
__device__ float g_agg[NMAX * DIM];
__device__ float g_h1[NMAX * DIM];
__device__ float g_z[NMAX * DIM];
__device__ float g_z2[NMAX * DIM];
__device__ float g_tmp[NMAX * DIM];
__device__ float g_score[EMAX * HEADS];
__device__ float g_m[NMAX * HEADS];
__device__ float g_s[NMAX * HEADS];

// ---------------- helpers ----------------
__device__ __forceinline__ void atomicMaxFloat(float* addr, float val) {
    // ordered-int trick; buffer initialized to -INF
    if (val >= 0.f) atomicMax((int*)addr, __float_as_int(val));
    else            atomicMin((unsigned int*)addr, (unsigned int)__float_as_int(val));
}

__device__ __forceinline__ float warpReduceSum(float v) {
#pragma unroll
    for (int o = 16; o > 0; o >>= 1) v += __shfl_xor_sync(0xffffffffu, v, o);
    return v;
}

// ---------------- fill ----------------
__global__ void fill_kernel(float* __restrict__ p, float v, int n) {
    int i = blockIdx.x * blockDim.x + threadIdx.x;
    if (i < n) p[i] = v;
}

// ---------------- tiled SGEMM: C = A[M,K] @ B[K,N] (+bias) ----------------
#define BM 64
#define BN 64
#define BK 16
__global__ void sgemm_kernel(const float* __restrict__ A, const float* __restrict__ B,
                             const float* __restrict__ bias, float* __restrict__ C,
                             int M, int N, int K) {
    __shared__ float As[BK][BM + 4];   // +4 keeps 16B alignment of rows, kills STS conflicts
    __shared__ float Bs[BK][BN];
    int tid = threadIdx.x;              // 256 threads
    int tr = tid >> 4, tc = tid & 15;   // 16x16 thread grid; 4x4 micro-tile each
    int row0 = blockIdx.y * BM, col0 = blockIdx.x * BN;
    float acc[4][4] = {};
    int ntile = (K + BK - 1) / BK;
    for (int t = 0; t < ntile; t++) {
        int k0 = t * BK;
        // A tile: thread loads 4 consecutive k of one row (coalesced in k)
        {
            int r = tid >> 2;
            int gr = row0 + r;
#pragma unroll
            for (int i = 0; i < 4; i++) {
                int kk = ((tid & 3) << 2) + i;
                int gk = k0 + kk;
                As[kk][r] = (gr < M && gk < K) ? A[(size_t)gr * K + gk] : 0.f;
            }
        }
        // B tile: consecutive tid -> consecutive columns (coalesced)
#pragma unroll
        for (int i = 0; i < 4; i++) {
            int idx = tid + i * 256;
            int c = idx & 63, kk = idx >> 6;
            int gk = k0 + kk, gc = col0 + c;
            Bs[kk][c] = (gk < K && gc < N) ? B[(size_t)gk * N + gc] : 0.f;
        }
        __syncthreads();
#pragma unroll
        for (int kk = 0; kk < BK; kk++) {
            float a[4], b[4];
#pragma unroll
            for (int i = 0; i < 4; i++) a[i] = As[kk][tr * 4 + i];
#pragma unroll
            for (int j = 0; j < 4; j++) b[j] = Bs[kk][tc * 4 + j];
#pragma unroll
            for (int i = 0; i < 4; i++)
#pragma unroll
                for (int j = 0; j < 4; j++) acc[i][j] += a[i] * b[j];
        }
        __syncthreads();
    }
#pragma unroll
    for (int i = 0; i < 4; i++) {
        int gr = row0 + tr * 4 + i;
        if (gr >= M) continue;
#pragma unroll
        for (int j = 0; j < 4; j++) {
            int gc = col0 + tc * 4 + j;
            if (gc < N) C[(size_t)gr * N + gc] = acc[i][j] + (bias ? bias[gc] : 0.f);
        }
    }
}

// ---------------- edge pass A: scores + segment max ----------------
// warp per edge; i = h*32 + lane
__global__ void edge_score_kernel(const float* __restrict__ xl, const float* __restrict__ xr,
                                  const float* __restrict__ ea, const float* __restrict__ We,
                                  const float* __restrict__ att,
                                  const int* __restrict__ src, const int* __restrict__ dst,
                                  float* __restrict__ score, float* __restrict__ mbuf, int E) {
    int warp = (blockIdx.x * blockDim.x + threadIdx.x) >> 5;
    int lane = threadIdx.x & 31;
    if (warp >= E) return;
    int s = src[warp], d = dst[warp];
    float a = ea[warp];
    const float* xls = xl + (size_t)s * DIM;
    const float* xrd = xr + (size_t)d * DIM;
#pragma unroll
    for (int h = 0; h < HEADS; h++) {
        int i = h * 32 + lane;
        float v = xls[i] + xrd[i] + a * We[i];
        v = v > 0.f ? v : 0.2f * v;          // leaky_relu(0.2)
        float p = warpReduceSum(v * att[i]);
        if (lane == 0) {
            score[(size_t)warp * HEADS + h] = p;
            atomicMaxFloat(&mbuf[d * HEADS + h], p);
        }
    }
}

// ---------------- edge pass B: exp + segment sum ----------------
__global__ void edge_exp_kernel(float* __restrict__ score, const float* __restrict__ m,
                                float* __restrict__ ssum, const int* __restrict__ dst, int E) {
    int idx = blockIdx.x * blockDim.x + threadIdx.x;
    if (idx >= E * HEADS) return;
    int e = idx >> 3, h = idx & 7;
    int d = dst[e];
    float ex = __expf(score[idx] - m[d * HEADS + h]);
    score[idx] = ex;
    atomicAdd(&ssum[d * HEADS + h], ex);
}

// ---------------- edge pass C: weighted aggregation ----------------
__global__ void edge_agg_kernel(const float* __restrict__ score, const float* __restrict__ ssum,
                                const float* __restrict__ xl,
                                const int* __restrict__ src, const int* __restrict__ dst,
                                float* __restrict__ agg, int E) {
    int warp = (blockIdx.x * blockDim.x + threadIdx.x) >> 5;
    int lane = threadIdx.x & 31;
    if (warp >= E) return;
    int s = src[warp], d = dst[warp];
    const float* xls = xl + (size_t)s * DIM;
    float* aggd = agg + (size_t)d * DIM;
#pragma unroll
    for (int h = 0; h < HEADS; h++) {
        float al = score[(size_t)warp * HEADS + h] / (ssum[d * HEADS + h] + 1e-16f);
        atomicAdd(&aggd[h * 32 + lane], al * xls[h * 32 + lane]);
    }
}

// ---------------- layernorm (dim=256), optional residual + bias pre-add ----------------
__global__ void ln_kernel(const float* __restrict__ x, const float* __restrict__ res,
                          const float* __restrict__ bias, const float* __restrict__ g,
                          const float* __restrict__ b, float* __restrict__ out, int n) {
    int row = blockIdx.x * 8 + (threadIdx.x >> 5);
    int lane = threadIdx.x & 31;
    if (row >= n) return;
    const float* xr = x + (size_t)row * DIM;
    float v[8];
    float sum = 0.f;
#pragma unroll
    for (int k = 0; k < 8; k++) {
        int i = k * 32 + lane;
        float t = xr[i];
        if (res)  t += res[(size_t)row * DIM + i];
        if (bias) t += bias[i];
        v[k] = t;
        sum += t;
    }
    sum = warpReduceSum(sum);
    float mu = sum * (1.f / 256.f);
    float var = 0.f;
#pragma unroll
    for (int k = 0; k < 8; k++) { float dd = v[k] - mu; var += dd * dd; }
    var = warpReduceSum(var) * (1.f / 256.f);
    float inv = rsqrtf(var + 1e-5f);
#pragma unroll
    for (int k = 0; k < 8; k++) {
        int i = k * 32 + lane;
        out[(size_t)row * DIM + i] = (v[k] - mu) * inv * g[i] + b[i];
    }
}

// ---------------- host ----------------
static inline void launch_gemm(const float* A, const float* B, const float* bias, float* C,
                               int M, int N, int K) {
    dim3 grid((N + BN - 1) / BN, (M + BM - 1) / BM);
    sgemm_kernel<<<grid, 256>>>(A, B, bias, C, M, N, K);
}

extern "C" void kernel_launch(void* const* d_in, const int* in_sizes, int n_in,
                              void* d_out, int out_size) {
    const float* x_gnn = (const float*)d_in[0];
    const int*   eidx  = (const int*)d_in[1];
    const float* eattr = (const float*)d_in[2];
    const float* W_in  = (const float*)d_in[3];
    const float* b_in  = (const float*)d_in[4];
    const float* Wl1   = (const float*)d_in[5];
    const float* Wr1   = (const float*)d_in[6];
    const float* We1   = (const float*)d_in[7];
    const float* att1  = (const float*)d_in[8];
    const float* bg1   = (const float*)d_in[9];
    const float* ln1_g = (const float*)d_in[10];
    const float* ln1_b = (const float*)d_in[11];
    const float* W_down= (const float*)d_in[12];
    const float* lnd_g = (const float*)d_in[13];
    const float* lnd_b = (const float*)d_in[14];
    const float* Wl2   = (const float*)d_in[15];
    const float* Wr2   = (const float*)d_in[16];
    const float* We2   = (const float*)d_in[17];
    const float* att2  = (const float*)d_in[18];
    const float* bg2   = (const float*)d_in[19];
    const float* ln2_g = (const float*)d_in[20];
    const float* ln2_b = (const float*)d_in[21];
    const float* W_up  = (const float*)d_in[22];
    const float* lnu_g = (const float*)d_in[23];
    const float* lnu_b = (const float*)d_in[24];
    const float* W_cls = (const float*)d_in[25];
    const float* b_cls = (const float*)d_in[26];

    const int n = in_sizes[0] / 18;        // 20000
    const int E = in_sizes[1] / 2;         // 320000
    const int* src = eidx;
    const int* dst = eidx + E;

    float *h0, *xl, *xr, *agg, *h1, *z, *z2, *tmp, *score, *mb, *sb;
    cudaGetSymbolAddress((void**)&h0, g_h0);
    cudaGetSymbolAddress((void**)&xl, g_xl);
    cudaGetSymbolAddress((void**)&xr, g_xr);
    cudaGetSymbolAddress((void**)&agg, g_agg);
    cudaGetSymbolAddress((void**)&h1, g_h1);
    cudaGetSymbolAddress((void**)&z, g_z);
    cudaGetSymbolAddress((void**)&z2, g_z2);
    cudaGetSymbolAddress((void**)&tmp, g_tmp);
    cudaGetSymbolAddress((void**)&score, g_score);
    cudaGetSymbolAddress((void**)&mb, g_m);
    cudaGetSymbolAddress((void**)&sb, g_s);

    float* out_logits = (float*)d_out;
    float* out_h = (float*)d_out + (size_t)n * 1000;

    const int edgeBlocks = (E + 7) / 8;          // warp per edge, 8 warps/block
    const int lnBlocks = (n + 7) / 8;
    const int nh = n * HEADS;
    const int nd = n * DIM;

    // ---- input projection ----
    launch_gemm(x_gnn, W_in, b_in, h0, n, 32, 18);

    // ---- GAT layer 1 ----
    launch_gemm(h0, Wl1, nullptr, xl, n, DIM, 32);
    launch_gemm(h0, Wr1, nullptr, xr, n, DIM, 32);
    fill_kernel<<<(nh + 255) / 256, 256>>>(mb, -INFINITY, nh);
    fill_kernel<<<(nh + 255) / 256, 256>>>(sb, 0.f, nh);
    fill_kernel<<<(nd + 255) / 256, 256>>>(agg, 0.f, nd);
    edge_score_kernel<<<edgeBlocks, 256>>>(xl, xr, eattr, We1, att1, src, dst, score, mb, E);
    edge_exp_kernel<<<(E * HEADS + 255) / 256, 256>>>(score, mb, sb, dst, E);
    edge_agg_kernel<<<edgeBlocks, 256>>>(score, sb, xl, src, dst, agg, E);
    ln_kernel<<<lnBlocks, 256>>>(agg, nullptr, bg1, ln1_g, ln1_b, h1, n);  // h1 = LN(g1 + bg1)

    // ---- bottleneck down ----
    launch_gemm(h1, W_down, nullptr, tmp, n, DIM, DIM);
    ln_kernel<<<lnBlocks, 256>>>(tmp, nullptr, nullptr, lnd_g, lnd_b, z, n);

    // ---- GAT layer 2 ----
    launch_gemm(z, Wl2, nullptr, xl, n, DIM, DIM);
    launch_gemm(z, Wr2, nullptr, xr, n, DIM, DIM);
    fill_kernel<<<(nh + 255) / 256, 256>>>(mb, -INFINITY, nh);
    fill_kernel<<<(nh + 255) / 256, 256>>>(sb, 0.f, nh);
    fill_kernel<<<(nd + 255) / 256, 256>>>(agg, 0.f, nd);
    edge_score_kernel<<<edgeBlocks, 256>>>(xl, xr, eattr, We2, att2, src, dst, score, mb, E);
    edge_exp_kernel<<<(E * HEADS + 255) / 256, 256>>>(score, mb, sb, dst, E);
    edge_agg_kernel<<<edgeBlocks, 256>>>(score, sb, xl, src, dst, agg, E);
    ln_kernel<<<lnBlocks, 256>>>(agg, z, bg2, ln2_g, ln2_b, z2, n);        // z2 = LN(g2 + bg2 + z)

    // ---- up projection + final LN (writes h output) ----
    launch_gemm(z2, W_up, nullptr, tmp, n, DIM, DIM);
    ln_kernel<<<lnBlocks, 256>>>(tmp, h1, nullptr, lnu_g, lnu_b, out_h, n); // h = LN(h1 + h2)

    // ---- classifier ----
    launch_gemm(out_h, W_cls, b_cls, out_logits, n, 1000, DIM);
}

// round 2
// speedup vs baseline: 1.1826x; 1.1826x over previous
#include <cuda_runtime.h>
#include <math.h>

// ---------------- problem constants ----------------
#define NMAX 20000
#define EMAX 320000
#define DIM 256
#define HEADS 8

// ---------------- scratch ----------------
__device__ float g_h0[NMAX * 32];
__device__ float g_xl[NMAX * DIM];
__device__ float g_xr[NMAX * DIM];
__device__ float g_agg[NMAX * DIM];
__device__ float g_h1[NMAX * DIM];
__device__ float g_z[NMAX * DIM];
__device__ float g_z2[NMAX * DIM];
__device__ float g_tmp[NMAX * DIM];
__device__ float g_score[EMAX * HEADS];
__device__ float g_s[NMAX * HEADS];

// ---------------- helpers ----------------
__device__ __forceinline__ float warpReduceSum(float v) {
#pragma unroll
    for (int o = 16; o > 0; o >>= 1) v += __shfl_xor_sync(0xffffffffu, v, o);
    return v;
}

__device__ __forceinline__ void redAdd4(float* addr, float4 v) {
    asm volatile("red.global.add.v4.f32 [%0], {%1,%2,%3,%4};"
                 :: "l"(addr), "f"(v.x), "f"(v.y), "f"(v.z), "f"(v.w) : "memory");
}

__device__ __forceinline__ float leaky(float v) { return v > 0.f ? v : 0.2f * v; }

// ---------------- fill ----------------
__global__ void fill_kernel(float* __restrict__ p, float v, int n) {
    int i = blockIdx.x * blockDim.x + threadIdx.x;
    if (i < n) p[i] = v;
}

// ---------------- SGEMM 128x128x8, 8x8 micro, double-buffered ----------------
#define TBM 128
#define TBN 128
#define TBK 8
__global__ __launch_bounds__(256)
void sgemm128(const float* __restrict__ A, const float* __restrict__ B,
              const float* __restrict__ bias, float* __restrict__ C,
              int M, int N, int K) {
    __shared__ float As[2][TBK][TBM];
    __shared__ float Bs[2][TBK][TBN];
    const int tid = threadIdx.x;
    const int row0 = blockIdx.y * TBM, col0 = blockIdx.x * TBN;
    const int tr = tid >> 4, tc = tid & 15;
    const int arow = tid >> 1, ak = (tid & 1) << 2;
    const int bk = tid >> 5, bcol = (tid & 31) << 2;
    const int ntile = (K + TBK - 1) / TBK;
    const bool a4ok = ((K & 3) == 0);

    float acc[8][8];
#pragma unroll
    for (int i = 0; i < 8; i++)
#pragma unroll
        for (int j = 0; j < 8; j++) acc[i][j] = 0.f;

    float4 aR, bR;
    // prologue: tile 0
    {
        int gr = row0 + arow;
        aR = make_float4(0.f, 0.f, 0.f, 0.f);
        if (gr < M) {
            if (a4ok && ak + 3 < K) aR = *(const float4*)(A + (size_t)gr * K + ak);
            else {
                float* av = (float*)&aR;
#pragma unroll
                for (int i = 0; i < 4; i++) { int gk = ak + i; if (gk < K) av[i] = A[(size_t)gr * K + gk]; }
            }
        }
        int gc = col0 + bcol;
        bR = make_float4(0.f, 0.f, 0.f, 0.f);
        if (bk < K) {
            if (gc + 3 < N) bR = *(const float4*)(B + (size_t)bk * N + gc);
            else { float* bv = (float*)&bR;
#pragma unroll
                for (int i = 0; i < 4; i++) { int c = gc + i; if (c < N) bv[i] = B[(size_t)bk * N + c]; } }
        }
        As[0][ak + 0][arow] = aR.x; As[0][ak + 1][arow] = aR.y;
        As[0][ak + 2][arow] = aR.z; As[0][ak + 3][arow] = aR.w;
        *(float4*)&Bs[0][bk][bcol] = bR;
    }
    __syncthreads();

    for (int t = 0; t < ntile; t++) {
        int cur = t & 1, nxt = cur ^ 1;
        if (t + 1 < ntile) {
            int k0 = (t + 1) * TBK;
            int gr = row0 + arow;
            aR = make_float4(0.f, 0.f, 0.f, 0.f);
            if (gr < M) {
                if (a4ok && k0 + ak + 3 < K) aR = *(const float4*)(A + (size_t)gr * K + k0 + ak);
                else { float* av = (float*)&aR;
#pragma unroll
                    for (int i = 0; i < 4; i++) { int gk = k0 + ak + i; if (gk < K) av[i] = A[(size_t)gr * K + gk]; } }
            }
            int gk = k0 + bk;
            int gc = col0 + bcol;
            bR = make_float4(0.f, 0.f, 0.f, 0.f);
            if (gk < K) {
                if (gc + 3 < N) bR = *(const float4*)(B + (size_t)gk * N + gc);
                else { float* bv = (float*)&bR;
#pragma unroll
                    for (int i = 0; i < 4; i++) { int c = gc + i; if (c < N) bv[i] = B[(size_t)gk * N + c]; } }
            }
        }
#pragma unroll
        for (int kk = 0; kk < TBK; kk++) {
            float4 a0 = *(const float4*)&As[cur][kk][tr * 8];
            float4 a1 = *(const float4*)&As[cur][kk][tr * 8 + 4];
            float4 b0 = *(const float4*)&Bs[cur][kk][tc * 8];
            float4 b1 = *(const float4*)&Bs[cur][kk][tc * 8 + 4];
            float av[8] = {a0.x, a0.y, a0.z, a0.w, a1.x, a1.y, a1.z, a1.w};
            float bv[8] = {b0.x, b0.y, b0.z, b0.w, b1.x, b1.y, b1.z, b1.w};
#pragma unroll
            for (int i = 0; i < 8; i++)
#pragma unroll
                for (int j = 0; j < 8; j++) acc[i][j] = fmaf(av[i], bv[j], acc[i][j]);
        }
        if (t + 1 < ntile) {
            As[nxt][ak + 0][arow] = aR.x; As[nxt][ak + 1][arow] = aR.y;
            As[nxt][ak + 2][arow] = aR.z; As[nxt][ak + 3][arow] = aR.w;
            *(float4*)&Bs[nxt][bk][bcol] = bR;
        }
        __syncthreads();
    }
    // epilogue
#pragma unroll
    for (int i = 0; i < 8; i++) {
        int gr = row0 + tr * 8 + i;
        if (gr >= M) continue;
#pragma unroll
        for (int j = 0; j < 8; j += 4) {
            int gc = col0 + tc * 8 + j;
            if (gc + 3 < N) {
                float4 v = make_float4(acc[i][j], acc[i][j + 1], acc[i][j + 2], acc[i][j + 3]);
                if (bias) { v.x += bias[gc]; v.y += bias[gc + 1]; v.z += bias[gc + 2]; v.w += bias[gc + 3]; }
                *(float4*)(C + (size_t)gr * N + gc) = v;
            } else {
#pragma unroll
                for (int q = 0; q < 4; q++) {
                    int c = gc + q;
                    if (c < N) C[(size_t)gr * N + c] = acc[i][j + q] + (bias ? bias[c] : 0.f);
                }
            }
        }
    }
}

// ---------------- edge pass A: score + exp + segment sum (no max; softmax shift-invariant) ----
__global__ void edge_score_kernel(const float* __restrict__ xl, const float* __restrict__ xr,
                                  const float* __restrict__ ea, const float* __restrict__ We,
                                  const float* __restrict__ att,
                                  const int* __restrict__ src, const int* __restrict__ dst,
                                  float* __restrict__ score, float* __restrict__ ssum, int E) {
    int e = (blockIdx.x * blockDim.x + threadIdx.x) >> 5;
    int lane = threadIdx.x & 31;
    if (e >= E) return;
    int s = src[e], d = dst[e];
    float a = ea[e];
    const float4* xls = (const float4*)(xl + (size_t)s * DIM);
    const float4* xrd = (const float4*)(xr + (size_t)d * DIM);
    const float4* We4 = (const float4*)We;
    const float4* at4 = (const float4*)att;
#pragma unroll
    for (int c = 0; c < 2; c++) {
        int q = c * 32 + lane;
        float4 l = xls[q], r = xrd[q], w = We4[q], t = at4[q];
        float p = leaky(l.x + r.x + a * w.x) * t.x + leaky(l.y + r.y + a * w.y) * t.y
                + leaky(l.z + r.z + a * w.z) * t.z + leaky(l.w + r.w + a * w.w) * t.w;
        p += __shfl_xor_sync(0xffffffffu, p, 1);
        p += __shfl_xor_sync(0xffffffffu, p, 2);
        p += __shfl_xor_sync(0xffffffffu, p, 4);
        if ((lane & 7) == 0) {
            int h = c * 4 + (lane >> 3);
            float ex = __expf(p);
            score[(size_t)e * 8 + h] = ex;
            atomicAdd(&ssum[d * 8 + h], ex);
        }
    }
}

// ---------------- edge pass B: weighted aggregation (vector RED) ----------------
__global__ void edge_agg_kernel(const float* __restrict__ score, const float* __restrict__ ssum,
                                const float* __restrict__ xl,
                                const int* __restrict__ src, const int* __restrict__ dst,
                                float* __restrict__ agg, int E) {
    int e = (blockIdx.x * blockDim.x + threadIdx.x) >> 5;
    int lane = threadIdx.x & 31;
    if (e >= E) return;
    int s = src[e], d = dst[e];
    const float4* xls = (const float4*)(xl + (size_t)s * DIM);
    float* aggd = agg + (size_t)d * DIM;
#pragma unroll
    for (int c = 0; c < 2; c++) {
        int h = c * 4 + (lane >> 3);
        float al = score[(size_t)e * 8 + h] / (ssum[d * 8 + h] + 1e-16f);
        float4 x = xls[c * 32 + lane];
        redAdd4(aggd + c * 128 + lane * 4, make_float4(al * x.x, al * x.y, al * x.z, al * x.w));
    }
}

// ---------------- layernorm (dim=256), vectorized ----------------
__global__ void ln_kernel(const float* __restrict__ x, const float* __restrict__ res,
                          const float* __restrict__ bias, const float* __restrict__ g,
                          const float* __restrict__ b, float* __restrict__ out, int n) {
    int row = blockIdx.x * 8 + (threadIdx.x >> 5);
    int lane = threadIdx.x & 31;
    if (row >= n) return;
    const float4* xr4 = (const float4*)(x + (size_t)row * DIM);
    const float4* rs4 = res ? (const float4*)(res + (size_t)row * DIM) : nullptr;
    const float4* bi4 = bias ? (const float4*)bias : nullptr;
    float4 v[2];
    float sum = 0.f;
#pragma unroll
    for (int k = 0; k < 2; k++) {
        int q = k * 32 + lane;
        float4 t = xr4[q];
        if (rs4) { float4 r = rs4[q]; t.x += r.x; t.y += r.y; t.z += r.z; t.w += r.w; }
        if (bi4) { float4 r = bi4[q]; t.x += r.x; t.y += r.y; t.z += r.z; t.w += r.w; }
        v[k] = t;
        sum += t.x + t.y + t.z + t.w;
    }
    sum = warpReduceSum(sum);
    float mu = sum * (1.f / 256.f);
    float var = 0.f;
#pragma unroll
    for (int k = 0; k < 2; k++) {
        float dx = v[k].x - mu, dy = v[k].y - mu, dz = v[k].z - mu, dw = v[k].w - mu;
        var += dx * dx + dy * dy + dz * dz + dw * dw;
    }
    var = warpReduceSum(var) * (1.f / 256.f);
    float inv = rsqrtf(var + 1e-5f);
    const float4* g4 = (const float4*)g;
    const float4* b4 = (const float4*)b;
    float4* o4 = (float4*)(out + (size_t)row * DIM);
#pragma unroll
    for (int k = 0; k < 2; k++) {
        int q = k * 32 + lane;
        float4 gg = g4[q], bb = b4[q];
        o4[q] = make_float4((v[k].x - mu) * inv * gg.x + bb.x,
                            (v[k].y - mu) * inv * gg.y + bb.y,
                            (v[k].z - mu) * inv * gg.z + bb.z,
                            (v[k].w - mu) * inv * gg.w + bb.w);
    }
}

// ---------------- host ----------------
static inline void launch_gemm(const float* A, const float* B, const float* bias, float* C,
                               int M, int N, int K) {
    dim3 grid((N + TBN - 1) / TBN, (M + TBM - 1) / TBM);
    sgemm128<<<grid, 256>>>(A, B, bias, C, M, N, K);
}

extern "C" void kernel_launch(void* const* d_in, const int* in_sizes, int n_in,
                              void* d_out, int out_size) {
    const float* x_gnn = (const float*)d_in[0];
    const int*   eidx  = (const int*)d_in[1];
    const float* eattr = (const float*)d_in[2];
    const float* W_in  = (const float*)d_in[3];
    const float* b_in  = (const float*)d_in[4];
    const float* Wl1   = (const float*)d_in[5];
    const float* Wr1   = (const float*)d_in[6];
    const float* We1   = (const float*)d_in[7];
    const float* att1  = (const float*)d_in[8];
    const float* bg1   = (const float*)d_in[9];
    const float* ln1_g = (const float*)d_in[10];
    const float* ln1_b = (const float*)d_in[11];
    const float* W_down= (const float*)d_in[12];
    const float* lnd_g = (const float*)d_in[13];
    const float* lnd_b = (const float*)d_in[14];
    const float* Wl2   = (const float*)d_in[15];
    const float* Wr2   = (const float*)d_in[16];
    const float* We2   = (const float*)d_in[17];
    const float* att2  = (const float*)d_in[18];
    const float* bg2   = (const float*)d_in[19];
    const float* ln2_g = (const float*)d_in[20];
    const float* ln2_b = (const float*)d_in[21];
    const float* W_up  = (const float*)d_in[22];
    const float* lnu_g = (const float*)d_in[23];
    const float* lnu_b = (const float*)d_in[24];
    const float* W_cls = (const float*)d_in[25];
    const float* b_cls = (const float*)d_in[26];

    const int n = in_sizes[0] / 18;        // 20000
    const int E = in_sizes[1] / 2;         // 320000
    const int* src = eidx;
    const int* dst = eidx + E;

    float *h0, *xl, *xr, *agg, *h1, *z, *z2, *tmp, *score, *sb;
    cudaGetSymbolAddress((void**)&h0, g_h0);
    cudaGetSymbolAddress((void**)&xl, g_xl);
    cudaGetSymbolAddress((void**)&xr, g_xr);
    cudaGetSymbolAddress((void**)&agg, g_agg);
    cudaGetSymbolAddress((void**)&h1, g_h1);
    cudaGetSymbolAddress((void**)&z, g_z);
    cudaGetSymbolAddress((void**)&z2, g_z2);
    cudaGetSymbolAddress((void**)&tmp, g_tmp);
    cudaGetSymbolAddress((void**)&score, g_score);
    cudaGetSymbolAddress((void**)&sb, g_s);

    float* out_logits = (float*)d_out;
    float* out_h = (float*)d_out + (size_t)n * 1000;

    const int edgeBlocks = (E + 7) / 8;          // warp per edge, 8 warps/block
    const int lnBlocks = (n + 7) / 8;
    const int nh = n * HEADS;
    const int nd = n * DIM;

    // ---- input projection ----
    launch_gemm(x_gnn, W_in, b_in, h0, n, 32, 18);

    // ---- GAT layer 1 ----
    launch_gemm(h0, Wl1, nullptr, xl, n, DIM, 32);
    launch_gemm(h0, Wr1, nullptr, xr, n, DIM, 32);
    fill_kernel<<<(nh + 255) / 256, 256>>>(sb, 0.f, nh);
    fill_kernel<<<(nd + 255) / 256, 256>>>(agg, 0.f, nd);
    edge_score_kernel<<<edgeBlocks, 256>>>(xl, xr, eattr, We1, att1, src, dst, score, sb, E);
    edge_agg_kernel<<<edgeBlocks, 256>>>(score, sb, xl, src, dst, agg, E);
    ln_kernel<<<lnBlocks, 256>>>(agg, nullptr, bg1, ln1_g, ln1_b, h1, n);

    // ---- bottleneck down ----
    launch_gemm(h1, W_down, nullptr, tmp, n, DIM, DIM);
    ln_kernel<<<lnBlocks, 256>>>(tmp, nullptr, nullptr, lnd_g, lnd_b, z, n);

    // ---- GAT layer 2 ----
    launch_gemm(z, Wl2, nullptr, xl, n, DIM, DIM);
    launch_gemm(z, Wr2, nullptr, xr, n, DIM, DIM);
    fill_kernel<<<(nh + 255) / 256, 256>>>(sb, 0.f, nh);
    fill_kernel<<<(nd + 255) / 256, 256>>>(agg, 0.f, nd);
    edge_score_kernel<<<edgeBlocks, 256>>>(xl, xr, eattr, We2, att2, src, dst, score, sb, E);
    edge_agg_kernel<<<edgeBlocks, 256>>>(score, sb, xl, src, dst, agg, E);
    ln_kernel<<<lnBlocks, 256>>>(agg, z, bg2, ln2_g, ln2_b, z2, n);

    // ---- up projection + final LN ----
    launch_gemm(z2, W_up, nullptr, tmp, n, DIM, DIM);
    ln_kernel<<<lnBlocks, 256>>>(tmp, h1, nullptr, lnu_g, lnu_b, out_h, n);

    // ---- classifier ----
    launch_gemm(out_h, W_cls, b_cls, out_logits, n, 1000, DIM);
}

// round 4
// speedup vs baseline: 1.9576x; 1.6554x over previous
#include <cuda_runtime.h>
#include <math.h>
#include <stdint.h>

// ---------------- problem constants ----------------
#define NMAX 20000
#define EMAX 320000
#define DIM 256
#define HEADS 8

// ---------------- scratch ----------------
__device__ float g_h0[NMAX * 32];
__device__ float g_xl[NMAX * DIM];
__device__ float g_xr[NMAX * DIM];
__device__ float g_agg[NMAX * DIM];
__device__ float g_h1[NMAX * DIM];
__device__ float g_z[NMAX * DIM];
__device__ float g_z2[NMAX * DIM];
__device__ float g_tmp[NMAX * DIM];
__device__ float g_score[EMAX * HEADS];
__device__ float g_s[NMAX * HEADS];
// transposed weights
__device__ float g_wt[8192 + 8192 + 4 * 65536 + 256000];

#define WT_L1 0
#define WT_R1 8192
#define WT_DN 16384
#define WT_L2 (16384 + 65536)
#define WT_R2 (16384 + 2 * 65536)
#define WT_UP (16384 + 3 * 65536)
#define WT_CLS (16384 + 4 * 65536)

// ---------------- helpers ----------------
__device__ __forceinline__ float warpReduceSum(float v) {
#pragma unroll
    for (int o = 16; o > 0; o >>= 1) v += __shfl_xor_sync(0xffffffffu, v, o);
    return v;
}

__device__ __forceinline__ void redAdd4(float* addr, float4 v) {
    asm volatile("red.global.add.v4.f32 [%0], {%1,%2,%3,%4};"
                 :: "l"(addr), "f"(v.x), "f"(v.y), "f"(v.z), "f"(v.w) : "memory");
}

__device__ __forceinline__ float leaky(float v) { return v > 0.f ? v : 0.2f * v; }

__device__ __forceinline__ uint32_t smem_u32(const void* p) {
    uint32_t a;
    asm("{ .reg .u64 t; cvta.to.shared.u64 t, %1; cvt.u32.u64 %0, t; }" : "=r"(a) : "l"(p));
    return a;
}

__device__ __forceinline__ void cpasync16(uint32_t dst, const void* src, bool valid) {
    int sz = valid ? 16 : 0;
    asm volatile("cp.async.cg.shared.global [%0], [%1], 16, %2;"
                 :: "r"(dst), "l"(src), "r"(sz));
}

__device__ __forceinline__ void cpasync_commit() {
    asm volatile("cp.async.commit_group;");
}

__device__ __forceinline__ void cpasync_wait0() {
    asm volatile("cp.async.wait_group 0;");
}

// ---------------- fill ----------------
__global__ void fill_kernel(float* __restrict__ p, float v, int n) {
    int i = blockIdx.x * blockDim.x + threadIdx.x;
    if (i < n) p[i] = v;
}

// ---------------- transpose: in[K,N] -> out[N,K] ----------------
__global__ void transpose_kernel(const float* __restrict__ in, float* __restrict__ out,
                                 int K, int N) {
    __shared__ float t[32][33];
    int bx = blockIdx.x * 32, by = blockIdx.y * 32;
    int x = bx + threadIdx.x;
    int y = by + threadIdx.y;
#pragma unroll
    for (int i = 0; i < 32; i += 8)
        if (x < N && y + i < K) t[threadIdx.y + i][threadIdx.x] = in[(size_t)(y + i) * N + x];
    __syncthreads();
    x = by + threadIdx.x;
    y = bx + threadIdx.y;
#pragma unroll
    for (int i = 0; i < 32; i += 8)
        if (x < K && y + i < N) out[(size_t)(y + i) * K + x] = t[threadIdx.x][threadIdx.y + i];
}

// ---------------- tf32 mma.sync GEMM: C[M,N] = A[M,K] @ WT[N,K]^T (+bias) ----------------
// K % 32 == 0. Block tile 128x128, K-chunk 32, 8 warps (2m x 4n), warp tile 64x32.
// m16n8k8 tf32 mma. Double-buffered dynamic smem via cp.async.
#define GSTR 36   // smem row stride in floats (128B rows + 16B pad; conflict-free frag loads)
#define CHUNK_FLOATS (128 * GSTR)

extern __shared__ float g_dynsmem[];

__global__ __launch_bounds__(256)
void mma_gemm(const float* __restrict__ A, const float* __restrict__ WT,
              const float* __restrict__ bias, float* __restrict__ C,
              int M, int N, int K) {
    float* sA[2] = { g_dynsmem, g_dynsmem + 2 * CHUNK_FLOATS };
    float* sB[2] = { g_dynsmem + CHUNK_FLOATS, g_dynsmem + 3 * CHUNK_FLOATS };

    const int tid = threadIdx.x;
    const int wid = tid >> 5, lane = tid & 31;
    const int gid = lane >> 2, tig = lane & 3;       // mma groupID / threadID-in-group
    const int wm = (wid >> 2) * 64, wn = (wid & 3) * 32;
    const int m0 = blockIdx.y * 128, n0 = blockIdx.x * 128;

    const int ldrow = tid >> 3, ldq = tid & 7;       // unused pattern base (see loop)

    float acc[4][4][4];
#pragma unroll
    for (int mi = 0; mi < 4; mi++)
#pragma unroll
        for (int ni = 0; ni < 4; ni++)
#pragma unroll
            for (int q = 0; q < 4; q++) acc[mi][ni][q] = 0.f;

    const int nc = K >> 5;
    uint32_t sAaddr[2] = { smem_u32(sA[0]), smem_u32(sA[1]) };
    uint32_t sBaddr[2] = { smem_u32(sB[0]), smem_u32(sB[1]) };

    // issue chunk c into buffer b
    auto issue = [&](int c, int b) {
        int k0 = c << 5;
#pragma unroll
        for (int i = 0; i < 4; i++) {
            int idx = tid + i * 256;
            int row = idx >> 3, q = idx & 7;
            uint32_t soff = (uint32_t)(row * GSTR + q * 4) * 4u;
            int ga = m0 + row;
            cpasync16(sAaddr[b] + soff, A + (size_t)ga * K + k0 + q * 4, ga < M);
            int gb = n0 + row;
            cpasync16(sBaddr[b] + soff, WT + (size_t)gb * K + k0 + q * 4, gb < N);
        }
        cpasync_commit();
    };

    issue(0, 0);
    for (int c = 0; c < nc; c++) {
        int cur = c & 1;
        cpasync_wait0();
        __syncthreads();
        if (c + 1 < nc) issue(c + 1, cur ^ 1);
        const float* cA = sA[cur];
        const float* cB = sB[cur];
#pragma unroll
        for (int ks = 0; ks < 4; ks++) {
            int ko = ks * 8;
            uint32_t af[4][4], bf[4][2];
#pragma unroll
            for (int mi = 0; mi < 4; mi++) {
                const float* base = cA + (wm + mi * 16 + gid) * GSTR + ko + tig;
                af[mi][0] = __float_as_uint(base[0]);
                af[mi][1] = __float_as_uint(base[8 * GSTR]);
                af[mi][2] = __float_as_uint(base[4]);
                af[mi][3] = __float_as_uint(base[8 * GSTR + 4]);
            }
#pragma unroll
            for (int ni = 0; ni < 4; ni++) {
                const float* base = cB + (wn + ni * 8 + gid) * GSTR + ko + tig;
                bf[ni][0] = __float_as_uint(base[0]);
                bf[ni][1] = __float_as_uint(base[4]);
            }
#pragma unroll
            for (int mi = 0; mi < 4; mi++)
#pragma unroll
                for (int ni = 0; ni < 4; ni++) {
                    asm volatile(
                        "mma.sync.aligned.m16n8k8.row.col.f32.tf32.tf32.f32 "
                        "{%0,%1,%2,%3}, {%4,%5,%6,%7}, {%8,%9}, {%0,%1,%2,%3};"
                        : "+f"(acc[mi][ni][0]), "+f"(acc[mi][ni][1]),
                          "+f"(acc[mi][ni][2]), "+f"(acc[mi][ni][3])
                        : "r"(af[mi][0]), "r"(af[mi][1]), "r"(af[mi][2]), "r"(af[mi][3]),
                          "r"(bf[ni][0]), "r"(bf[ni][1]));
                }
        }
        __syncthreads();
    }

    // epilogue: c0=(gid, 2*tig), c1=(gid, 2*tig+1), c2=(gid+8, 2*tig), c3=(gid+8, 2*tig+1)
#pragma unroll
    for (int mi = 0; mi < 4; mi++) {
        int r0 = m0 + wm + mi * 16 + gid;
        int r1 = r0 + 8;
#pragma unroll
        for (int ni = 0; ni < 4; ni++) {
            int col = n0 + wn + ni * 8 + tig * 2;
            if (col >= N) continue;
            float bx = 0.f, by = 0.f;
            if (bias) { bx = bias[col]; by = bias[col + 1]; }
            if (r0 < M) {
                float2 v = make_float2(acc[mi][ni][0] + bx, acc[mi][ni][1] + by);
                *(float2*)(C + (size_t)r0 * N + col) = v;
            }
            if (r1 < M) {
                float2 v = make_float2(acc[mi][ni][2] + bx, acc[mi][ni][3] + by);
                *(float2*)(C + (size_t)r1 * N + col) = v;
            }
        }
    }
    (void)ldrow; (void)ldq;
}

// ---------------- small fp32 SGEMM (for W_in, K=18) ----------------
#define BM 64
#define BN 64
#define BK 16
__global__ void sgemm_kernel(const float* __restrict__ A, const float* __restrict__ B,
                             const float* __restrict__ bias, float* __restrict__ C,
                             int M, int N, int K) {
    __shared__ float As[BK][BM + 4];
    __shared__ float Bs[BK][BN];
    int tid = threadIdx.x;
    int tr = tid >> 4, tc = tid & 15;
    int row0 = blockIdx.y * BM, col0 = blockIdx.x * BN;
    float acc[4][4] = {};
    int ntile = (K + BK - 1) / BK;
    for (int t = 0; t < ntile; t++) {
        int k0 = t * BK;
        {
            int r = tid >> 2;
            int gr = row0 + r;
#pragma unroll
            for (int i = 0; i < 4; i++) {
                int kk = ((tid & 3) << 2) + i;
                int gk = k0 + kk;
                As[kk][r] = (gr < M && gk < K) ? A[(size_t)gr * K + gk] : 0.f;
            }
        }
#pragma unroll
        for (int i = 0; i < 4; i++) {
            int idx = tid + i * 256;
            int ccol = idx & 63, kk = idx >> 6;
            int gk = k0 + kk, gc = col0 + ccol;
            Bs[kk][ccol] = (gk < K && gc < N) ? B[(size_t)gk * N + gc] : 0.f;
        }
        __syncthreads();
#pragma unroll
        for (int kk = 0; kk < BK; kk++) {
            float a[4], b[4];
#pragma unroll
            for (int i = 0; i < 4; i++) a[i] = As[kk][tr * 4 + i];
#pragma unroll
            for (int j = 0; j < 4; j++) b[j] = Bs[kk][tc * 4 + j];
#pragma unroll
            for (int i = 0; i < 4; i++)
#pragma unroll
                for (int j = 0; j < 4; j++) acc[i][j] += a[i] * b[j];
        }
        __syncthreads();
    }
#pragma unroll
    for (int i = 0; i < 4; i++) {
        int gr = row0 + tr * 4 + i;
        if (gr >= M) continue;
#pragma unroll
        for (int j = 0; j < 4; j++) {
            int gc = col0 + tc * 4 + j;
            if (gc < N) C[(size_t)gr * N + gc] = acc[i][j] + (bias ? bias[gc] : 0.f);
        }
    }
}

// ---------------- edge pass A: score + exp + segment sum ----------------
__global__ void edge_score_kernel(const float* __restrict__ xl, const float* __restrict__ xr,
                                  const float* __restrict__ ea, const float* __restrict__ We,
                                  const float* __restrict__ att,
                                  const int* __restrict__ src, const int* __restrict__ dst,
                                  float* __restrict__ score, float* __restrict__ ssum, int E) {
    int e = (blockIdx.x * blockDim.x + threadIdx.x) >> 5;
    int lane = threadIdx.x & 31;
    if (e >= E) return;
    int s = src[e], d = dst[e];
    float a = ea[e];
    const float4* xls = (const float4*)(xl + (size_t)s * DIM);
    const float4* xrd = (const float4*)(xr + (size_t)d * DIM);
    const float4* We4 = (const float4*)We;
    const float4* at4 = (const float4*)att;
#pragma unroll
    for (int c = 0; c < 2; c++) {
        int q = c * 32 + lane;
        float4 l = xls[q], r = xrd[q], w = We4[q], t = at4[q];
        float p = leaky(l.x + r.x + a * w.x) * t.x + leaky(l.y + r.y + a * w.y) * t.y
                + leaky(l.z + r.z + a * w.z) * t.z + leaky(l.w + r.w + a * w.w) * t.w;
        p += __shfl_xor_sync(0xffffffffu, p, 1);
        p += __shfl_xor_sync(0xffffffffu, p, 2);
        p += __shfl_xor_sync(0xffffffffu, p, 4);
        if ((lane & 7) == 0) {
            int h = c * 4 + (lane >> 3);
            float ex = __expf(p);
            score[(size_t)e * 8 + h] = ex;
            atomicAdd(&ssum[d * 8 + h], ex);
        }
    }
}

// ---------------- edge pass B: weighted aggregation ----------------
__global__ void edge_agg_kernel(const float* __restrict__ score, const float* __restrict__ ssum,
                                const float* __restrict__ xl,
                                const int* __restrict__ src, const int* __restrict__ dst,
                                float* __restrict__ agg, int E) {
    int e = (blockIdx.x * blockDim.x + threadIdx.x) >> 5;
    int lane = threadIdx.x & 31;
    if (e >= E) return;
    int s = src[e], d = dst[e];
    const float4* xls = (const float4*)(xl + (size_t)s * DIM);
    float* aggd = agg + (size_t)d * DIM;
#pragma unroll
    for (int c = 0; c < 2; c++) {
        int h = c * 4 + (lane >> 3);
        float al = score[(size_t)e * 8 + h] / (ssum[d * 8 + h] + 1e-16f);
        float4 x = xls[c * 32 + lane];
        redAdd4(aggd + c * 128 + lane * 4, make_float4(al * x.x, al * x.y, al * x.z, al * x.w));
    }
}

// ---------------- layernorm (dim=256) ----------------
__global__ void ln_kernel(const float* __restrict__ x, const float* __restrict__ res,
                          const float* __restrict__ bias, const float* __restrict__ g,
                          const float* __restrict__ b, float* __restrict__ out, int n) {
    int row = blockIdx.x * 8 + (threadIdx.x >> 5);
    int lane = threadIdx.x & 31;
    if (row >= n) return;
    const float4* xr4 = (const float4*)(x + (size_t)row * DIM);
    const float4* rs4 = res ? (const float4*)(res + (size_t)row * DIM) : nullptr;
    const float4* bi4 = bias ? (const float4*)bias : nullptr;
    float4 v[2];
    float sum = 0.f;
#pragma unroll
    for (int k = 0; k < 2; k++) {
        int q = k * 32 + lane;
        float4 t = xr4[q];
        if (rs4) { float4 r = rs4[q]; t.x += r.x; t.y += r.y; t.z += r.z; t.w += r.w; }
        if (bi4) { float4 r = bi4[q]; t.x += r.x; t.y += r.y; t.z += r.z; t.w += r.w; }
        v[k] = t;
        sum += t.x + t.y + t.z + t.w;
    }
    sum = warpReduceSum(sum);
    float mu = sum * (1.f / 256.f);
    float var = 0.f;
#pragma unroll
    for (int k = 0; k < 2; k++) {
        float dx = v[k].x - mu, dy = v[k].y - mu, dz = v[k].z - mu, dw = v[k].w - mu;
        var += dx * dx + dy * dy + dz * dz + dw * dw;
    }
    var = warpReduceSum(var) * (1.f / 256.f);
    float inv = rsqrtf(var + 1e-5f);
    const float4* g4 = (const float4*)g;
    const float4* b4 = (const float4*)b;
    float4* o4 = (float4*)(out + (size_t)row * DIM);
#pragma unroll
    for (int k = 0; k < 2; k++) {
        int q = k * 32 + lane;
        float4 gg = g4[q], bb = b4[q];
        o4[q] = make_float4((v[k].x - mu) * inv * gg.x + bb.x,
                            (v[k].y - mu) * inv * gg.y + bb.y,
                            (v[k].z - mu) * inv * gg.z + bb.z,
                            (v[k].w - mu) * inv * gg.w + bb.w);
    }
}

// ---------------- host ----------------
#define DYN_SMEM (4 * CHUNK_FLOATS * sizeof(float))   // 73728 bytes

static inline void launch_tgemm(const float* A, const float* WT, const float* bias, float* C,
                                int M, int N, int K) {
    dim3 grid((N + 127) / 128, (M + 127) / 128);
    mma_gemm<<<grid, 256, DYN_SMEM>>>(A, WT, bias, C, M, N, K);
}

static inline void launch_transpose(const float* in, float* out, int K, int N) {
    dim3 grid((N + 31) / 32, (K + 31) / 32);
    transpose_kernel<<<grid, dim3(32, 8)>>>(in, out, K, N);
}

extern "C" void kernel_launch(void* const* d_in, const int* in_sizes, int n_in,
                              void* d_out, int out_size) {
    static bool attr_set = false;
    if (!attr_set) {
        cudaFuncSetAttribute(mma_gemm, cudaFuncAttributeMaxDynamicSharedMemorySize, DYN_SMEM);
        attr_set = true;
    }

    const float* x_gnn = (const float*)d_in[0];
    const int*   eidx  = (const int*)d_in[1];
    const float* eattr = (const float*)d_in[2];
    const float* W_in  = (const float*)d_in[3];
    const float* b_in  = (const float*)d_in[4];
    const float* Wl1   = (const float*)d_in[5];
    const float* Wr1   = (const float*)d_in[6];
    const float* We1   = (const float*)d_in[7];
    const float* att1  = (const float*)d_in[8];
    const float* bg1   = (const float*)d_in[9];
    const float* ln1_g = (const float*)d_in[10];
    const float* ln1_b = (const float*)d_in[11];
    const float* W_down= (const float*)d_in[12];
    const float* lnd_g = (const float*)d_in[13];
    const float* lnd_b = (const float*)d_in[14];
    const float* Wl2   = (const float*)d_in[15];
    const float* Wr2   = (const float*)d_in[16];
    const float* We2   = (const float*)d_in[17];
    const float* att2  = (const float*)d_in[18];
    const float* bg2   = (const float*)d_in[19];
    const float* ln2_g = (const float*)d_in[20];
    const float* ln2_b = (const float*)d_in[21];
    const float* W_up  = (const float*)d_in[22];
    const float* lnu_g = (const float*)d_in[23];
    const float* lnu_b = (const float*)d_in[24];
    const float* W_cls = (const float*)d_in[25];
    const float* b_cls = (const float*)d_in[26];

    const int n = in_sizes[0] / 18;        // 20000
    const int E = in_sizes[1] / 2;         // 320000
    const int* src = eidx;
    const int* dst = eidx + E;

    float *h0, *xl, *xr, *agg, *h1, *z, *z2, *tmp, *score, *sb, *wt;
    cudaGetSymbolAddress((void**)&h0, g_h0);
    cudaGetSymbolAddress((void**)&xl, g_xl);
    cudaGetSymbolAddress((void**)&xr, g_xr);
    cudaGetSymbolAddress((void**)&agg, g_agg);
    cudaGetSymbolAddress((void**)&h1, g_h1);
    cudaGetSymbolAddress((void**)&z, g_z);
    cudaGetSymbolAddress((void**)&z2, g_z2);
    cudaGetSymbolAddress((void**)&tmp, g_tmp);
    cudaGetSymbolAddress((void**)&score, g_score);
    cudaGetSymbolAddress((void**)&sb, g_s);
    cudaGetSymbolAddress((void**)&wt, g_wt);

    float* out_logits = (float*)d_out;
    float* out_h = (float*)d_out + (size_t)n * 1000;

    const int edgeBlocks = (E + 7) / 8;
    const int lnBlocks = (n + 7) / 8;
    const int nh = n * HEADS;
    const int nd = n * DIM;

    // ---- transpose all weights upfront ----
    launch_transpose(Wl1, wt + WT_L1, 32, DIM);
    launch_transpose(Wr1, wt + WT_R1, 32, DIM);
    launch_transpose(W_down, wt + WT_DN, DIM, DIM);
    launch_transpose(Wl2, wt + WT_L2, DIM, DIM);
    launch_transpose(Wr2, wt + WT_R2, DIM, DIM);
    launch_transpose(W_up, wt + WT_UP, DIM, DIM);
    launch_transpose(W_cls, wt + WT_CLS, DIM, 1000);

    // ---- input projection (K=18, fp32) ----
    {
        dim3 grid(1, (n + BM - 1) / BM);
        sgemm_kernel<<<grid, 256>>>(x_gnn, W_in, b_in, h0, n, 32, 18);
    }

    // ---- GAT layer 1 ----
    launch_tgemm(h0, wt + WT_L1, nullptr, xl, n, DIM, 32);
    launch_tgemm(h0, wt + WT_R1, nullptr, xr, n, DIM, 32);
    fill_kernel<<<(nh + 255) / 256, 256>>>(sb, 0.f, nh);
    fill_kernel<<<(nd + 255) / 256, 256>>>(agg, 0.f, nd);
    edge_score_kernel<<<edgeBlocks, 256>>>(xl, xr, eattr, We1, att1, src, dst, score, sb, E);
    edge_agg_kernel<<<edgeBlocks, 256>>>(score, sb, xl, src, dst, agg, E);
    ln_kernel<<<lnBlocks, 256>>>(agg, nullptr, bg1, ln1_g, ln1_b, h1, n);

    // ---- bottleneck down ----
    launch_tgemm(h1, wt + WT_DN, nullptr, tmp, n, DIM, DIM);
    ln_kernel<<<lnBlocks, 256>>>(tmp, nullptr, nullptr, lnd_g, lnd_b, z, n);

    // ---- GAT layer 2 ----
    launch_tgemm(z, wt + WT_L2, nullptr, xl, n, DIM, DIM);
    launch_tgemm(z, wt + WT_R2, nullptr, xr, n, DIM, DIM);
    fill_kernel<<<(nh + 255) / 256, 256>>>(sb, 0.f, nh);
    fill_kernel<<<(nd + 255) / 256, 256>>>(agg, 0.f, nd);
    edge_score_kernel<<<edgeBlocks, 256>>>(xl, xr, eattr, We2, att2, src, dst, score, sb, E);
    edge_agg_kernel<<<edgeBlocks, 256>>>(score, sb, xl, src, dst, agg, E);
    ln_kernel<<<lnBlocks, 256>>>(agg, z, bg2, ln2_g, ln2_b, z2, n);

    // ---- up projection + final LN ----
    launch_tgemm(z2, wt + WT_UP, nullptr, tmp, n, DIM, DIM);
    ln_kernel<<<lnBlocks, 256>>>(tmp, h1, nullptr, lnu_g, lnu_b, out_h, n);

    // ---- classifier ----
    launch_tgemm(out_h, wt + WT_CLS, b_cls, out_logits, n, 1000, DIM);
}

// round 5
// speedup vs baseline: 2.2923x; 1.1709x over previous
#include <cuda_runtime.h>
#include <math.h>
#include <stdint.h>

// ---------------- problem constants ----------------
#define NMAX 20000
#define EMAX 320000
#define DIM 256
#define HEADS 8

// ---------------- scratch ----------------
__device__ float g_h0[NMAX * 32];
__device__ float g_xl[NMAX * DIM];
__device__ float g_xr[NMAX * DIM];
__device__ float g_agg[NMAX * DIM];
__device__ float g_h1[NMAX * DIM];
__device__ float g_z[NMAX * DIM];
__device__ float g_z2[NMAX * DIM];
__device__ float g_tmp[NMAX * DIM];
__device__ float g_s[NMAX * HEADS];
// transposed (and tf32-RN-rounded) weights
__device__ float g_wt[8192 + 8192 + 4 * 65536 + 256000];

#define WT_L1 0
#define WT_R1 8192
#define WT_DN 16384
#define WT_L2 (16384 + 65536)
#define WT_R2 (16384 + 2 * 65536)
#define WT_UP (16384 + 3 * 65536)
#define WT_CLS (16384 + 4 * 65536)

// ---------------- helpers ----------------
__device__ __forceinline__ float warpReduceSum(float v) {
#pragma unroll
    for (int o = 16; o > 0; o >>= 1) v += __shfl_xor_sync(0xffffffffu, v, o);
    return v;
}

__device__ __forceinline__ void redAdd4(float* addr, float4 v) {
    asm volatile("red.global.add.v4.f32 [%0], {%1,%2,%3,%4};"
                 :: "l"(addr), "f"(v.x), "f"(v.y), "f"(v.z), "f"(v.w) : "memory");
}

__device__ __forceinline__ float leaky(float v) { return v > 0.f ? v : 0.2f * v; }

__device__ __forceinline__ uint32_t smem_u32(const void* p) {
    uint32_t a;
    asm("{ .reg .u64 t; cvta.to.shared.u64 t, %1; cvt.u32.u64 %0, t; }" : "=r"(a) : "l"(p));
    return a;
}

__device__ __forceinline__ uint32_t tf32_rn(float f) {
    uint32_t r;
    asm("cvt.rna.tf32.f32 %0, %1;" : "=r"(r) : "f"(f));
    return r;
}

__device__ __forceinline__ void cpasync16(uint32_t dst, const void* src, bool valid) {
    int sz = valid ? 16 : 0;
    asm volatile("cp.async.cg.shared.global [%0], [%1], 16, %2;"
                 :: "r"(dst), "l"(src), "r"(sz));
}

__device__ __forceinline__ void cpasync_commit() { asm volatile("cp.async.commit_group;"); }
__device__ __forceinline__ void cpasync_wait0() { asm volatile("cp.async.wait_group 0;"); }

// ---------------- zero both ssum and agg in one launch ----------------
__global__ void zero2_kernel(float4* __restrict__ a, int na4, float4* __restrict__ b, int nb4) {
    int i = blockIdx.x * blockDim.x + threadIdx.x;
    float4 z = make_float4(0.f, 0.f, 0.f, 0.f);
    if (i < na4) a[i] = z;
    else if (i < na4 + nb4) b[i - na4] = z;
}

// ---------------- transpose + tf32-RN round: in[K,N] -> out[N,K] ----------------
__global__ void transpose_kernel(const float* __restrict__ in, float* __restrict__ out,
                                 int K, int N) {
    __shared__ float t[32][33];
    int bx = blockIdx.x * 32, by = blockIdx.y * 32;
    int x = bx + threadIdx.x;
    int y = by + threadIdx.y;
#pragma unroll
    for (int i = 0; i < 32; i += 8)
        if (x < N && y + i < K) t[threadIdx.y + i][threadIdx.x] = in[(size_t)(y + i) * N + x];
    __syncthreads();
    x = by + threadIdx.x;
    y = bx + threadIdx.y;
#pragma unroll
    for (int i = 0; i < 32; i += 8)
        if (x < K && y + i < N)
            out[(size_t)(y + i) * K + x] = __uint_as_float(tf32_rn(t[threadIdx.x][threadIdx.y + i]));
}

// ---------------- tf32 mma.sync GEMM: C[M,N] = A[M,K] @ WT[N,K]^T (+bias) ----------------
#define GSTR 36
#define CHUNK_FLOATS (128 * GSTR)

extern __shared__ float g_dynsmem[];

__global__ __launch_bounds__(256)
void mma_gemm(const float* __restrict__ A, const float* __restrict__ WT,
              const float* __restrict__ bias, float* __restrict__ C,
              int M, int N, int K) {
    float* sA[2] = { g_dynsmem, g_dynsmem + 2 * CHUNK_FLOATS };
    float* sB[2] = { g_dynsmem + CHUNK_FLOATS, g_dynsmem + 3 * CHUNK_FLOATS };

    const int tid = threadIdx.x;
    const int wid = tid >> 5, lane = tid & 31;
    const int gid = lane >> 2, tig = lane & 3;
    const int wm = (wid >> 2) * 64, wn = (wid & 3) * 32;
    const int m0 = blockIdx.y * 128, n0 = blockIdx.x * 128;

    float acc[4][4][4];
#pragma unroll
    for (int mi = 0; mi < 4; mi++)
#pragma unroll
        for (int ni = 0; ni < 4; ni++)
#pragma unroll
            for (int q = 0; q < 4; q++) acc[mi][ni][q] = 0.f;

    const int nc = K >> 5;
    uint32_t sAaddr[2] = { smem_u32(sA[0]), smem_u32(sA[1]) };
    uint32_t sBaddr[2] = { smem_u32(sB[0]), smem_u32(sB[1]) };

    auto issue = [&](int c, int b) {
        int k0 = c << 5;
#pragma unroll
        for (int i = 0; i < 4; i++) {
            int idx = tid + i * 256;
            int row = idx >> 3, q = idx & 7;
            uint32_t soff = (uint32_t)(row * GSTR + q * 4) * 4u;
            int ga = m0 + row;
            cpasync16(sAaddr[b] + soff, A + (size_t)ga * K + k0 + q * 4, ga < M);
            int gb = n0 + row;
            cpasync16(sBaddr[b] + soff, WT + (size_t)gb * K + k0 + q * 4, gb < N);
        }
        cpasync_commit();
    };

    issue(0, 0);
    for (int c = 0; c < nc; c++) {
        int cur = c & 1;
        cpasync_wait0();
        __syncthreads();
        if (c + 1 < nc) issue(c + 1, cur ^ 1);
        const float* cA = sA[cur];
        const float* cB = sB[cur];
#pragma unroll
        for (int ks = 0; ks < 4; ks++) {
            int ko = ks * 8;
            uint32_t af[4][4], bf[4][2];
#pragma unroll
            for (int mi = 0; mi < 4; mi++) {
                const float* base = cA + (wm + mi * 16 + gid) * GSTR + ko + tig;
                af[mi][0] = tf32_rn(base[0]);                 // A: round-to-nearest tf32
                af[mi][1] = tf32_rn(base[8 * GSTR]);
                af[mi][2] = tf32_rn(base[4]);
                af[mi][3] = tf32_rn(base[8 * GSTR + 4]);
            }
#pragma unroll
            for (int ni = 0; ni < 4; ni++) {
                const float* base = cB + (wn + ni * 8 + gid) * GSTR + ko + tig;
                bf[ni][0] = __float_as_uint(base[0]);         // WT pre-rounded in transpose
                bf[ni][1] = __float_as_uint(base[4]);
            }
#pragma unroll
            for (int mi = 0; mi < 4; mi++)
#pragma unroll
                for (int ni = 0; ni < 4; ni++) {
                    asm volatile(
                        "mma.sync.aligned.m16n8k8.row.col.f32.tf32.tf32.f32 "
                        "{%0,%1,%2,%3}, {%4,%5,%6,%7}, {%8,%9}, {%0,%1,%2,%3};"
                        : "+f"(acc[mi][ni][0]), "+f"(acc[mi][ni][1]),
                          "+f"(acc[mi][ni][2]), "+f"(acc[mi][ni][3])
                        : "r"(af[mi][0]), "r"(af[mi][1]), "r"(af[mi][2]), "r"(af[mi][3]),
                          "r"(bf[ni][0]), "r"(bf[ni][1]));
                }
        }
        __syncthreads();
    }

#pragma unroll
    for (int mi = 0; mi < 4; mi++) {
        int r0 = m0 + wm + mi * 16 + gid;
        int r1 = r0 + 8;
#pragma unroll
        for (int ni = 0; ni < 4; ni++) {
            int col = n0 + wn + ni * 8 + tig * 2;
            if (col >= N) continue;
            float bx = 0.f, by = 0.f;
            if (bias) { bx = bias[col]; by = bias[col + 1]; }
            if (r0 < M)
                *(float2*)(C + (size_t)r0 * N + col) =
                    make_float2(acc[mi][ni][0] + bx, acc[mi][ni][1] + by);
            if (r1 < M)
                *(float2*)(C + (size_t)r1 * N + col) =
                    make_float2(acc[mi][ni][2] + bx, acc[mi][ni][3] + by);
        }
    }
}

// ---------------- small fp32 SGEMM (for W_in, K=18) ----------------
#define BM 64
#define BN 64
#define BK 16
__global__ void sgemm_kernel(const float* __restrict__ A, const float* __restrict__ B,
                             const float* __restrict__ bias, float* __restrict__ C,
                             int M, int N, int K) {
    __shared__ float As[BK][BM + 4];
    __shared__ float Bs[BK][BN];
    int tid = threadIdx.x;
    int tr = tid >> 4, tc = tid & 15;
    int row0 = blockIdx.y * BM, col0 = blockIdx.x * BN;
    float acc[4][4] = {};
    int ntile = (K + BK - 1) / BK;
    for (int t = 0; t < ntile; t++) {
        int k0 = t * BK;
        {
            int r = tid >> 2;
            int gr = row0 + r;
#pragma unroll
            for (int i = 0; i < 4; i++) {
                int kk = ((tid & 3) << 2) + i;
                int gk = k0 + kk;
                As[kk][r] = (gr < M && gk < K) ? A[(size_t)gr * K + gk] : 0.f;
            }
        }
#pragma unroll
        for (int i = 0; i < 4; i++) {
            int idx = tid + i * 256;
            int ccol = idx & 63, kk = idx >> 6;
            int gk = k0 + kk, gc = col0 + ccol;
            Bs[kk][ccol] = (gk < K && gc < N) ? B[(size_t)gk * N + gc] : 0.f;
        }
        __syncthreads();
#pragma unroll
        for (int kk = 0; kk < BK; kk++) {
            float a[4], b[4];
#pragma unroll
            for (int i = 0; i < 4; i++) a[i] = As[kk][tr * 4 + i];
#pragma unroll
            for (int j = 0; j < 4; j++) b[j] = Bs[kk][tc * 4 + j];
#pragma unroll
            for (int i = 0; i < 4; i++)
#pragma unroll
                for (int j = 0; j < 4; j++) acc[i][j] += a[i] * b[j];
        }
        __syncthreads();
    }
#pragma unroll
    for (int i = 0; i < 4; i++) {
        int gr = row0 + tr * 4 + i;
        if (gr >= M) continue;
#pragma unroll
        for (int j = 0; j < 4; j++) {
            int gc = col0 + tc * 4 + j;
            if (gc < N) C[(size_t)gr * N + gc] = acc[i][j] + (bias ? bias[gc] : 0.f);
        }
    }
}

// ---------------- fused edge pass: score + exp + ssum + unnormalized aggregation ----------
// warp per edge. agg[d] += exp(score_h) * xl[src]; ssum[d,h] += exp(score_h).
// Normalization by ssum deferred to the LN kernel.
__global__ void edge_fused_kernel(const float* __restrict__ xl, const float* __restrict__ xr,
                                  const float* __restrict__ ea, const float* __restrict__ We,
                                  const float* __restrict__ att,
                                  const int* __restrict__ src, const int* __restrict__ dst,
                                  float* __restrict__ ssum, float* __restrict__ agg, int E) {
    int e = (blockIdx.x * blockDim.x + threadIdx.x) >> 5;
    int lane = threadIdx.x & 31;
    if (e >= E) return;
    int s = src[e], d = dst[e];
    float a = ea[e];
    const float4* xls = (const float4*)(xl + (size_t)s * DIM);
    const float4* xrd = (const float4*)(xr + (size_t)d * DIM);
    const float4* We4 = (const float4*)We;
    const float4* at4 = (const float4*)att;
    float* aggd = agg + (size_t)d * DIM;
#pragma unroll
    for (int c = 0; c < 2; c++) {
        int q = c * 32 + lane;
        float4 l = xls[q], r = xrd[q], w = We4[q], t = at4[q];
        float p = leaky(l.x + r.x + a * w.x) * t.x + leaky(l.y + r.y + a * w.y) * t.y
                + leaky(l.z + r.z + a * w.z) * t.z + leaky(l.w + r.w + a * w.w) * t.w;
        p += __shfl_xor_sync(0xffffffffu, p, 1);
        p += __shfl_xor_sync(0xffffffffu, p, 2);
        p += __shfl_xor_sync(0xffffffffu, p, 4);   // all 8 lanes of subgroup hold head sum
        float ex = __expf(p);
        redAdd4(aggd + q * 4, make_float4(ex * l.x, ex * l.y, ex * l.z, ex * l.w));
        if ((lane & 7) == 0) {
            int h = c * 4 + (lane >> 3);
            atomicAdd(&ssum[d * 8 + h], ex);
        }
    }
}

// ---------------- layernorm (dim=256); optional per-head ssum normalize, residual, bias ----
__global__ void ln_kernel(const float* __restrict__ x, const float* __restrict__ ssum,
                          const float* __restrict__ res, const float* __restrict__ bias,
                          const float* __restrict__ g, const float* __restrict__ b,
                          float* __restrict__ out, int n) {
    int row = blockIdx.x * 8 + (threadIdx.x >> 5);
    int lane = threadIdx.x & 31;
    if (row >= n) return;
    const float4* xr4 = (const float4*)(x + (size_t)row * DIM);
    const float4* rs4 = res ? (const float4*)(res + (size_t)row * DIM) : nullptr;
    const float4* bi4 = bias ? (const float4*)bias : nullptr;
    float4 v[2];
    float sum = 0.f;
#pragma unroll
    for (int k = 0; k < 2; k++) {
        int q = k * 32 + lane;
        float4 t = xr4[q];
        if (ssum) {
            int h = q >> 3;                     // head of this float4
            float inv = 1.f / (ssum[row * 8 + h] + 1e-16f);
            t.x *= inv; t.y *= inv; t.z *= inv; t.w *= inv;
        }
        if (rs4) { float4 r = rs4[q]; t.x += r.x; t.y += r.y; t.z += r.z; t.w += r.w; }
        if (bi4) { float4 r = bi4[q]; t.x += r.x; t.y += r.y; t.z += r.z; t.w += r.w; }
        v[k] = t;
        sum += t.x + t.y + t.z + t.w;
    }
    sum = warpReduceSum(sum);
    float mu = sum * (1.f / 256.f);
    float var = 0.f;
#pragma unroll
    for (int k = 0; k < 2; k++) {
        float dx = v[k].x - mu, dy = v[k].y - mu, dz = v[k].z - mu, dw = v[k].w - mu;
        var += dx * dx + dy * dy + dz * dz + dw * dw;
    }
    var = warpReduceSum(var) * (1.f / 256.f);
    float inv = rsqrtf(var + 1e-5f);
    const float4* g4 = (const float4*)g;
    const float4* b4 = (const float4*)b;
    float4* o4 = (float4*)(out + (size_t)row * DIM);
#pragma unroll
    for (int k = 0; k < 2; k++) {
        int q = k * 32 + lane;
        float4 gg = g4[q], bb = b4[q];
        o4[q] = make_float4((v[k].x - mu) * inv * gg.x + bb.x,
                            (v[k].y - mu) * inv * gg.y + bb.y,
                            (v[k].z - mu) * inv * gg.z + bb.z,
                            (v[k].w - mu) * inv * gg.w + bb.w);
    }
}

// ---------------- host ----------------
#define DYN_SMEM (4 * CHUNK_FLOATS * sizeof(float))

static inline void launch_tgemm(const float* A, const float* WT, const float* bias, float* C,
                                int M, int N, int K) {
    dim3 grid((N + 127) / 128, (M + 127) / 128);
    mma_gemm<<<grid, 256, DYN_SMEM>>>(A, WT, bias, C, M, N, K);
}

static inline void launch_transpose(const float* in, float* out, int K, int N) {
    dim3 grid((N + 31) / 32, (K + 31) / 32);
    transpose_kernel<<<grid, dim3(32, 8)>>>(in, out, K, N);
}

extern "C" void kernel_launch(void* const* d_in, const int* in_sizes, int n_in,
                              void* d_out, int out_size) {
    static bool attr_set = false;
    if (!attr_set) {
        cudaFuncSetAttribute(mma_gemm, cudaFuncAttributeMaxDynamicSharedMemorySize, DYN_SMEM);
        attr_set = true;
    }

    const float* x_gnn = (const float*)d_in[0];
    const int*   eidx  = (const int*)d_in[1];
    const float* eattr = (const float*)d_in[2];
    const float* W_in  = (const float*)d_in[3];
    const float* b_in  = (const float*)d_in[4];
    const float* Wl1   = (const float*)d_in[5];
    const float* Wr1   = (const float*)d_in[6];
    const float* We1   = (const float*)d_in[7];
    const float* att1  = (const float*)d_in[8];
    const float* bg1   = (const float*)d_in[9];
    const float* ln1_g = (const float*)d_in[10];
    const float* ln1_b = (const float*)d_in[11];
    const float* W_down= (const float*)d_in[12];
    const float* lnd_g = (const float*)d_in[13];
    const float* lnd_b = (const float*)d_in[14];
    const float* Wl2   = (const float*)d_in[15];
    const float* Wr2   = (const float*)d_in[16];
    const float* We2   = (const float*)d_in[17];
    const float* att2  = (const float*)d_in[18];
    const float* bg2   = (const float*)d_in[19];
    const float* ln2_g = (const float*)d_in[20];
    const float* ln2_b = (const float*)d_in[21];
    const float* W_up  = (const float*)d_in[22];
    const float* lnu_g = (const float*)d_in[23];
    const float* lnu_b = (const float*)d_in[24];
    const float* W_cls = (const float*)d_in[25];
    const float* b_cls = (const float*)d_in[26];

    const int n = in_sizes[0] / 18;        // 20000
    const int E = in_sizes[1] / 2;         // 320000
    const int* src = eidx;
    const int* dst = eidx + E;

    float *h0, *xl, *xr, *agg, *h1, *z, *z2, *tmp, *sb, *wt;
    cudaGetSymbolAddress((void**)&h0, g_h0);
    cudaGetSymbolAddress((void**)&xl, g_xl);
    cudaGetSymbolAddress((void**)&xr, g_xr);
    cudaGetSymbolAddress((void**)&agg, g_agg);
    cudaGetSymbolAddress((void**)&h1, g_h1);
    cudaGetSymbolAddress((void**)&z, g_z);
    cudaGetSymbolAddress((void**)&z2, g_z2);
    cudaGetSymbolAddress((void**)&tmp, g_tmp);
    cudaGetSymbolAddress((void**)&sb, g_s);
    cudaGetSymbolAddress((void**)&wt, g_wt);

    float* out_logits = (float*)d_out;
    float* out_h = (float*)d_out + (size_t)n * 1000;

    const int edgeBlocks = (E + 7) / 8;
    const int lnBlocks = (n + 7) / 8;
    const int nh4 = n * HEADS / 4;
    const int nd4 = n * DIM / 4;
    const int zeroBlocks = (nh4 + nd4 + 255) / 256;

    // ---- transpose + tf32-round all weights ----
    launch_transpose(Wl1, wt + WT_L1, 32, DIM);
    launch_transpose(Wr1, wt + WT_R1, 32, DIM);
    launch_transpose(W_down, wt + WT_DN, DIM, DIM);
    launch_transpose(Wl2, wt + WT_L2, DIM, DIM);
    launch_transpose(Wr2, wt + WT_R2, DIM, DIM);
    launch_transpose(W_up, wt + WT_UP, DIM, DIM);
    launch_transpose(W_cls, wt + WT_CLS, DIM, 1000);

    // ---- input projection (K=18, fp32) ----
    {
        dim3 grid(1, (n + BM - 1) / BM);
        sgemm_kernel<<<grid, 256>>>(x_gnn, W_in, b_in, h0, n, 32, 18);
    }

    // ---- GAT layer 1 ----
    launch_tgemm(h0, wt + WT_L1, nullptr, xl, n, DIM, 32);
    launch_tgemm(h0, wt + WT_R1, nullptr, xr, n, DIM, 32);
    zero2_kernel<<<zeroBlocks, 256>>>((float4*)sb, nh4, (float4*)agg, nd4);
    edge_fused_kernel<<<edgeBlocks, 256>>>(xl, xr, eattr, We1, att1, src, dst, sb, agg, E);
    ln_kernel<<<lnBlocks, 256>>>(agg, sb, nullptr, bg1, ln1_g, ln1_b, h1, n);

    // ---- bottleneck down ----
    launch_tgemm(h1, wt + WT_DN, nullptr, tmp, n, DIM, DIM);
    ln_kernel<<<lnBlocks, 256>>>(tmp, nullptr, nullptr, nullptr, lnd_g, lnd_b, z, n);

    // ---- GAT layer 2 ----
    launch_tgemm(z, wt + WT_L2, nullptr, xl, n, DIM, DIM);
    launch_tgemm(z, wt + WT_R2, nullptr, xr, n, DIM, DIM);
    zero2_kernel<<<zeroBlocks, 256>>>((float4*)sb, nh4, (float4*)agg, nd4);
    edge_fused_kernel<<<edgeBlocks, 256>>>(xl, xr, eattr, We2, att2, src, dst, sb, agg, E);
    ln_kernel<<<lnBlocks, 256>>>(agg, sb, z, bg2, ln2_g, ln2_b, z2, n);

    // ---- up projection + final LN ----
    launch_tgemm(z2, wt + WT_UP, nullptr, tmp, n, DIM, DIM);
    ln_kernel<<<lnBlocks, 256>>>(tmp, nullptr, h1, nullptr, lnu_g, lnu_b, out_h, n);

    // ---- classifier ----
    launch_tgemm(out_h, wt + WT_CLS, b_cls, out_logits, n, 1000, DIM);
}

// round 6
// speedup vs baseline: 2.4009x; 1.0474x over previous
#include <cuda_runtime.h>
#include <math.h>
#include <stdint.h>

// ---------------- problem constants ----------------
#define NMAX 20000
#define EMAX 320000
#define DIM 256
#define HEADS 8

// ---------------- scratch ----------------
__device__ float g_h0[NMAX * 32];
__device__ float g_xlr[NMAX * 512];       // [n, 0:256]=xl, [n, 256:512]=xr
__device__ float g_agg[NMAX * DIM];
__device__ float g_h1[NMAX * DIM];
__device__ float g_z[NMAX * DIM];
__device__ float g_z2[NMAX * DIM];
__device__ float g_tmp[NMAX * DIM];
__device__ float g_s[NMAX * HEADS];
// transposed (and tf32-RN-rounded) weights
__device__ float g_wt[8192 + 8192 + 4 * 65536 + 256000];

#define WT_L1 0
#define WT_R1 8192
#define WT_DN 16384
#define WT_L2 (16384 + 65536)
#define WT_R2 (16384 + 2 * 65536)
#define WT_UP (16384 + 3 * 65536)
#define WT_CLS (16384 + 4 * 65536)

// ---------------- helpers ----------------
__device__ __forceinline__ float warpReduceSum(float v) {
#pragma unroll
    for (int o = 16; o > 0; o >>= 1) v += __shfl_xor_sync(0xffffffffu, v, o);
    return v;
}

__device__ __forceinline__ void redAdd4(float* addr, float4 v) {
    asm volatile("red.global.add.v4.f32 [%0], {%1,%2,%3,%4};"
                 :: "l"(addr), "f"(v.x), "f"(v.y), "f"(v.z), "f"(v.w) : "memory");
}

__device__ __forceinline__ float leaky(float v) { return v > 0.f ? v : 0.2f * v; }

__device__ __forceinline__ uint32_t smem_u32(const void* p) {
    uint32_t a;
    asm("{ .reg .u64 t; cvta.to.shared.u64 t, %1; cvt.u32.u64 %0, t; }" : "=r"(a) : "l"(p));
    return a;
}

__device__ __forceinline__ uint32_t tf32_rn(float f) {
    uint32_t r;
    asm("cvt.rna.tf32.f32 %0, %1;" : "=r"(r) : "f"(f));
    return r;
}

__device__ __forceinline__ void cpasync16(uint32_t dst, const void* src, bool valid) {
    int sz = valid ? 16 : 0;
    asm volatile("cp.async.cg.shared.global [%0], [%1], 16, %2;"
                 :: "r"(dst), "l"(src), "r"(sz));
}

__device__ __forceinline__ void cpasync_commit() { asm volatile("cp.async.commit_group;"); }
__device__ __forceinline__ void cpasync_wait0() { asm volatile("cp.async.wait_group 0;"); }

// ---------------- fill (float4) ----------------
__global__ void fill4_kernel(float4* __restrict__ p, int n4) {
    int i = blockIdx.x * blockDim.x + threadIdx.x;
    if (i < n4) p[i] = make_float4(0.f, 0.f, 0.f, 0.f);
}

// ---------------- fused transpose-all: 7 matrices, in[K,N] -> out[N,K] + tf32 round ----
struct TransDesc { const float* in; float* out; int K, N, blkStart, nx; };
struct TransDescs { TransDesc d[7]; int total; };

__global__ void transpose_all_kernel(TransDescs td) {
    __shared__ float t[32][33];
    int bid = blockIdx.x;
    int di = 0;
#pragma unroll
    for (int i = 1; i < 7; i++) if (bid >= td.d[i].blkStart) di = i;
    const TransDesc& D = td.d[di];
    int rem = bid - D.blkStart;
    int bx = (rem % D.nx) * 32, by = (rem / D.nx) * 32;
    int x = bx + threadIdx.x;
    int y = by + threadIdx.y;
#pragma unroll
    for (int i = 0; i < 32; i += 8)
        if (x < D.N && y + i < D.K) t[threadIdx.y + i][threadIdx.x] = D.in[(size_t)(y + i) * D.N + x];
    __syncthreads();
    x = by + threadIdx.x;
    y = bx + threadIdx.y;
#pragma unroll
    for (int i = 0; i < 32; i += 8)
        if (x < D.K && y + i < D.N)
            D.out[(size_t)(y + i) * D.K + x] = __uint_as_float(tf32_rn(t[threadIdx.x][threadIdx.y + i]));
}

// ---------------- tf32 mma.sync GEMM: C[M,N] = A[M,K] @ WT[N,K]^T (+bias) ----------------
#define GSTR 36
#define CHUNK_FLOATS (128 * GSTR)

extern __shared__ float g_dynsmem[];

__global__ __launch_bounds__(256)
void mma_gemm(const float* __restrict__ A, const float* __restrict__ WT,
              const float* __restrict__ bias, float* __restrict__ C,
              int M, int N, int K) {
    float* sA[2] = { g_dynsmem, g_dynsmem + 2 * CHUNK_FLOATS };
    float* sB[2] = { g_dynsmem + CHUNK_FLOATS, g_dynsmem + 3 * CHUNK_FLOATS };

    const int tid = threadIdx.x;
    const int wid = tid >> 5, lane = tid & 31;
    const int gid = lane >> 2, tig = lane & 3;
    const int wm = (wid >> 2) * 64, wn = (wid & 3) * 32;
    const int m0 = blockIdx.y * 128, n0 = blockIdx.x * 128;

    float acc[4][4][4];
#pragma unroll
    for (int mi = 0; mi < 4; mi++)
#pragma unroll
        for (int ni = 0; ni < 4; ni++)
#pragma unroll
            for (int q = 0; q < 4; q++) acc[mi][ni][q] = 0.f;

    const int nc = K >> 5;
    uint32_t sAaddr[2] = { smem_u32(sA[0]), smem_u32(sA[1]) };
    uint32_t sBaddr[2] = { smem_u32(sB[0]), smem_u32(sB[1]) };

    auto issue = [&](int c, int b) {
        int k0 = c << 5;
#pragma unroll
        for (int i = 0; i < 4; i++) {
            int idx = tid + i * 256;
            int row = idx >> 3, q = idx & 7;
            uint32_t soff = (uint32_t)(row * GSTR + q * 4) * 4u;
            int ga = m0 + row;
            cpasync16(sAaddr[b] + soff, A + (size_t)ga * K + k0 + q * 4, ga < M);
            int gb = n0 + row;
            cpasync16(sBaddr[b] + soff, WT + (size_t)gb * K + k0 + q * 4, gb < N);
        }
        cpasync_commit();
    };

    issue(0, 0);
    for (int c = 0; c < nc; c++) {
        int cur = c & 1;
        cpasync_wait0();
        __syncthreads();
        if (c + 1 < nc) issue(c + 1, cur ^ 1);
        const float* cA = sA[cur];
        const float* cB = sB[cur];
#pragma unroll
        for (int ks = 0; ks < 4; ks++) {
            int ko = ks * 8;
            uint32_t af[4][4], bf[4][2];
#pragma unroll
            for (int mi = 0; mi < 4; mi++) {
                const float* base = cA + (wm + mi * 16 + gid) * GSTR + ko + tig;
                af[mi][0] = tf32_rn(base[0]);
                af[mi][1] = tf32_rn(base[8 * GSTR]);
                af[mi][2] = tf32_rn(base[4]);
                af[mi][3] = tf32_rn(base[8 * GSTR + 4]);
            }
#pragma unroll
            for (int ni = 0; ni < 4; ni++) {
                const float* base = cB + (wn + ni * 8 + gid) * GSTR + ko + tig;
                bf[ni][0] = __float_as_uint(base[0]);
                bf[ni][1] = __float_as_uint(base[4]);
            }
#pragma unroll
            for (int mi = 0; mi < 4; mi++)
#pragma unroll
                for (int ni = 0; ni < 4; ni++) {
                    asm volatile(
                        "mma.sync.aligned.m16n8k8.row.col.f32.tf32.tf32.f32 "
                        "{%0,%1,%2,%3}, {%4,%5,%6,%7}, {%8,%9}, {%0,%1,%2,%3};"
                        : "+f"(acc[mi][ni][0]), "+f"(acc[mi][ni][1]),
                          "+f"(acc[mi][ni][2]), "+f"(acc[mi][ni][3])
                        : "r"(af[mi][0]), "r"(af[mi][1]), "r"(af[mi][2]), "r"(af[mi][3]),
                          "r"(bf[ni][0]), "r"(bf[ni][1]));
                }
        }
        __syncthreads();
    }

#pragma unroll
    for (int mi = 0; mi < 4; mi++) {
        int r0 = m0 + wm + mi * 16 + gid;
        int r1 = r0 + 8;
#pragma unroll
        for (int ni = 0; ni < 4; ni++) {
            int col = n0 + wn + ni * 8 + tig * 2;
            if (col >= N) continue;
            float bx = 0.f, by = 0.f;
            if (bias) { bx = bias[col]; by = bias[col + 1]; }
            if (r0 < M)
                *(float2*)(C + (size_t)r0 * N + col) =
                    make_float2(acc[mi][ni][0] + bx, acc[mi][ni][1] + by);
            if (r1 < M)
                *(float2*)(C + (size_t)r1 * N + col) =
                    make_float2(acc[mi][ni][2] + bx, acc[mi][ni][3] + by);
        }
    }
}

// ---------------- small fp32 SGEMM (for W_in, K=18) ----------------
#define BM 64
#define BN 64
#define BK 16
__global__ void sgemm_kernel(const float* __restrict__ A, const float* __restrict__ B,
                             const float* __restrict__ bias, float* __restrict__ C,
                             int M, int N, int K) {
    __shared__ float As[BK][BM + 4];
    __shared__ float Bs[BK][BN];
    int tid = threadIdx.x;
    int tr = tid >> 4, tc = tid & 15;
    int row0 = blockIdx.y * BM, col0 = blockIdx.x * BN;
    float acc[4][4] = {};
    int ntile = (K + BK - 1) / BK;
    for (int t = 0; t < ntile; t++) {
        int k0 = t * BK;
        {
            int r = tid >> 2;
            int gr = row0 + r;
#pragma unroll
            for (int i = 0; i < 4; i++) {
                int kk = ((tid & 3) << 2) + i;
                int gk = k0 + kk;
                As[kk][r] = (gr < M && gk < K) ? A[(size_t)gr * K + gk] : 0.f;
            }
        }
#pragma unroll
        for (int i = 0; i < 4; i++) {
            int idx = tid + i * 256;
            int ccol = idx & 63, kk = idx >> 6;
            int gk = k0 + kk, gc = col0 + ccol;
            Bs[kk][ccol] = (gk < K && gc < N) ? B[(size_t)gk * N + gc] : 0.f;
        }
        __syncthreads();
#pragma unroll
        for (int kk = 0; kk < BK; kk++) {
            float a[4], b[4];
#pragma unroll
            for (int i = 0; i < 4; i++) a[i] = As[kk][tr * 4 + i];
#pragma unroll
            for (int j = 0; j < 4; j++) b[j] = Bs[kk][tc * 4 + j];
#pragma unroll
            for (int i = 0; i < 4; i++)
#pragma unroll
                for (int j = 0; j < 4; j++) acc[i][j] += a[i] * b[j];
        }
        __syncthreads();
    }
#pragma unroll
    for (int i = 0; i < 4; i++) {
        int gr = row0 + tr * 4 + i;
        if (gr >= M) continue;
#pragma unroll
        for (int j = 0; j < 4; j++) {
            int gc = col0 + tc * 4 + j;
            if (gc < N) C[(size_t)gr * N + gc] = acc[i][j] + (bias ? bias[gc] : 0.f);
        }
    }
}

// ---------------- fused edge pass (xlr layout, stride 512) ----------------
__global__ void edge_fused_kernel(const float* __restrict__ xlr,
                                  const float* __restrict__ ea, const float* __restrict__ We,
                                  const float* __restrict__ att,
                                  const int* __restrict__ src, const int* __restrict__ dst,
                                  float* __restrict__ ssum, float* __restrict__ agg, int E) {
    int e = (blockIdx.x * blockDim.x + threadIdx.x) >> 5;
    int lane = threadIdx.x & 31;
    if (e >= E) return;
    int s = src[e], d = dst[e];
    float a = ea[e];
    const float4* xls = (const float4*)(xlr + (size_t)s * 512);
    const float4* xrd = (const float4*)(xlr + (size_t)d * 512 + 256);
    const float4* We4 = (const float4*)We;
    const float4* at4 = (const float4*)att;
    float* aggd = agg + (size_t)d * DIM;
#pragma unroll
    for (int c = 0; c < 2; c++) {
        int q = c * 32 + lane;
        float4 l = xls[q], r = xrd[q], w = We4[q], t = at4[q];
        float p = leaky(l.x + r.x + a * w.x) * t.x + leaky(l.y + r.y + a * w.y) * t.y
                + leaky(l.z + r.z + a * w.z) * t.z + leaky(l.w + r.w + a * w.w) * t.w;
        p += __shfl_xor_sync(0xffffffffu, p, 1);
        p += __shfl_xor_sync(0xffffffffu, p, 2);
        p += __shfl_xor_sync(0xffffffffu, p, 4);
        float ex = __expf(p);
        redAdd4(aggd + q * 4, make_float4(ex * l.x, ex * l.y, ex * l.z, ex * l.w));
        if ((lane & 7) == 0) {
            int h = c * 4 + (lane >> 3);
            atomicAdd(&ssum[d * 8 + h], ex);
        }
    }
}

// ---------------- layernorm (dim=256); optional ssum normalize, residual, bias ----------
__global__ void ln_kernel(const float* __restrict__ x, const float* __restrict__ ssum,
                          const float* __restrict__ res, const float* __restrict__ bias,
                          const float* __restrict__ g, const float* __restrict__ b,
                          float* __restrict__ out, int n) {
    int row = blockIdx.x * 8 + (threadIdx.x >> 5);
    int lane = threadIdx.x & 31;
    if (row >= n) return;
    const float4* xr4 = (const float4*)(x + (size_t)row * DIM);
    const float4* rs4 = res ? (const float4*)(res + (size_t)row * DIM) : nullptr;
    const float4* bi4 = bias ? (const float4*)bias : nullptr;
    float4 v[2];
    float sum = 0.f;
#pragma unroll
    for (int k = 0; k < 2; k++) {
        int q = k * 32 + lane;
        float4 t = xr4[q];
        if (ssum) {
            int h = q >> 3;
            float inv = 1.f / (ssum[row * 8 + h] + 1e-16f);
            t.x *= inv; t.y *= inv; t.z *= inv; t.w *= inv;
        }
        if (rs4) { float4 r = rs4[q]; t.x += r.x; t.y += r.y; t.z += r.z; t.w += r.w; }
        if (bi4) { float4 r = bi4[q]; t.x += r.x; t.y += r.y; t.z += r.z; t.w += r.w; }
        v[k] = t;
        sum += t.x + t.y + t.z + t.w;
    }
    sum = warpReduceSum(sum);
    float mu = sum * (1.f / 256.f);
    float var = 0.f;
#pragma unroll
    for (int k = 0; k < 2; k++) {
        float dx = v[k].x - mu, dy = v[k].y - mu, dz = v[k].z - mu, dw = v[k].w - mu;
        var += dx * dx + dy * dy + dz * dz + dw * dw;
    }
    var = warpReduceSum(var) * (1.f / 256.f);
    float inv = rsqrtf(var + 1e-5f);
    const float4* g4 = (const float4*)g;
    const float4* b4 = (const float4*)b;
    float4* o4 = (float4*)(out + (size_t)row * DIM);
#pragma unroll
    for (int k = 0; k < 2; k++) {
        int q = k * 32 + lane;
        float4 gg = g4[q], bb = b4[q];
        o4[q] = make_float4((v[k].x - mu) * inv * gg.x + bb.x,
                            (v[k].y - mu) * inv * gg.y + bb.y,
                            (v[k].z - mu) * inv * gg.z + bb.z,
                            (v[k].w - mu) * inv * gg.w + bb.w);
    }
}

// ---------------- host ----------------
#define DYN_SMEM (4 * CHUNK_FLOATS * sizeof(float))

static inline void launch_tgemm(const float* A, const float* WT, const float* bias, float* C,
                                int M, int N, int K) {
    dim3 grid((N + 127) / 128, (M + 127) / 128);
    mma_gemm<<<grid, 256, DYN_SMEM>>>(A, WT, bias, C, M, N, K);
}

extern "C" void kernel_launch(void* const* d_in, const int* in_sizes, int n_in,
                              void* d_out, int out_size) {
    cudaFuncSetAttribute(mma_gemm, cudaFuncAttributeMaxDynamicSharedMemorySize, DYN_SMEM);

    const float* x_gnn = (const float*)d_in[0];
    const int*   eidx  = (const int*)d_in[1];
    const float* eattr = (const float*)d_in[2];
    const float* W_in  = (const float*)d_in[3];
    const float* b_in  = (const float*)d_in[4];
    const float* Wl1   = (const float*)d_in[5];
    const float* Wr1   = (const float*)d_in[6];
    const float* We1   = (const float*)d_in[7];
    const float* att1  = (const float*)d_in[8];
    const float* bg1   = (const float*)d_in[9];
    const float* ln1_g = (const float*)d_in[10];
    const float* ln1_b = (const float*)d_in[11];
    const float* W_down= (const float*)d_in[12];
    const float* lnd_g = (const float*)d_in[13];
    const float* lnd_b = (const float*)d_in[14];
    const float* Wl2   = (const float*)d_in[15];
    const float* Wr2   = (const float*)d_in[16];
    const float* We2   = (const float*)d_in[17];
    const float* att2  = (const float*)d_in[18];
    const float* bg2   = (const float*)d_in[19];
    const float* ln2_g = (const float*)d_in[20];
    const float* ln2_b = (const float*)d_in[21];
    const float* W_up  = (const float*)d_in[22];
    const float* lnu_g = (const float*)d_in[23];
    const float* lnu_b = (const float*)d_in[24];
    const float* W_cls = (const float*)d_in[25];
    const float* b_cls = (const float*)d_in[26];

    const int n = in_sizes[0] / 18;        // 20000
    const int E = in_sizes[1] / 2;         // 320000
    const int* src = eidx;
    const int* dst = eidx + E;

    float *h0, *xlr, *agg, *h1, *z, *z2, *tmp, *sb, *wt;
    cudaGetSymbolAddress((void**)&h0, g_h0);
    cudaGetSymbolAddress((void**)&xlr, g_xlr);
    cudaGetSymbolAddress((void**)&agg, g_agg);
    cudaGetSymbolAddress((void**)&h1, g_h1);
    cudaGetSymbolAddress((void**)&z, g_z);
    cudaGetSymbolAddress((void**)&z2, g_z2);
    cudaGetSymbolAddress((void**)&tmp, g_tmp);
    cudaGetSymbolAddress((void**)&sb, g_s);
    cudaGetSymbolAddress((void**)&wt, g_wt);

    float* out_logits = (float*)d_out;
    float* out_h = (float*)d_out + (size_t)n * 1000;

    const int edgeBlocks = (E + 7) / 8;
    const int lnBlocks = (n + 7) / 8;
    const int nh4 = n * HEADS / 4;
    const int nd4 = n * DIM / 4;

    // ---- fused transpose of all 7 weights (one launch) ----
    {
        TransDescs td;
        auto set = [&](int i, const float* in, float* out, int K, int N, int& cum) {
            td.d[i].in = in; td.d[i].out = out; td.d[i].K = K; td.d[i].N = N;
            td.d[i].blkStart = cum; td.d[i].nx = (N + 31) / 32;
            cum += td.d[i].nx * ((K + 31) / 32);
        };
        int cum = 0;
        set(0, Wl1,    wt + WT_L1, 32, DIM, cum);
        set(1, Wr1,    wt + WT_R1, 32, DIM, cum);
        set(2, W_down, wt + WT_DN, DIM, DIM, cum);
        set(3, Wl2,    wt + WT_L2, DIM, DIM, cum);
        set(4, Wr2,    wt + WT_R2, DIM, DIM, cum);
        set(5, W_up,   wt + WT_UP, DIM, DIM, cum);
        set(6, W_cls,  wt + WT_CLS, DIM, 1000, cum);
        td.total = cum;
        transpose_all_kernel<<<cum, dim3(32, 8)>>>(td);
    }

    // ---- input projection (K=18, fp32) ----
    {
        dim3 grid(1, (n + BM - 1) / BM);
        sgemm_kernel<<<grid, 256>>>(x_gnn, W_in, b_in, h0, n, 32, 18);
    }

    // ---- GAT layer 1: fused xl|xr GEMM (N=512) ----
    launch_tgemm(h0, wt + WT_L1, nullptr, xlr, n, 512, 32);
    fill4_kernel<<<(nh4 + 255) / 256, 256>>>((float4*)sb, nh4);
    fill4_kernel<<<(nd4 + 255) / 256, 256>>>((float4*)agg, nd4);
    edge_fused_kernel<<<edgeBlocks, 256>>>(xlr, eattr, We1, att1, src, dst, sb, agg, E);   // launch #5
    ln_kernel<<<lnBlocks, 256>>>(agg, sb, nullptr, bg1, ln1_g, ln1_b, h1, n);

    // ---- bottleneck down ----
    launch_tgemm(h1, wt + WT_DN, nullptr, tmp, n, DIM, DIM);
    ln_kernel<<<lnBlocks, 256>>>(tmp, nullptr, nullptr, nullptr, lnd_g, lnd_b, z, n);

    // ---- GAT layer 2: fused xl|xr GEMM (N=512) ----
    launch_tgemm(z, wt + WT_L2, nullptr, xlr, n, 512, DIM);
    fill4_kernel<<<(nh4 + 255) / 256, 256>>>((float4*)sb, nh4);
    fill4_kernel<<<(nd4 + 255) / 256, 256>>>((float4*)agg, nd4);
    edge_fused_kernel<<<edgeBlocks, 256>>>(xlr, eattr, We2, att2, src, dst, sb, agg, E);
    ln_kernel<<<lnBlocks, 256>>>(agg, sb, z, bg2, ln2_g, ln2_b, z2, n);

    // ---- up projection + final LN ----
    launch_tgemm(z2, wt + WT_UP, nullptr, tmp, n, DIM, DIM);
    ln_kernel<<<lnBlocks, 256>>>(tmp, nullptr, h1, nullptr, lnu_g, lnu_b, out_h, n);

    // ---- classifier ----
    launch_tgemm(out_h, wt + WT_CLS, b_cls, out_logits, n, 1000, DIM);
}

// round 7
// speedup vs baseline: 2.6408x; 1.0999x over previous
#include <cuda_runtime.h>
#include <math.h>
#include <stdint.h>

// ---------------- problem constants ----------------
#define NMAX 20000
#define EMAX 320000
#define DIM 256
#define HEADS 8

// ---------------- scratch ----------------
__device__ float g_h0[NMAX * 32];
__device__ float g_xlr[NMAX * 512];       // [n, 0:256]=xl, [n, 256:512]=xr
__device__ float g_agg[NMAX * DIM];
__device__ float g_h1[NMAX * DIM];
__device__ float g_z[NMAX * DIM];
__device__ float g_z2[NMAX * DIM];
__device__ float g_tmp[NMAX * DIM];
// CSR by dst
__device__ int   g_deg[NMAX];
__device__ int   g_cur[NMAX];
__device__ int   g_off[NMAX + 1];
__device__ int   g_esrc[EMAX];
__device__ float g_eea[EMAX];
// transposed (and tf32-RN-rounded) weights
__device__ float g_wt[8192 + 8192 + 4 * 65536 + 256000];

#define WT_L1 0
#define WT_R1 8192
#define WT_DN 16384
#define WT_L2 (16384 + 65536)
#define WT_R2 (16384 + 2 * 65536)
#define WT_UP (16384 + 3 * 65536)
#define WT_CLS (16384 + 4 * 65536)

// ---------------- helpers ----------------
__device__ __forceinline__ float warpReduceSum(float v) {
#pragma unroll
    for (int o = 16; o > 0; o >>= 1) v += __shfl_xor_sync(0xffffffffu, v, o);
    return v;
}

__device__ __forceinline__ float leaky(float v) { return v > 0.f ? v : 0.2f * v; }

__device__ __forceinline__ uint32_t smem_u32(const void* p) {
    uint32_t a;
    asm("{ .reg .u64 t; cvta.to.shared.u64 t, %1; cvt.u32.u64 %0, t; }" : "=r"(a) : "l"(p));
    return a;
}

__device__ __forceinline__ uint32_t tf32_rn(float f) {
    uint32_t r;
    asm("cvt.rna.tf32.f32 %0, %1;" : "=r"(r) : "f"(f));
    return r;
}

__device__ __forceinline__ void cpasync16(uint32_t dst, const void* src, bool valid) {
    int sz = valid ? 16 : 0;
    asm volatile("cp.async.cg.shared.global [%0], [%1], 16, %2;"
                 :: "r"(dst), "l"(src), "r"(sz));
}

__device__ __forceinline__ void cpasync_commit() { asm volatile("cp.async.commit_group;"); }
__device__ __forceinline__ void cpasync_wait0() { asm volatile("cp.async.wait_group 0;"); }

// ---------------- CSR build ----------------
__global__ void zero_int2_kernel(int* __restrict__ a, int* __restrict__ b, int n) {
    int i = blockIdx.x * blockDim.x + threadIdx.x;
    if (i < n) { a[i] = 0; b[i] = 0; }
}

__global__ void hist_kernel(const int* __restrict__ dst, int* __restrict__ deg, int E) {
    int e = blockIdx.x * blockDim.x + threadIdx.x;
    if (e < E) atomicAdd(&deg[dst[e]], 1);
}

__global__ void scan_kernel(const int* __restrict__ deg, int* __restrict__ off, int n) {
    __shared__ int warp_sums[32];
    __shared__ int carry_s;
    int tid = threadIdx.x;                    // 1024 threads, single block
    if (tid == 0) carry_s = 0;
    __syncthreads();
    for (int base = 0; base < n; base += 1024) {
        int i = base + tid;
        int v = (i < n) ? deg[i] : 0;
        int x = v;
#pragma unroll
        for (int o = 1; o < 32; o <<= 1) {
            int y = __shfl_up_sync(0xffffffffu, x, o);
            if ((tid & 31) >= o) x += y;
        }
        if ((tid & 31) == 31) warp_sums[tid >> 5] = x;
        __syncthreads();
        if (tid < 32) {
            int s = warp_sums[tid];
#pragma unroll
            for (int o = 1; o < 32; o <<= 1) {
                int y = __shfl_up_sync(0xffffffffu, s, o);
                if (tid >= o) s += y;
            }
            warp_sums[tid] = s;
        }
        __syncthreads();
        int incl = x + ((tid >= 32) ? warp_sums[(tid >> 5) - 1] : 0);
        if (i < n) off[i] = carry_s + incl - v;
        __syncthreads();
        if (tid == 1023) carry_s += incl;
        __syncthreads();
    }
    if (tid == 0) off[n] = carry_s;
}

__global__ void scatter_kernel(const int* __restrict__ src, const int* __restrict__ dst,
                               const float* __restrict__ ea, const int* __restrict__ off,
                               int* __restrict__ cur, int* __restrict__ esrc,
                               float* __restrict__ eea, int E) {
    int e = blockIdx.x * blockDim.x + threadIdx.x;
    if (e >= E) return;
    int d = dst[e];
    int pos = off[d] + atomicAdd(&cur[d], 1);
    esrc[pos] = src[e];
    eea[pos] = ea[e];
}

// ---------------- fused transpose-all ----------------
struct TransDesc { const float* in; float* out; int K, N, blkStart, nx; };
struct TransDescs { TransDesc d[7]; int total; };

__global__ void transpose_all_kernel(TransDescs td) {
    __shared__ float t[32][33];
    int bid = blockIdx.x;
    int di = 0;
#pragma unroll
    for (int i = 1; i < 7; i++) if (bid >= td.d[i].blkStart) di = i;
    const TransDesc& D = td.d[di];
    int rem = bid - D.blkStart;
    int bx = (rem % D.nx) * 32, by = (rem / D.nx) * 32;
    int x = bx + threadIdx.x;
    int y = by + threadIdx.y;
#pragma unroll
    for (int i = 0; i < 32; i += 8)
        if (x < D.N && y + i < D.K) t[threadIdx.y + i][threadIdx.x] = D.in[(size_t)(y + i) * D.N + x];
    __syncthreads();
    x = by + threadIdx.x;
    y = bx + threadIdx.y;
#pragma unroll
    for (int i = 0; i < 32; i += 8)
        if (x < D.K && y + i < D.N)
            D.out[(size_t)(y + i) * D.K + x] = __uint_as_float(tf32_rn(t[threadIdx.x][threadIdx.y + i]));
}

// ---------------- tf32 mma.sync GEMM ----------------
#define GSTR 36
#define CHUNK_FLOATS (128 * GSTR)

extern __shared__ float g_dynsmem[];

__global__ __launch_bounds__(256)
void mma_gemm(const float* __restrict__ A, const float* __restrict__ WT,
              const float* __restrict__ bias, float* __restrict__ C,
              int M, int N, int K) {
    float* sA[2] = { g_dynsmem, g_dynsmem + 2 * CHUNK_FLOATS };
    float* sB[2] = { g_dynsmem + CHUNK_FLOATS, g_dynsmem + 3 * CHUNK_FLOATS };

    const int tid = threadIdx.x;
    const int wid = tid >> 5, lane = tid & 31;
    const int gid = lane >> 2, tig = lane & 3;
    const int wm = (wid >> 2) * 64, wn = (wid & 3) * 32;
    const int m0 = blockIdx.y * 128, n0 = blockIdx.x * 128;

    float acc[4][4][4];
#pragma unroll
    for (int mi = 0; mi < 4; mi++)
#pragma unroll
        for (int ni = 0; ni < 4; ni++)
#pragma unroll
            for (int q = 0; q < 4; q++) acc[mi][ni][q] = 0.f;

    const int nc = K >> 5;
    uint32_t sAaddr[2] = { smem_u32(sA[0]), smem_u32(sA[1]) };
    uint32_t sBaddr[2] = { smem_u32(sB[0]), smem_u32(sB[1]) };

    auto issue = [&](int c, int b) {
        int k0 = c << 5;
#pragma unroll
        for (int i = 0; i < 4; i++) {
            int idx = tid + i * 256;
            int row = idx >> 3, q = idx & 7;
            uint32_t soff = (uint32_t)(row * GSTR + q * 4) * 4u;
            int ga = m0 + row;
            cpasync16(sAaddr[b] + soff, A + (size_t)ga * K + k0 + q * 4, ga < M);
            int gb = n0 + row;
            cpasync16(sBaddr[b] + soff, WT + (size_t)gb * K + k0 + q * 4, gb < N);
        }
        cpasync_commit();
    };

    issue(0, 0);
    for (int c = 0; c < nc; c++) {
        int cur = c & 1;
        cpasync_wait0();
        __syncthreads();
        if (c + 1 < nc) issue(c + 1, cur ^ 1);
        const float* cA = sA[cur];
        const float* cB = sB[cur];
#pragma unroll
        for (int ks = 0; ks < 4; ks++) {
            int ko = ks * 8;
            uint32_t af[4][4], bf[4][2];
#pragma unroll
            for (int mi = 0; mi < 4; mi++) {
                const float* base = cA + (wm + mi * 16 + gid) * GSTR + ko + tig;
                af[mi][0] = tf32_rn(base[0]);
                af[mi][1] = tf32_rn(base[8 * GSTR]);
                af[mi][2] = tf32_rn(base[4]);
                af[mi][3] = tf32_rn(base[8 * GSTR + 4]);
            }
#pragma unroll
            for (int ni = 0; ni < 4; ni++) {
                const float* base = cB + (wn + ni * 8 + gid) * GSTR + ko + tig;
                bf[ni][0] = __float_as_uint(base[0]);
                bf[ni][1] = __float_as_uint(base[4]);
            }
#pragma unroll
            for (int mi = 0; mi < 4; mi++)
#pragma unroll
                for (int ni = 0; ni < 4; ni++) {
                    asm volatile(
                        "mma.sync.aligned.m16n8k8.row.col.f32.tf32.tf32.f32 "
                        "{%0,%1,%2,%3}, {%4,%5,%6,%7}, {%8,%9}, {%0,%1,%2,%3};"
                        : "+f"(acc[mi][ni][0]), "+f"(acc[mi][ni][1]),
                          "+f"(acc[mi][ni][2]), "+f"(acc[mi][ni][3])
                        : "r"(af[mi][0]), "r"(af[mi][1]), "r"(af[mi][2]), "r"(af[mi][3]),
                          "r"(bf[ni][0]), "r"(bf[ni][1]));
                }
        }
        __syncthreads();
    }

#pragma unroll
    for (int mi = 0; mi < 4; mi++) {
        int r0 = m0 + wm + mi * 16 + gid;
        int r1 = r0 + 8;
#pragma unroll
        for (int ni = 0; ni < 4; ni++) {
            int col = n0 + wn + ni * 8 + tig * 2;
            if (col >= N) continue;
            float bx = 0.f, by = 0.f;
            if (bias) { bx = bias[col]; by = bias[col + 1]; }
            if (r0 < M)
                *(float2*)(C + (size_t)r0 * N + col) =
                    make_float2(acc[mi][ni][0] + bx, acc[mi][ni][1] + by);
            if (r1 < M)
                *(float2*)(C + (size_t)r1 * N + col) =
                    make_float2(acc[mi][ni][2] + bx, acc[mi][ni][3] + by);
        }
    }
}

// ---------------- small fp32 SGEMM (for W_in, K=18) ----------------
#define BM 64
#define BN 64
#define BK 16
__global__ void sgemm_kernel(const float* __restrict__ A, const float* __restrict__ B,
                             const float* __restrict__ bias, float* __restrict__ C,
                             int M, int N, int K) {
    __shared__ float As[BK][BM + 4];
    __shared__ float Bs[BK][BN];
    int tid = threadIdx.x;
    int tr = tid >> 4, tc = tid & 15;
    int row0 = blockIdx.y * BM, col0 = blockIdx.x * BN;
    float acc[4][4] = {};
    int ntile = (K + BK - 1) / BK;
    for (int t = 0; t < ntile; t++) {
        int k0 = t * BK;
        {
            int r = tid >> 2;
            int gr = row0 + r;
#pragma unroll
            for (int i = 0; i < 4; i++) {
                int kk = ((tid & 3) << 2) + i;
                int gk = k0 + kk;
                As[kk][r] = (gr < M && gk < K) ? A[(size_t)gr * K + gk] : 0.f;
            }
        }
#pragma unroll
        for (int i = 0; i < 4; i++) {
            int idx = tid + i * 256;
            int ccol = idx & 63, kk = idx >> 6;
            int gk = k0 + kk, gc = col0 + ccol;
            Bs[kk][ccol] = (gk < K && gc < N) ? B[(size_t)gk * N + gc] : 0.f;
        }
        __syncthreads();
#pragma unroll
        for (int kk = 0; kk < BK; kk++) {
            float a[4], b[4];
#pragma unroll
            for (int i = 0; i < 4; i++) a[i] = As[kk][tr * 4 + i];
#pragma unroll
            for (int j = 0; j < 4; j++) b[j] = Bs[kk][tc * 4 + j];
#pragma unroll
            for (int i = 0; i < 4; i++)
#pragma unroll
                for (int j = 0; j < 4; j++) acc[i][j] += a[i] * b[j];
        }
        __syncthreads();
    }
#pragma unroll
    for (int i = 0; i < 4; i++) {
        int gr = row0 + tr * 4 + i;
        if (gr >= M) continue;
#pragma unroll
        for (int j = 0; j < 4; j++) {
            int gc = col0 + tc * 4 + j;
            if (gc < N) C[(size_t)gr * N + gc] = acc[i][j] + (bias ? bias[gc] : 0.f);
        }
    }
}

// ---------------- CSR gather GAT: warp per dst node ----------------
// agg[d] = (1/ssum) * sum_i exp(score_i) * xl[src_i]  (normalized, no atomics)
__global__ void gat_gather_kernel(const float* __restrict__ xlr,
                                  const int* __restrict__ off, const int* __restrict__ esrc,
                                  const float* __restrict__ eea,
                                  const float* __restrict__ We, const float* __restrict__ att,
                                  float* __restrict__ agg, int n) {
    int d = (blockIdx.x * blockDim.x + threadIdx.x) >> 5;
    int lane = threadIdx.x & 31;
    if (d >= n) return;
    const float4* xrd = (const float4*)(xlr + (size_t)d * 512 + 256);
    float4 r0 = xrd[lane], r1 = xrd[32 + lane];
    float4 w0 = ((const float4*)We)[lane],  w1 = ((const float4*)We)[32 + lane];
    float4 t0 = ((const float4*)att)[lane], t1 = ((const float4*)att)[32 + lane];
    float4 acc0 = make_float4(0.f, 0.f, 0.f, 0.f), acc1 = acc0;
    float ss0 = 0.f, ss1 = 0.f;
    int beg = off[d], end = off[d + 1];
    for (int i = beg; i < end; i++) {
        int s = esrc[i];
        float a = eea[i];
        const float4* xls = (const float4*)(xlr + (size_t)s * 512);
        float4 l0 = xls[lane], l1 = xls[32 + lane];
        float p0 = leaky(l0.x + r0.x + a * w0.x) * t0.x + leaky(l0.y + r0.y + a * w0.y) * t0.y
                 + leaky(l0.z + r0.z + a * w0.z) * t0.z + leaky(l0.w + r0.w + a * w0.w) * t0.w;
        float p1 = leaky(l1.x + r1.x + a * w1.x) * t1.x + leaky(l1.y + r1.y + a * w1.y) * t1.y
                 + leaky(l1.z + r1.z + a * w1.z) * t1.z + leaky(l1.w + r1.w + a * w1.w) * t1.w;
        p0 += __shfl_xor_sync(0xffffffffu, p0, 1);
        p1 += __shfl_xor_sync(0xffffffffu, p1, 1);
        p0 += __shfl_xor_sync(0xffffffffu, p0, 2);
        p1 += __shfl_xor_sync(0xffffffffu, p1, 2);
        p0 += __shfl_xor_sync(0xffffffffu, p0, 4);
        p1 += __shfl_xor_sync(0xffffffffu, p1, 4);
        float e0 = __expf(p0), e1 = __expf(p1);
        acc0.x += e0 * l0.x; acc0.y += e0 * l0.y; acc0.z += e0 * l0.z; acc0.w += e0 * l0.w;
        acc1.x += e1 * l1.x; acc1.y += e1 * l1.y; acc1.z += e1 * l1.z; acc1.w += e1 * l1.w;
        ss0 += e0; ss1 += e1;
    }
    float i0 = 1.f / (ss0 + 1e-16f), i1 = 1.f / (ss1 + 1e-16f);
    float4* o = (float4*)(agg + (size_t)d * DIM);
    o[lane]      = make_float4(acc0.x * i0, acc0.y * i0, acc0.z * i0, acc0.w * i0);
    o[32 + lane] = make_float4(acc1.x * i1, acc1.y * i1, acc1.z * i1, acc1.w * i1);
}

// ---------------- layernorm (dim=256); optional residual, bias ----------
__global__ void ln_kernel(const float* __restrict__ x, const float* __restrict__ res,
                          const float* __restrict__ bias, const float* __restrict__ g,
                          const float* __restrict__ b, float* __restrict__ out, int n) {
    int row = blockIdx.x * 8 + (threadIdx.x >> 5);
    int lane = threadIdx.x & 31;
    if (row >= n) return;
    const float4* xr4 = (const float4*)(x + (size_t)row * DIM);
    const float4* rs4 = res ? (const float4*)(res + (size_t)row * DIM) : nullptr;
    const float4* bi4 = bias ? (const float4*)bias : nullptr;
    float4 v[2];
    float sum = 0.f;
#pragma unroll
    for (int k = 0; k < 2; k++) {
        int q = k * 32 + lane;
        float4 t = xr4[q];
        if (rs4) { float4 r = rs4[q]; t.x += r.x; t.y += r.y; t.z += r.z; t.w += r.w; }
        if (bi4) { float4 r = bi4[q]; t.x += r.x; t.y += r.y; t.z += r.z; t.w += r.w; }
        v[k] = t;
        sum += t.x + t.y + t.z + t.w;
    }
    sum = warpReduceSum(sum);
    float mu = sum * (1.f / 256.f);
    float var = 0.f;
#pragma unroll
    for (int k = 0; k < 2; k++) {
        float dx = v[k].x - mu, dy = v[k].y - mu, dz = v[k].z - mu, dw = v[k].w - mu;
        var += dx * dx + dy * dy + dz * dz + dw * dw;
    }
    var = warpReduceSum(var) * (1.f / 256.f);
    float inv = rsqrtf(var + 1e-5f);
    const float4* g4 = (const float4*)g;
    const float4* b4 = (const float4*)b;
    float4* o4 = (float4*)(out + (size_t)row * DIM);
#pragma unroll
    for (int k = 0; k < 2; k++) {
        int q = k * 32 + lane;
        float4 gg = g4[q], bb = b4[q];
        o4[q] = make_float4((v[k].x - mu) * inv * gg.x + bb.x,
                            (v[k].y - mu) * inv * gg.y + bb.y,
                            (v[k].z - mu) * inv * gg.z + bb.z,
                            (v[k].w - mu) * inv * gg.w + bb.w);
    }
}

// ---------------- host ----------------
#define DYN_SMEM (4 * CHUNK_FLOATS * sizeof(float))

static inline void launch_tgemm(const float* A, const float* WT, const float* bias, float* C,
                                int M, int N, int K) {
    dim3 grid((N + 127) / 128, (M + 127) / 128);
    mma_gemm<<<grid, 256, DYN_SMEM>>>(A, WT, bias, C, M, N, K);
}

extern "C" void kernel_launch(void* const* d_in, const int* in_sizes, int n_in,
                              void* d_out, int out_size) {
    cudaFuncSetAttribute(mma_gemm, cudaFuncAttributeMaxDynamicSharedMemorySize, DYN_SMEM);

    const float* x_gnn = (const float*)d_in[0];
    const int*   eidx  = (const int*)d_in[1];
    const float* eattr = (const float*)d_in[2];
    const float* W_in  = (const float*)d_in[3];
    const float* b_in  = (const float*)d_in[4];
    const float* Wl1   = (const float*)d_in[5];
    const float* Wr1   = (const float*)d_in[6];
    const float* We1   = (const float*)d_in[7];
    const float* att1  = (const float*)d_in[8];
    const float* bg1   = (const float*)d_in[9];
    const float* ln1_g = (const float*)d_in[10];
    const float* ln1_b = (const float*)d_in[11];
    const float* W_down= (const float*)d_in[12];
    const float* lnd_g = (const float*)d_in[13];
    const float* lnd_b = (const float*)d_in[14];
    const float* Wl2   = (const float*)d_in[15];
    const float* Wr2   = (const float*)d_in[16];
    const float* We2   = (const float*)d_in[17];
    const float* att2  = (const float*)d_in[18];
    const float* bg2   = (const float*)d_in[19];
    const float* ln2_g = (const float*)d_in[20];
    const float* ln2_b = (const float*)d_in[21];
    const float* W_up  = (const float*)d_in[22];
    const float* lnu_g = (const float*)d_in[23];
    const float* lnu_b = (const float*)d_in[24];
    const float* W_cls = (const float*)d_in[25];
    const float* b_cls = (const float*)d_in[26];

    const int n = in_sizes[0] / 18;        // 20000
    const int E = in_sizes[1] / 2;         // 320000
    const int* src = eidx;
    const int* dst = eidx + E;

    float *h0, *xlr, *agg, *h1, *z, *z2, *tmp, *wt, *eea;
    int *deg, *cur, *off, *esrc;
    cudaGetSymbolAddress((void**)&h0, g_h0);
    cudaGetSymbolAddress((void**)&xlr, g_xlr);
    cudaGetSymbolAddress((void**)&agg, g_agg);
    cudaGetSymbolAddress((void**)&h1, g_h1);
    cudaGetSymbolAddress((void**)&z, g_z);
    cudaGetSymbolAddress((void**)&z2, g_z2);
    cudaGetSymbolAddress((void**)&tmp, g_tmp);
    cudaGetSymbolAddress((void**)&wt, g_wt);
    cudaGetSymbolAddress((void**)&deg, g_deg);
    cudaGetSymbolAddress((void**)&cur, g_cur);
    cudaGetSymbolAddress((void**)&off, g_off);
    cudaGetSymbolAddress((void**)&esrc, g_esrc);
    cudaGetSymbolAddress((void**)&eea, g_eea);

    float* out_logits = (float*)d_out;
    float* out_h = (float*)d_out + (size_t)n * 1000;

    const int lnBlocks = (n + 7) / 8;
    const int gatherBlocks = (n + 7) / 8;   // warp per node, 8 warps/block

    // ---- CSR build (once; reused by both layers) ----
    zero_int2_kernel<<<(n + 255) / 256, 256>>>(deg, cur, n);
    hist_kernel<<<(E + 255) / 256, 256>>>(dst, deg, E);
    scan_kernel<<<1, 1024>>>(deg, off, n);
    scatter_kernel<<<(E + 255) / 256, 256>>>(src, dst, eattr, off, cur, esrc, eea, E);

    // ---- fused transpose of all 7 weights ----
    {
        TransDescs td;
        auto set = [&](int i, const float* in, float* out, int K, int N, int& cum) {
            td.d[i].in = in; td.d[i].out = out; td.d[i].K = K; td.d[i].N = N;
            td.d[i].blkStart = cum; td.d[i].nx = (N + 31) / 32;
            cum += td.d[i].nx * ((K + 31) / 32);
        };
        int cum = 0;
        set(0, Wl1,    wt + WT_L1, 32, DIM, cum);
        set(1, Wr1,    wt + WT_R1, 32, DIM, cum);
        set(2, W_down, wt + WT_DN, DIM, DIM, cum);
        set(3, Wl2,    wt + WT_L2, DIM, DIM, cum);
        set(4, Wr2,    wt + WT_R2, DIM, DIM, cum);
        set(5, W_up,   wt + WT_UP, DIM, DIM, cum);
        set(6, W_cls,  wt + WT_CLS, DIM, 1000, cum);
        td.total = cum;
        transpose_all_kernel<<<cum, dim3(32, 8)>>>(td);
    }

    // ---- input projection (K=18, fp32) ----
    {
        dim3 grid(1, (n + BM - 1) / BM);
        sgemm_kernel<<<grid, 256>>>(x_gnn, W_in, b_in, h0, n, 32, 18);
    }

    // ---- GAT layer 1 ----
    launch_tgemm(h0, wt + WT_L1, nullptr, xlr, n, 512, 32);
    gat_gather_kernel<<<gatherBlocks, 256>>>(xlr, off, esrc, eea, We1, att1, agg, n);
    ln_kernel<<<lnBlocks, 256>>>(agg, nullptr, bg1, ln1_g, ln1_b, h1, n);

    // ---- bottleneck down ----
    launch_tgemm(h1, wt + WT_DN, nullptr, tmp, n, DIM, DIM);
    ln_kernel<<<lnBlocks, 256>>>(tmp, nullptr, nullptr, lnd_g, lnd_b, z, n);

    // ---- GAT layer 2 ----
    launch_tgemm(z, wt + WT_L2, nullptr, xlr, n, 512, DIM);
    gat_gather_kernel<<<gatherBlocks, 256>>>(xlr, off, esrc, eea, We2, att2, agg, n);
    ln_kernel<<<lnBlocks, 256>>>(agg, z, bg2, ln2_g, ln2_b, z2, n);

    // ---- up projection + final LN ----
    launch_tgemm(z2, wt + WT_UP, nullptr, tmp, n, DIM, DIM);
    ln_kernel<<<lnBlocks, 256>>>(tmp, h1, nullptr, lnu_g, lnu_b, out_h, n);

    // ---- classifier ----
    launch_tgemm(out_h, wt + WT_CLS, b_cls, out_logits, n, 1000, DIM);
}

// round 8
// speedup vs baseline: 4.0612x; 1.5379x over previous
#include <cuda_runtime.h>
#include <cuda_fp16.h>
#include <math.h>
#include <stdint.h>

// ---------------- problem constants ----------------
#define NMAX 20000
#define EMAX 320000
#define DIM 256
#define HEADS 8

// ---------------- scratch ----------------
__device__ __align__(16) float g_xlr[NMAX * 512];       // [n,0:256]=xl, [n,256:512]=xr
__device__ __align__(16) float g_h1[NMAX * DIM];
__device__ __align__(16) float g_z[NMAX * DIM];
__device__ __align__(16) float g_tmp[NMAX * DIM];
// fp16 activation copies (GEMM A operands)
__device__ __align__(16) __half g_h0h[NMAX * 64];
__device__ __align__(16) __half g_h1h[NMAX * DIM];
__device__ __align__(16) __half g_zh[NMAX * DIM];
__device__ __align__(16) __half g_z2h[NMAX * DIM];
__device__ __align__(16) __half g_outh[NMAX * DIM];
// CSR by dst
__device__ int   g_deg[NMAX];
__device__ int   g_cur[NMAX];
__device__ int   g_off[NMAX + 1];
__device__ int   g_esrc[EMAX];
__device__ float g_eea[EMAX];
// fp16 transposed weights
#define WTH_L1  0                    // 512 x 64   (Wl1 rows 0-255, Wr1 rows 256-511, K padded 32->64)
#define WTH_DN  32768                // 256 x 256
#define WTH_L2  98304                // 512 x 256  (Wl2 + Wr2)
#define WTH_UP  229376               // 256 x 256
#define WTH_CLS 294912               // 1000 x 256
#define WTH_TOTAL (294912 + 256000)
__device__ __align__(16) __half g_wth[WTH_TOTAL];

// ---------------- helpers ----------------
__device__ __forceinline__ float warpReduceSum(float v) {
#pragma unroll
    for (int o = 16; o > 0; o >>= 1) v += __shfl_xor_sync(0xffffffffu, v, o);
    return v;
}

__device__ __forceinline__ float leaky(float v) { return v > 0.f ? v : 0.2f * v; }

__device__ __forceinline__ uint32_t smem_u32(const void* p) {
    uint32_t a;
    asm("{ .reg .u64 t; cvta.to.shared.u64 t, %1; cvt.u32.u64 %0, t; }" : "=r"(a) : "l"(p));
    return a;
}

__device__ __forceinline__ void cpasync16(uint32_t dst, const void* src, bool valid) {
    int sz = valid ? 16 : 0;
    asm volatile("cp.async.cg.shared.global [%0], [%1], 16, %2;"
                 :: "r"(dst), "l"(src), "r"(sz));
}
__device__ __forceinline__ void cpasync_commit() { asm volatile("cp.async.commit_group;"); }
__device__ __forceinline__ void cpasync_wait0() { asm volatile("cp.async.wait_group 0;"); }

// ---------------- CSR build ----------------
__global__ void zero_int2_kernel(int* __restrict__ a, int* __restrict__ b, int n) {
    int i = blockIdx.x * blockDim.x + threadIdx.x;
    if (i < n) { a[i] = 0; b[i] = 0; }
}

__global__ void hist_kernel(const int* __restrict__ dst, int* __restrict__ deg, int E) {
    int e = blockIdx.x * blockDim.x + threadIdx.x;
    if (e < E) atomicAdd(&deg[dst[e]], 1);
}

__global__ void scan_kernel(const int* __restrict__ deg, int* __restrict__ off, int n) {
    __shared__ int warp_sums[32];
    __shared__ int carry_s;
    int tid = threadIdx.x;                    // 1024 threads, single block
    if (tid == 0) carry_s = 0;
    __syncthreads();
    for (int base = 0; base < n; base += 1024) {
        int i = base + tid;
        int v = (i < n) ? deg[i] : 0;
        int x = v;
#pragma unroll
        for (int o = 1; o < 32; o <<= 1) {
            int y = __shfl_up_sync(0xffffffffu, x, o);
            if ((tid & 31) >= o) x += y;
        }
        if ((tid & 31) == 31) warp_sums[tid >> 5] = x;
        __syncthreads();
        if (tid < 32) {
            int s = warp_sums[tid];
#pragma unroll
            for (int o = 1; o < 32; o <<= 1) {
                int y = __shfl_up_sync(0xffffffffu, s, o);
                if (tid >= o) s += y;
            }
            warp_sums[tid] = s;
        }
        __syncthreads();
        int incl = x + ((tid >= 32) ? warp_sums[(tid >> 5) - 1] : 0);
        if (i < n) off[i] = carry_s + incl - v;
        __syncthreads();
        if (tid == 1023) carry_s += incl;
        __syncthreads();
    }
    if (tid == 0) off[n] = carry_s;
}

__global__ void scatter_kernel(const int* __restrict__ src, const int* __restrict__ dst,
                               const float* __restrict__ ea, const int* __restrict__ off,
                               int* __restrict__ cur, int* __restrict__ esrc,
                               float* __restrict__ eea, int E) {
    int e = blockIdx.x * blockDim.x + threadIdx.x;
    if (e >= E) return;
    int d = dst[e];
    int pos = off[d] + atomicAdd(&cur[d], 1);
    esrc[pos] = src[e];
    eea[pos] = ea[e];
}

// ---------------- fused transpose-all: in[Kreal,N] fp32 -> out[N,Kpad] fp16 ----------------
struct TransDesc { const float* in; __half* out; int Kreal, Kpad, N, blkStart, nx; };
struct TransDescs { TransDesc d[7]; int total; };

__global__ void transpose_all_kernel(TransDescs td) {
    __shared__ float t[32][33];
    int bid = blockIdx.x;
    int di = 0;
#pragma unroll
    for (int i = 1; i < 7; i++) if (bid >= td.d[i].blkStart) di = i;
    const TransDesc& D = td.d[di];
    int rem = bid - D.blkStart;
    int bx = (rem % D.nx) * 32, by = (rem / D.nx) * 32;   // bx: N dim, by: K dim
    int x = bx + threadIdx.x;        // n
    int y = by + threadIdx.y;        // k
#pragma unroll
    for (int i = 0; i < 32; i += 8)
        t[threadIdx.y + i][threadIdx.x] =
            (x < D.N && y + i < D.Kreal) ? D.in[(size_t)(y + i) * D.N + x] : 0.f;
    __syncthreads();
    x = by + threadIdx.x;            // k
    y = bx + threadIdx.y;            // n
#pragma unroll
    for (int i = 0; i < 32; i += 8)
        if (x < D.Kpad && y + i < D.N)
            D.out[(size_t)(y + i) * D.Kpad + x] = __float2half(t[threadIdx.x][threadIdx.y + i]);
}

// ---------------- fp16 mma.sync GEMM: C[M,N] = A[M,K] @ WT[N,K]^T (+bias), fp32 accum ----
// Block tile 128x128, K-chunk 64, 8 warps (2m x 4n), warp tile 64x32, m16n8k16.
#define SWW 36                    // smem row stride in 32-bit words (144B; conflict-free)
#define CHUNK_WORDS (128 * SWW)

extern __shared__ uint32_t g_dynsmem_u[];

__global__ __launch_bounds__(256)
void mma_gemm_h(const __half* __restrict__ A, const __half* __restrict__ WT,
                const float* __restrict__ bias, float* __restrict__ C,
                int M, int N, int K) {
    uint32_t* pA[2] = { g_dynsmem_u, g_dynsmem_u + 2 * CHUNK_WORDS };
    uint32_t* pB[2] = { g_dynsmem_u + CHUNK_WORDS, g_dynsmem_u + 3 * CHUNK_WORDS };

    const int tid = threadIdx.x;
    const int wid = tid >> 5, lane = tid & 31;
    const int gid = lane >> 2, tig = lane & 3;
    const int wm = (wid >> 2) * 64, wn = (wid & 3) * 32;
    const int m0 = blockIdx.y * 128, n0 = blockIdx.x * 128;

    float acc[4][4][4];
#pragma unroll
    for (int mi = 0; mi < 4; mi++)
#pragma unroll
        for (int ni = 0; ni < 4; ni++)
#pragma unroll
            for (int q = 0; q < 4; q++) acc[mi][ni][q] = 0.f;

    const int nc = (K + 63) >> 6;
    uint32_t aAddr[2] = { smem_u32(pA[0]), smem_u32(pA[1]) };
    uint32_t bAddr[2] = { smem_u32(pB[0]), smem_u32(pB[1]) };

    auto issue = [&](int c, int b) {
        int k0 = c << 6;
        int Kc = K - k0; if (Kc > 64) Kc = 64;
#pragma unroll
        for (int i = 0; i < 4; i++) {
            int idx = tid + i * 256;
            int row = idx >> 3, q = idx & 7;       // q: 16B segment within 128B row
            uint32_t soff = (uint32_t)(row * 144 + q * 16);
            bool kv = (q * 8) < Kc;
            cpasync16(aAddr[b] + soff, A + (size_t)(m0 + row) * K + k0 + q * 8,
                      kv && (m0 + row < M));
            cpasync16(bAddr[b] + soff, WT + (size_t)(n0 + row) * K + k0 + q * 8,
                      kv && (n0 + row < N));
        }
        cpasync_commit();
    };

    issue(0, 0);
    for (int c = 0; c < nc; c++) {
        int cur = c & 1;
        cpasync_wait0();
        __syncthreads();
        if (c + 1 < nc) issue(c + 1, cur ^ 1);
        const uint32_t* cA = pA[cur];
        const uint32_t* cB = pB[cur];
        int Kc = K - (c << 6); if (Kc > 64) Kc = 64;
#pragma unroll
        for (int ks = 0; ks < 4; ks++) {
            if (ks * 16 < Kc) {
                uint32_t af[4][4], bf[4][2];
#pragma unroll
                for (int mi = 0; mi < 4; mi++) {
                    const uint32_t* base = cA + (wm + mi * 16 + gid) * SWW + ks * 8 + tig;
                    af[mi][0] = base[0];
                    af[mi][1] = base[8 * SWW];
                    af[mi][2] = base[4];
                    af[mi][3] = base[8 * SWW + 4];
                }
#pragma unroll
                for (int ni = 0; ni < 4; ni++) {
                    const uint32_t* base = cB + (wn + ni * 8 + gid) * SWW + ks * 8 + tig;
                    bf[ni][0] = base[0];
                    bf[ni][1] = base[4];
                }
#pragma unroll
                for (int mi = 0; mi < 4; mi++)
#pragma unroll
                    for (int ni = 0; ni < 4; ni++) {
                        asm volatile(
                            "mma.sync.aligned.m16n8k16.row.col.f32.f16.f16.f32 "
                            "{%0,%1,%2,%3}, {%4,%5,%6,%7}, {%8,%9}, {%0,%1,%2,%3};"
                            : "+f"(acc[mi][ni][0]), "+f"(acc[mi][ni][1]),
                              "+f"(acc[mi][ni][2]), "+f"(acc[mi][ni][3])
                            : "r"(af[mi][0]), "r"(af[mi][1]), "r"(af[mi][2]), "r"(af[mi][3]),
                              "r"(bf[ni][0]), "r"(bf[ni][1]));
                    }
            }
        }
        __syncthreads();
    }

#pragma unroll
    for (int mi = 0; mi < 4; mi++) {
        int r0 = m0 + wm + mi * 16 + gid;
        int r1 = r0 + 8;
#pragma unroll
        for (int ni = 0; ni < 4; ni++) {
            int col = n0 + wn + ni * 8 + tig * 2;
            if (col >= N) continue;
            float bx = 0.f, by = 0.f;
            if (bias) { bx = bias[col]; by = bias[col + 1]; }
            if (r0 < M)
                *(float2*)(C + (size_t)r0 * N + col) =
                    make_float2(acc[mi][ni][0] + bx, acc[mi][ni][1] + by);
            if (r1 < M)
                *(float2*)(C + (size_t)r1 * N + col) =
                    make_float2(acc[mi][ni][2] + bx, acc[mi][ni][3] + by);
        }
    }
}

// ---------------- input projection (K=18, N=32, fp32 math, fp16 out padded to 64) ------
__global__ void inproj_kernel(const float* __restrict__ x, const float* __restrict__ W,
                              const float* __restrict__ b, __half* __restrict__ h0h, int n) {
    __shared__ float sW[18 * 32];
    __shared__ float sb[32];
    int tid = threadIdx.x;
    for (int i = tid; i < 18 * 32; i += 256) sW[i] = W[i];
    if (tid < 32) sb[tid] = b[tid];
    __syncthreads();
    int row = blockIdx.x * 8 + (tid >> 5);
    int col = tid & 31;
    if (row >= n) return;
    const float* xr = x + (size_t)row * 18;
    float v = sb[col];
#pragma unroll
    for (int k = 0; k < 18; k++) v += xr[k] * sW[k * 32 + col];
    h0h[(size_t)row * 64 + col] = __float2half(v);
    h0h[(size_t)row * 64 + 32 + col] = __float2half(0.f);
}

// ---------------- fused CSR gather GAT + LayerNorm: warp per dst node ----------------
__global__ void gatln_kernel(const float* __restrict__ xlr,
                             const int* __restrict__ off, const int* __restrict__ esrc,
                             const float* __restrict__ eea,
                             const float* __restrict__ We, const float* __restrict__ att,
                             const float* __restrict__ bias, const float* __restrict__ res,
                             const float* __restrict__ lng, const float* __restrict__ lnb,
                             float* __restrict__ out32, __half* __restrict__ out16, int n) {
    int d = (blockIdx.x * blockDim.x + threadIdx.x) >> 5;
    int lane = threadIdx.x & 31;
    if (d >= n) return;
    const float4* xrd = (const float4*)(xlr + (size_t)d * 512 + 256);
    float4 r0 = xrd[lane], r1 = xrd[32 + lane];
    float4 w0 = ((const float4*)We)[lane],  w1 = ((const float4*)We)[32 + lane];
    float4 t0 = ((const float4*)att)[lane], t1 = ((const float4*)att)[32 + lane];
    float4 acc0 = make_float4(0.f, 0.f, 0.f, 0.f), acc1 = acc0;
    float ss0 = 0.f, ss1 = 0.f;
    int beg = off[d], end = off[d + 1];
    for (int i = beg; i < end; i++) {
        int s = esrc[i];
        float a = eea[i];
        const float4* xls = (const float4*)(xlr + (size_t)s * 512);
        float4 l0 = xls[lane], l1 = xls[32 + lane];
        float p0 = leaky(l0.x + r0.x + a * w0.x) * t0.x + leaky(l0.y + r0.y + a * w0.y) * t0.y
                 + leaky(l0.z + r0.z + a * w0.z) * t0.z + leaky(l0.w + r0.w + a * w0.w) * t0.w;
        float p1 = leaky(l1.x + r1.x + a * w1.x) * t1.x + leaky(l1.y + r1.y + a * w1.y) * t1.y
                 + leaky(l1.z + r1.z + a * w1.z) * t1.z + leaky(l1.w + r1.w + a * w1.w) * t1.w;
        p0 += __shfl_xor_sync(0xffffffffu, p0, 1);
        p1 += __shfl_xor_sync(0xffffffffu, p1, 1);
        p0 += __shfl_xor_sync(0xffffffffu, p0, 2);
        p1 += __shfl_xor_sync(0xffffffffu, p1, 2);
        p0 += __shfl_xor_sync(0xffffffffu, p0, 4);
        p1 += __shfl_xor_sync(0xffffffffu, p1, 4);
        float e0 = __expf(p0), e1 = __expf(p1);
        acc0.x += e0 * l0.x; acc0.y += e0 * l0.y; acc0.z += e0 * l0.z; acc0.w += e0 * l0.w;
        acc1.x += e1 * l1.x; acc1.y += e1 * l1.y; acc1.z += e1 * l1.z; acc1.w += e1 * l1.w;
        ss0 += e0; ss1 += e1;
    }
    float i0 = 1.f / (ss0 + 1e-16f), i1 = 1.f / (ss1 + 1e-16f);
    float4 bb0 = ((const float4*)bias)[lane], bb1 = ((const float4*)bias)[32 + lane];
    float4 v0 = make_float4(acc0.x * i0 + bb0.x, acc0.y * i0 + bb0.y,
                            acc0.z * i0 + bb0.z, acc0.w * i0 + bb0.w);
    float4 v1 = make_float4(acc1.x * i1 + bb1.x, acc1.y * i1 + bb1.y,
                            acc1.z * i1 + bb1.z, acc1.w * i1 + bb1.w);
    if (res) {
        const float4* rr = (const float4*)(res + (size_t)d * DIM);
        float4 q0 = rr[lane], q1 = rr[32 + lane];
        v0.x += q0.x; v0.y += q0.y; v0.z += q0.z; v0.w += q0.w;
        v1.x += q1.x; v1.y += q1.y; v1.z += q1.z; v1.w += q1.w;
    }
    float sum = v0.x + v0.y + v0.z + v0.w + v1.x + v1.y + v1.z + v1.w;
    sum = warpReduceSum(sum);
    float mu = sum * (1.f / 256.f);
    float var = (v0.x - mu) * (v0.x - mu) + (v0.y - mu) * (v0.y - mu)
              + (v0.z - mu) * (v0.z - mu) + (v0.w - mu) * (v0.w - mu)
              + (v1.x - mu) * (v1.x - mu) + (v1.y - mu) * (v1.y - mu)
              + (v1.z - mu) * (v1.z - mu) + (v1.w - mu) * (v1.w - mu);
    var = warpReduceSum(var) * (1.f / 256.f);
    float inv = rsqrtf(var + 1e-5f);
    float4 g0 = ((const float4*)lng)[lane], g1 = ((const float4*)lng)[32 + lane];
    float4 c0 = ((const float4*)lnb)[lane], c1 = ((const float4*)lnb)[32 + lane];
    float4 o0 = make_float4((v0.x - mu) * inv * g0.x + c0.x, (v0.y - mu) * inv * g0.y + c0.y,
                            (v0.z - mu) * inv * g0.z + c0.z, (v0.w - mu) * inv * g0.w + c0.w);
    float4 o1 = make_float4((v1.x - mu) * inv * g1.x + c1.x, (v1.y - mu) * inv * g1.y + c1.y,
                            (v1.z - mu) * inv * g1.z + c1.z, (v1.w - mu) * inv * g1.w + c1.w);
    if (out32) {
        float4* o = (float4*)(out32 + (size_t)d * DIM);
        o[lane] = o0; o[32 + lane] = o1;
    }
    if (out16) {
        __half2* o = (__half2*)(out16 + (size_t)d * DIM);
        o[lane * 2]         = __floats2half2_rn(o0.x, o0.y);
        o[lane * 2 + 1]     = __floats2half2_rn(o0.z, o0.w);
        o[64 + lane * 2]    = __floats2half2_rn(o1.x, o1.y);
        o[64 + lane * 2 + 1] = __floats2half2_rn(o1.z, o1.w);
    }
}

// ---------------- layernorm (dim=256); optional residual; fp32 + fp16 outputs ----------
__global__ void ln_kernel(const float* __restrict__ x, const float* __restrict__ res,
                          const float* __restrict__ g, const float* __restrict__ b,
                          float* __restrict__ out32, __half* __restrict__ out16, int n) {
    int row = blockIdx.x * 8 + (threadIdx.x >> 5);
    int lane = threadIdx.x & 31;
    if (row >= n) return;
    const float4* xr4 = (const float4*)(x + (size_t)row * DIM);
    const float4* rs4 = res ? (const float4*)(res + (size_t)row * DIM) : nullptr;
    float4 v[2];
    float sum = 0.f;
#pragma unroll
    for (int k = 0; k < 2; k++) {
        int q = k * 32 + lane;
        float4 t = xr4[q];
        if (rs4) { float4 r = rs4[q]; t.x += r.x; t.y += r.y; t.z += r.z; t.w += r.w; }
        v[k] = t;
        sum += t.x + t.y + t.z + t.w;
    }
    sum = warpReduceSum(sum);
    float mu = sum * (1.f / 256.f);
    float var = 0.f;
#pragma unroll
    for (int k = 0; k < 2; k++) {
        float dx = v[k].x - mu, dy = v[k].y - mu, dz = v[k].z - mu, dw = v[k].w - mu;
        var += dx * dx + dy * dy + dz * dz + dw * dw;
    }
    var = warpReduceSum(var) * (1.f / 256.f);
    float inv = rsqrtf(var + 1e-5f);
    const float4* g4 = (const float4*)g;
    const float4* b4 = (const float4*)b;
#pragma unroll
    for (int k = 0; k < 2; k++) {
        int q = k * 32 + lane;
        float4 gg = g4[q], bb = b4[q];
        float4 o = make_float4((v[k].x - mu) * inv * gg.x + bb.x,
                               (v[k].y - mu) * inv * gg.y + bb.y,
                               (v[k].z - mu) * inv * gg.z + bb.z,
                               (v[k].w - mu) * inv * gg.w + bb.w);
        if (out32) ((float4*)(out32 + (size_t)row * DIM))[q] = o;
        if (out16) {
            __half2* o16 = (__half2*)(out16 + (size_t)row * DIM);
            o16[q * 2]     = __floats2half2_rn(o.x, o.y);
            o16[q * 2 + 1] = __floats2half2_rn(o.z, o.w);
        }
    }
}

// ---------------- host ----------------
#define DYN_SMEM (4 * CHUNK_WORDS * sizeof(uint32_t))   // 73728 bytes

static inline void launch_tgemm(const __half* A, const __half* WT, const float* bias, float* C,
                                int M, int N, int K) {
    dim3 grid((N + 127) / 128, (M + 127) / 128);
    mma_gemm_h<<<grid, 256, DYN_SMEM>>>(A, WT, bias, C, M, N, K);
}

extern "C" void kernel_launch(void* const* d_in, const int* in_sizes, int n_in,
                              void* d_out, int out_size) {
    cudaFuncSetAttribute(mma_gemm_h, cudaFuncAttributeMaxDynamicSharedMemorySize, DYN_SMEM);

    const float* x_gnn = (const float*)d_in[0];
    const int*   eidx  = (const int*)d_in[1];
    const float* eattr = (const float*)d_in[2];
    const float* W_in  = (const float*)d_in[3];
    const float* b_in  = (const float*)d_in[4];
    const float* Wl1   = (const float*)d_in[5];
    const float* Wr1   = (const float*)d_in[6];
    const float* We1   = (const float*)d_in[7];
    const float* att1  = (const float*)d_in[8];
    const float* bg1   = (const float*)d_in[9];
    const float* ln1_g = (const float*)d_in[10];
    const float* ln1_b = (const float*)d_in[11];
    const float* W_down= (const float*)d_in[12];
    const float* lnd_g = (const float*)d_in[13];
    const float* lnd_b = (const float*)d_in[14];
    const float* Wl2   = (const float*)d_in[15];
    const float* Wr2   = (const float*)d_in[16];
    const float* We2   = (const float*)d_in[17];
    const float* att2  = (const float*)d_in[18];
    const float* bg2   = (const float*)d_in[19];
    const float* ln2_g = (const float*)d_in[20];
    const float* ln2_b = (const float*)d_in[21];
    const float* W_up  = (const float*)d_in[22];
    const float* lnu_g = (const float*)d_in[23];
    const float* lnu_b = (const float*)d_in[24];
    const float* W_cls = (const float*)d_in[25];
    const float* b_cls = (const float*)d_in[26];

    const int n = in_sizes[0] / 18;        // 20000
    const int E = in_sizes[1] / 2;         // 320000
    const int* src = eidx;
    const int* dst = eidx + E;

    float *xlr, *h1, *z, *tmp, *eea;
    __half *h0h, *h1h, *zh, *z2h, *outh, *wth;
    int *deg, *cur, *off, *esrc;
    cudaGetSymbolAddress((void**)&xlr, g_xlr);
    cudaGetSymbolAddress((void**)&h1, g_h1);
    cudaGetSymbolAddress((void**)&z, g_z);
    cudaGetSymbolAddress((void**)&tmp, g_tmp);
    cudaGetSymbolAddress((void**)&eea, g_eea);
    cudaGetSymbolAddress((void**)&h0h, g_h0h);
    cudaGetSymbolAddress((void**)&h1h, g_h1h);
    cudaGetSymbolAddress((void**)&zh, g_zh);
    cudaGetSymbolAddress((void**)&z2h, g_z2h);
    cudaGetSymbolAddress((void**)&outh, g_outh);
    cudaGetSymbolAddress((void**)&wth, g_wth);
    cudaGetSymbolAddress((void**)&deg, g_deg);
    cudaGetSymbolAddress((void**)&cur, g_cur);
    cudaGetSymbolAddress((void**)&off, g_off);
    cudaGetSymbolAddress((void**)&esrc, g_esrc);

    float* out_logits = (float*)d_out;
    float* out_h = (float*)d_out + (size_t)n * 1000;

    const int lnBlocks = (n + 7) / 8;
    const int nodeBlocks = (n + 7) / 8;     // warp per node, 8 warps/block

    // ---- CSR build (once; reused by both layers) ----
    zero_int2_kernel<<<(n + 255) / 256, 256>>>(deg, cur, n);
    hist_kernel<<<(E + 255) / 256, 256>>>(dst, deg, E);
    scan_kernel<<<1, 1024>>>(deg, off, n);
    scatter_kernel<<<(E + 255) / 256, 256>>>(src, dst, eattr, off, cur, esrc, eea, E);

    // ---- fused transpose of all 7 weights -> fp16 ----
    {
        TransDescs td;
        auto set = [&](int i, const float* in, __half* out, int Kreal, int Kpad, int N, int& cum) {
            td.d[i].in = in; td.d[i].out = out;
            td.d[i].Kreal = Kreal; td.d[i].Kpad = Kpad; td.d[i].N = N;
            td.d[i].blkStart = cum; td.d[i].nx = (N + 31) / 32;
            cum += td.d[i].nx * ((Kpad + 31) / 32);
        };
        int cum = 0;
        set(0, Wl1,    wth + WTH_L1,            32, 64, DIM, cum);
        set(1, Wr1,    wth + WTH_L1 + 256 * 64, 32, 64, DIM, cum);
        set(2, W_down, wth + WTH_DN,  DIM, DIM, DIM, cum);
        set(3, Wl2,    wth + WTH_L2,  DIM, DIM, DIM, cum);
        set(4, Wr2,    wth + WTH_L2 + 256 * 256, DIM, DIM, DIM, cum);
        set(5, W_up,   wth + WTH_UP,  DIM, DIM, DIM, cum);
        set(6, W_cls,  wth + WTH_CLS, DIM, DIM, 1000, cum);
        td.total = cum;
        transpose_all_kernel<<<cum, dim3(32, 8)>>>(td);
    }

    // ---- input projection (fp32 math, fp16 out, K padded to 64) ----
    inproj_kernel<<<(n + 7) / 8, 256>>>(x_gnn, W_in, b_in, h0h, n);

    // ---- GAT layer 1 ----
    launch_tgemm(h0h, wth + WTH_L1, nullptr, xlr, n, 512, 64);
    gatln_kernel<<<nodeBlocks, 256>>>(xlr, off, esrc, eea, We1, att1, bg1,
                                      nullptr, ln1_g, ln1_b, h1, h1h, n);

    // ---- bottleneck down ----
    launch_tgemm(h1h, wth + WTH_DN, nullptr, tmp, n, DIM, DIM);
    ln_kernel<<<lnBlocks, 256>>>(tmp, nullptr, lnd_g, lnd_b, z, zh, n);

    // ---- GAT layer 2 (residual z inside fused gather-LN) ----
    launch_tgemm(zh, wth + WTH_L2, nullptr, xlr, n, 512, DIM);
    gatln_kernel<<<nodeBlocks, 256>>>(xlr, off, esrc, eea, We2, att2, bg2,
                                      z, ln2_g, ln2_b, nullptr, z2h, n);

    // ---- up projection + final LN ----
    launch_tgemm(z2h, wth + WTH_UP, nullptr, tmp, n, DIM, DIM);
    ln_kernel<<<lnBlocks, 256>>>(tmp, h1, lnu_g, lnu_b, out_h, outh, n);

    // ---- classifier ----
    launch_tgemm(outh, wth + WTH_CLS, b_cls, out_logits, n, 1000, DIM);
}

// round 9
// speedup vs baseline: 4.4797x; 1.1030x over previous
#include <cuda_runtime.h>
#include <cuda_fp16.h>
#include <math.h>
#include <stdint.h>

// ---------------- problem constants ----------------
#define NMAX 20000
#define EMAX 320000
#define DIM 256
#define HEADS 8

// ---------------- scratch ----------------
__device__ __align__(16) float g_xlr[NMAX * 512];       // [n,0:256]=xl, [n,256:512]=xr
__device__ __align__(16) float g_h1[NMAX * DIM];
__device__ __align__(16) float g_z[NMAX * DIM];
__device__ __align__(16) float g_tmp[NMAX * DIM];
// fp16 activation copies (GEMM A operands)
__device__ __align__(16) __half g_h0h[NMAX * 64];
__device__ __align__(16) __half g_h1h[NMAX * DIM];
__device__ __align__(16) __half g_zh[NMAX * DIM];
__device__ __align__(16) __half g_z2h[NMAX * DIM];
__device__ __align__(16) __half g_outh[NMAX * DIM];
// CSR by dst
__device__ int   g_deg[NMAX];
__device__ int   g_cur[NMAX];
__device__ int   g_off[NMAX + 1];
__device__ int2  g_epack[EMAX];            // .x = src, .y = float bits of edge_attr
// fp16 transposed weights
#define WTH_L1  0
#define WTH_DN  32768
#define WTH_L2  98304
#define WTH_UP  229376
#define WTH_CLS 294912
#define WTH_TOTAL (294912 + 256000)
__device__ __align__(16) __half g_wth[WTH_TOTAL];

// ---------------- helpers ----------------
__device__ __forceinline__ float warpReduceSum(float v) {
#pragma unroll
    for (int o = 16; o > 0; o >>= 1) v += __shfl_xor_sync(0xffffffffu, v, o);
    return v;
}

__device__ __forceinline__ float leaky(float v) { return v > 0.f ? v : 0.2f * v; }

__device__ __forceinline__ uint32_t smem_u32(const void* p) {
    uint32_t a;
    asm("{ .reg .u64 t; cvta.to.shared.u64 t, %1; cvt.u32.u64 %0, t; }" : "=r"(a) : "l"(p));
    return a;
}

__device__ __forceinline__ void cpasync16(uint32_t dst, const void* src, bool valid) {
    int sz = valid ? 16 : 0;   // src_size < cp_size => zero-fill
    asm volatile("cp.async.cg.shared.global [%0], [%1], 16, %2;"
                 :: "r"(dst), "l"(src), "r"(sz));
}
__device__ __forceinline__ void cpasync_commit() { asm volatile("cp.async.commit_group;"); }
__device__ __forceinline__ void cpasync_wait0() { asm volatile("cp.async.wait_group 0;"); }

#define LDMATRIX_X4(r0, r1, r2, r3, addr) \
    asm volatile("ldmatrix.sync.aligned.m8n8.x4.shared.b16 {%0,%1,%2,%3}, [%4];" \
                 : "=r"(r0), "=r"(r1), "=r"(r2), "=r"(r3) : "r"(addr))

// ---------------- CSR build ----------------
__global__ void zero_int2_kernel(int* __restrict__ a, int* __restrict__ b, int n) {
    int i = blockIdx.x * blockDim.x + threadIdx.x;
    if (i < n) { a[i] = 0; b[i] = 0; }
}

__global__ void hist_kernel(const int* __restrict__ dst, int* __restrict__ deg, int E) {
    int e = blockIdx.x * blockDim.x + threadIdx.x;
    if (e < E) atomicAdd(&deg[dst[e]], 1);
}

__global__ void scan_kernel(const int* __restrict__ deg, int* __restrict__ off, int n) {
    __shared__ int warp_sums[32];
    __shared__ int carry_s;
    int tid = threadIdx.x;                    // 1024 threads, single block
    if (tid == 0) carry_s = 0;
    __syncthreads();
    for (int base = 0; base < n; base += 1024) {
        int i = base + tid;
        int v = (i < n) ? deg[i] : 0;
        int x = v;
#pragma unroll
        for (int o = 1; o < 32; o <<= 1) {
            int y = __shfl_up_sync(0xffffffffu, x, o);
            if ((tid & 31) >= o) x += y;
        }
        if ((tid & 31) == 31) warp_sums[tid >> 5] = x;
        __syncthreads();
        if (tid < 32) {
            int s = warp_sums[tid];
#pragma unroll
            for (int o = 1; o < 32; o <<= 1) {
                int y = __shfl_up_sync(0xffffffffu, s, o);
                if (tid >= o) s += y;
            }
            warp_sums[tid] = s;
        }
        __syncthreads();
        int incl = x + ((tid >= 32) ? warp_sums[(tid >> 5) - 1] : 0);
        if (i < n) off[i] = carry_s + incl - v;
        __syncthreads();
        if (tid == 1023) carry_s += incl;
        __syncthreads();
    }
    if (tid == 0) off[n] = carry_s;
}

__global__ void scatter_kernel(const int* __restrict__ src, const int* __restrict__ dst,
                               const float* __restrict__ ea, const int* __restrict__ off,
                               int* __restrict__ cur, int2* __restrict__ epack, int E) {
    int e = blockIdx.x * blockDim.x + threadIdx.x;
    if (e >= E) return;
    int d = dst[e];
    int pos = off[d] + atomicAdd(&cur[d], 1);
    epack[pos] = make_int2(src[e], __float_as_int(ea[e]));
}

// ---------------- fused transpose-all: in[Kreal,N] fp32 -> out[N,Kpad] fp16 ----------------
struct TransDesc { const float* in; __half* out; int Kreal, Kpad, N, blkStart, nx; };
struct TransDescs { TransDesc d[7]; int total; };

__global__ void transpose_all_kernel(TransDescs td) {
    __shared__ float t[32][33];
    int bid = blockIdx.x;
    int di = 0;
#pragma unroll
    for (int i = 1; i < 7; i++) if (bid >= td.d[i].blkStart) di = i;
    const TransDesc& D = td.d[di];
    int rem = bid - D.blkStart;
    int bx = (rem % D.nx) * 32, by = (rem / D.nx) * 32;
    int x = bx + threadIdx.x;        // n
    int y = by + threadIdx.y;        // k
#pragma unroll
    for (int i = 0; i < 32; i += 8)
        t[threadIdx.y + i][threadIdx.x] =
            (x < D.N && y + i < D.Kreal) ? D.in[(size_t)(y + i) * D.N + x] : 0.f;
    __syncthreads();
    x = by + threadIdx.x;            // k
    y = bx + threadIdx.y;            // n
#pragma unroll
    for (int i = 0; i < 32; i += 8)
        if (x < D.Kpad && y + i < D.N)
            D.out[(size_t)(y + i) * D.Kpad + x] = __float2half(t[threadIdx.x][threadIdx.y + i]);
}

// ---------------- fp16 mma.sync GEMM: C[M,N] = A[M,K] @ WT[N,K]^T (+bias), fp32 accum ----
// Block tile 128x128, K-chunk 64 (128B/row), 8 warps (2m x 4n), warp tile 64x32, m16n8k16.
// Fragments loaded via ldmatrix.x4 (canonical layout).
#define SWW 36                    // smem row stride in 32-bit words (144B; conflict-free)
#define CHUNK_WORDS (128 * SWW)

extern __shared__ uint32_t g_dynsmem_u[];

__global__ __launch_bounds__(256)
void mma_gemm_h(const __half* __restrict__ A, const __half* __restrict__ WT,
                const float* __restrict__ bias, float* __restrict__ C,
                int M, int N, int K) {
    const int tid = threadIdx.x;
    const int wid = tid >> 5, lane = tid & 31;
    const int gid = lane >> 2, tig = lane & 3;
    const int wm = (wid >> 2) * 64, wn = (wid & 3) * 32;
    const int m0 = blockIdx.y * 128, n0 = blockIdx.x * 128;

    float acc[4][4][4];
#pragma unroll
    for (int mi = 0; mi < 4; mi++)
#pragma unroll
        for (int ni = 0; ni < 4; ni++)
#pragma unroll
            for (int q = 0; q < 4; q++) acc[mi][ni][q] = 0.f;

    const int nc = (K + 63) >> 6;
    uint32_t aAddr[2], bAddr[2];
    aAddr[0] = smem_u32(g_dynsmem_u);
    bAddr[0] = aAddr[0] + CHUNK_WORDS * 4;
    aAddr[1] = aAddr[0] + 2 * CHUNK_WORDS * 4;
    bAddr[1] = aAddr[0] + 3 * CHUNK_WORDS * 4;

    // ldmatrix per-thread address offsets (bytes)
    const uint32_t aOff = (uint32_t)((wm + (lane & 15)) * 144 + (lane >> 4) * 16);
    const uint32_t bOff = (uint32_t)((wn + (lane & 7) + ((lane >> 4) << 3)) * 144
                                     + ((lane >> 3) & 1) * 16);

    auto issue = [&](int c, int b) {
        int k0 = c << 6;
        int Kc = K - k0; if (Kc > 64) Kc = 64;
#pragma unroll
        for (int i = 0; i < 4; i++) {
            int idx = tid + i * 256;
            int row = idx >> 3, q = idx & 7;
            uint32_t soff = (uint32_t)(row * 144 + q * 16);
            bool kv = (q * 8) < Kc;
            cpasync16(aAddr[b] + soff, A + (size_t)(m0 + row) * K + k0 + q * 8,
                      kv && (m0 + row < M));
            cpasync16(bAddr[b] + soff, WT + (size_t)(n0 + row) * K + k0 + q * 8,
                      kv && (n0 + row < N));
        }
        cpasync_commit();
    };

    issue(0, 0);
    for (int c = 0; c < nc; c++) {
        int cur = c & 1;
        cpasync_wait0();
        __syncthreads();
        if (c + 1 < nc) issue(c + 1, cur ^ 1);
        uint32_t aB = aAddr[cur] + aOff;
        uint32_t bB = bAddr[cur] + bOff;
        int Kc = K - (c << 6); if (Kc > 64) Kc = 64;
#pragma unroll
        for (int ks = 0; ks < 4; ks++) {
            if (ks * 16 < Kc) {
                uint32_t af[4][4], bf[4][2];
#pragma unroll
                for (int mi = 0; mi < 4; mi++)
                    LDMATRIX_X4(af[mi][0], af[mi][1], af[mi][2], af[mi][3],
                                aB + mi * 16 * 144 + ks * 32);
#pragma unroll
                for (int np = 0; np < 2; np++)
                    LDMATRIX_X4(bf[2 * np][0], bf[2 * np][1], bf[2 * np + 1][0], bf[2 * np + 1][1],
                                bB + np * 16 * 144 + ks * 32);
#pragma unroll
                for (int mi = 0; mi < 4; mi++)
#pragma unroll
                    for (int ni = 0; ni < 4; ni++) {
                        asm volatile(
                            "mma.sync.aligned.m16n8k16.row.col.f32.f16.f16.f32 "
                            "{%0,%1,%2,%3}, {%4,%5,%6,%7}, {%8,%9}, {%0,%1,%2,%3};"
                            : "+f"(acc[mi][ni][0]), "+f"(acc[mi][ni][1]),
                              "+f"(acc[mi][ni][2]), "+f"(acc[mi][ni][3])
                            : "r"(af[mi][0]), "r"(af[mi][1]), "r"(af[mi][2]), "r"(af[mi][3]),
                              "r"(bf[ni][0]), "r"(bf[ni][1]));
                    }
            }
        }
        __syncthreads();
    }

#pragma unroll
    for (int mi = 0; mi < 4; mi++) {
        int r0 = m0 + wm + mi * 16 + gid;
        int r1 = r0 + 8;
#pragma unroll
        for (int ni = 0; ni < 4; ni++) {
            int col = n0 + wn + ni * 8 + tig * 2;
            if (col >= N) continue;
            float bx = 0.f, by = 0.f;
            if (bias) { bx = bias[col]; by = bias[col + 1]; }
            if (r0 < M)
                *(float2*)(C + (size_t)r0 * N + col) =
                    make_float2(acc[mi][ni][0] + bx, acc[mi][ni][1] + by);
            if (r1 < M)
                *(float2*)(C + (size_t)r1 * N + col) =
                    make_float2(acc[mi][ni][2] + bx, acc[mi][ni][3] + by);
        }
    }
}

// ---------------- input projection (K=18, N=32, fp32 math, fp16 out padded to 64) ------
__global__ void inproj_kernel(const float* __restrict__ x, const float* __restrict__ W,
                              const float* __restrict__ b, __half* __restrict__ h0h, int n) {
    __shared__ float sW[18 * 32];
    __shared__ float sb[32];
    int tid = threadIdx.x;
    for (int i = tid; i < 18 * 32; i += 256) sW[i] = W[i];
    if (tid < 32) sb[tid] = b[tid];
    __syncthreads();
    int row = blockIdx.x * 8 + (tid >> 5);
    int col = tid & 31;
    if (row >= n) return;
    const float* xr = x + (size_t)row * 18;
    float v = sb[col];
#pragma unroll
    for (int k = 0; k < 18; k++) v += xr[k] * sW[k * 32 + col];
    h0h[(size_t)row * 64 + col] = __float2half(v);
    h0h[(size_t)row * 64 + 32 + col] = __float2half(0.f);
}

// ---------------- fused CSR gather GAT + LayerNorm: warp per dst node ----------------
__global__ void gatln_kernel(const float* __restrict__ xlr,
                             const int* __restrict__ off, const int2* __restrict__ epack,
                             const float* __restrict__ We, const float* __restrict__ att,
                             const float* __restrict__ bias, const float* __restrict__ res,
                             const float* __restrict__ lng, const float* __restrict__ lnb,
                             float* __restrict__ out32, __half* __restrict__ out16, int n) {
    int d = (blockIdx.x * blockDim.x + threadIdx.x) >> 5;
    int lane = threadIdx.x & 31;
    if (d >= n) return;
    const float4* xrd = (const float4*)(xlr + (size_t)d * 512 + 256);
    float4 r0 = xrd[lane], r1 = xrd[32 + lane];
    float4 w0 = ((const float4*)We)[lane],  w1 = ((const float4*)We)[32 + lane];
    float4 t0 = ((const float4*)att)[lane], t1 = ((const float4*)att)[32 + lane];
    float4 acc0 = make_float4(0.f, 0.f, 0.f, 0.f), acc1 = acc0;
    float ss0 = 0.f, ss1 = 0.f;
    int beg = off[d], cnt = off[d + 1] - beg;
    const int2* ep = epack + beg;
    if (cnt > 0) {
        int2 pk = ep[0];
        const float4* xp = (const float4*)(xlr + (size_t)pk.x * 512);
        float4 l0 = xp[lane], l1 = xp[32 + lane];
        float aa = __int_as_float(pk.y);
        for (int i = 0; i < cnt; i++) {
            float4 cl0 = l0, cl1 = l1;
            float ca = aa;
            if (i + 1 < cnt) {                 // prefetch next edge's src row
                int2 pk2 = ep[i + 1];
                const float4* xp2 = (const float4*)(xlr + (size_t)pk2.x * 512);
                l0 = xp2[lane]; l1 = xp2[32 + lane];
                aa = __int_as_float(pk2.y);
            }
            float p0 = leaky(cl0.x + r0.x + ca * w0.x) * t0.x + leaky(cl0.y + r0.y + ca * w0.y) * t0.y
                     + leaky(cl0.z + r0.z + ca * w0.z) * t0.z + leaky(cl0.w + r0.w + ca * w0.w) * t0.w;
            float p1 = leaky(cl1.x + r1.x + ca * w1.x) * t1.x + leaky(cl1.y + r1.y + ca * w1.y) * t1.y
                     + leaky(cl1.z + r1.z + ca * w1.z) * t1.z + leaky(cl1.w + r1.w + ca * w1.w) * t1.w;
            p0 += __shfl_xor_sync(0xffffffffu, p0, 1);
            p1 += __shfl_xor_sync(0xffffffffu, p1, 1);
            p0 += __shfl_xor_sync(0xffffffffu, p0, 2);
            p1 += __shfl_xor_sync(0xffffffffu, p1, 2);
            p0 += __shfl_xor_sync(0xffffffffu, p0, 4);
            p1 += __shfl_xor_sync(0xffffffffu, p1, 4);
            float e0 = __expf(p0), e1 = __expf(p1);
            acc0.x += e0 * cl0.x; acc0.y += e0 * cl0.y; acc0.z += e0 * cl0.z; acc0.w += e0 * cl0.w;
            acc1.x += e1 * cl1.x; acc1.y += e1 * cl1.y; acc1.z += e1 * cl1.z; acc1.w += e1 * cl1.w;
            ss0 += e0; ss1 += e1;
        }
    }
    float i0 = 1.f / (ss0 + 1e-16f), i1 = 1.f / (ss1 + 1e-16f);
    float4 bb0 = ((const float4*)bias)[lane], bb1 = ((const float4*)bias)[32 + lane];
    float4 v0 = make_float4(acc0.x * i0 + bb0.x, acc0.y * i0 + bb0.y,
                            acc0.z * i0 + bb0.z, acc0.w * i0 + bb0.w);
    float4 v1 = make_float4(acc1.x * i1 + bb1.x, acc1.y * i1 + bb1.y,
                            acc1.z * i1 + bb1.z, acc1.w * i1 + bb1.w);
    if (res) {
        const float4* rr = (const float4*)(res + (size_t)d * DIM);
        float4 q0 = rr[lane], q1 = rr[32 + lane];
        v0.x += q0.x; v0.y += q0.y; v0.z += q0.z; v0.w += q0.w;
        v1.x += q1.x; v1.y += q1.y; v1.z += q1.z; v1.w += q1.w;
    }
    float sum = v0.x + v0.y + v0.z + v0.w + v1.x + v1.y + v1.z + v1.w;
    sum = warpReduceSum(sum);
    float mu = sum * (1.f / 256.f);
    float var = (v0.x - mu) * (v0.x - mu) + (v0.y - mu) * (v0.y - mu)
              + (v0.z - mu) * (v0.z - mu) + (v0.w - mu) * (v0.w - mu)
              + (v1.x - mu) * (v1.x - mu) + (v1.y - mu) * (v1.y - mu)
              + (v1.z - mu) * (v1.z - mu) + (v1.w - mu) * (v1.w - mu);
    var = warpReduceSum(var) * (1.f / 256.f);
    float inv = rsqrtf(var + 1e-5f);
    float4 g0 = ((const float4*)lng)[lane], g1 = ((const float4*)lng)[32 + lane];
    float4 c0 = ((const float4*)lnb)[lane], c1 = ((const float4*)lnb)[32 + lane];
    float4 o0 = make_float4((v0.x - mu) * inv * g0.x + c0.x, (v0.y - mu) * inv * g0.y + c0.y,
                            (v0.z - mu) * inv * g0.z + c0.z, (v0.w - mu) * inv * g0.w + c0.w);
    float4 o1 = make_float4((v1.x - mu) * inv * g1.x + c1.x, (v1.y - mu) * inv * g1.y + c1.y,
                            (v1.z - mu) * inv * g1.z + c1.z, (v1.w - mu) * inv * g1.w + c1.w);
    if (out32) {
        float4* o = (float4*)(out32 + (size_t)d * DIM);
        o[lane] = o0; o[32 + lane] = o1;
    }
    if (out16) {
        __half2* o = (__half2*)(out16 + (size_t)d * DIM);
        o[lane * 2]          = __floats2half2_rn(o0.x, o0.y);
        o[lane * 2 + 1]      = __floats2half2_rn(o0.z, o0.w);
        o[64 + lane * 2]     = __floats2half2_rn(o1.x, o1.y);
        o[64 + lane * 2 + 1] = __floats2half2_rn(o1.z, o1.w);
    }
}

// ---------------- layernorm (dim=256); optional residual; fp32 + fp16 outputs ----------
__global__ void ln_kernel(const float* __restrict__ x, const float* __restrict__ res,
                          const float* __restrict__ g, const float* __restrict__ b,
                          float* __restrict__ out32, __half* __restrict__ out16, int n) {
    int row = blockIdx.x * 8 + (threadIdx.x >> 5);
    int lane = threadIdx.x & 31;
    if (row >= n) return;
    const float4* xr4 = (const float4*)(x + (size_t)row * DIM);
    const float4* rs4 = res ? (const float4*)(res + (size_t)row * DIM) : nullptr;
    float4 v[2];
    float sum = 0.f;
#pragma unroll
    for (int k = 0; k < 2; k++) {
        int q = k * 32 + lane;
        float4 t = xr4[q];
        if (rs4) { float4 r = rs4[q]; t.x += r.x; t.y += r.y; t.z += r.z; t.w += r.w; }
        v[k] = t;
        sum += t.x + t.y + t.z + t.w;
    }
    sum = warpReduceSum(sum);
    float mu = sum * (1.f / 256.f);
    float var = 0.f;
#pragma unroll
    for (int k = 0; k < 2; k++) {
        float dx = v[k].x - mu, dy = v[k].y - mu, dz = v[k].z - mu, dw = v[k].w - mu;
        var += dx * dx + dy * dy + dz * dz + dw * dw;
    }
    var = warpReduceSum(var) * (1.f / 256.f);
    float inv = rsqrtf(var + 1e-5f);
    const float4* g4 = (const float4*)g;
    const float4* b4 = (const float4*)b;
#pragma unroll
    for (int k = 0; k < 2; k++) {
        int q = k * 32 + lane;
        float4 gg = g4[q], bb = b4[q];
        float4 o = make_float4((v[k].x - mu) * inv * gg.x + bb.x,
                               (v[k].y - mu) * inv * gg.y + bb.y,
                               (v[k].z - mu) * inv * gg.z + bb.z,
                               (v[k].w - mu) * inv * gg.w + bb.w);
        if (out32) ((float4*)(out32 + (size_t)row * DIM))[q] = o;
        if (out16) {
            __half2* o16 = (__half2*)(out16 + (size_t)row * DIM);
            o16[q * 2]     = __floats2half2_rn(o.x, o.y);
            o16[q * 2 + 1] = __floats2half2_rn(o.z, o.w);
        }
    }
}

// ---------------- host ----------------
#define DYN_SMEM (4 * CHUNK_WORDS * sizeof(uint32_t))   // 73728 bytes

static inline void launch_tgemm(const __half* A, const __half* WT, const float* bias, float* C,
                                int M, int N, int K) {
    dim3 grid((N + 127) / 128, (M + 127) / 128);
    mma_gemm_h<<<grid, 256, DYN_SMEM>>>(A, WT, bias, C, M, N, K);
}

extern "C" void kernel_launch(void* const* d_in, const int* in_sizes, int n_in,
                              void* d_out, int out_size) {
    cudaFuncSetAttribute(mma_gemm_h, cudaFuncAttributeMaxDynamicSharedMemorySize, DYN_SMEM);

    const float* x_gnn = (const float*)d_in[0];
    const int*   eidx  = (const int*)d_in[1];
    const float* eattr = (const float*)d_in[2];
    const float* W_in  = (const float*)d_in[3];
    const float* b_in  = (const float*)d_in[4];
    const float* Wl1   = (const float*)d_in[5];
    const float* Wr1   = (const float*)d_in[6];
    const float* We1   = (const float*)d_in[7];
    const float* att1  = (const float*)d_in[8];
    const float* bg1   = (const float*)d_in[9];
    const float* ln1_g = (const float*)d_in[10];
    const float* ln1_b = (const float*)d_in[11];
    const float* W_down= (const float*)d_in[12];
    const float* lnd_g = (const float*)d_in[13];
    const float* lnd_b = (const float*)d_in[14];
    const float* Wl2   = (const float*)d_in[15];
    const float* Wr2   = (const float*)d_in[16];
    const float* We2   = (const float*)d_in[17];
    const float* att2  = (const float*)d_in[18];
    const float* bg2   = (const float*)d_in[19];
    const float* ln2_g = (const float*)d_in[20];
    const float* ln2_b = (const float*)d_in[21];
    const float* W_up  = (const float*)d_in[22];
    const float* lnu_g = (const float*)d_in[23];
    const float* lnu_b = (const float*)d_in[24];
    const float* W_cls = (const float*)d_in[25];
    const float* b_cls = (const float*)d_in[26];

    const int n = in_sizes[0] / 18;        // 20000
    const int E = in_sizes[1] / 2;         // 320000
    const int* src = eidx;
    const int* dst = eidx + E;

    float *xlr, *h1, *z, *tmp;
    __half *h0h, *h1h, *zh, *z2h, *outh, *wth;
    int *deg, *cur, *off;
    int2 *epack;
    cudaGetSymbolAddress((void**)&xlr, g_xlr);
    cudaGetSymbolAddress((void**)&h1, g_h1);
    cudaGetSymbolAddress((void**)&z, g_z);
    cudaGetSymbolAddress((void**)&tmp, g_tmp);
    cudaGetSymbolAddress((void**)&h0h, g_h0h);
    cudaGetSymbolAddress((void**)&h1h, g_h1h);
    cudaGetSymbolAddress((void**)&zh, g_zh);
    cudaGetSymbolAddress((void**)&z2h, g_z2h);
    cudaGetSymbolAddress((void**)&outh, g_outh);
    cudaGetSymbolAddress((void**)&wth, g_wth);
    cudaGetSymbolAddress((void**)&deg, g_deg);
    cudaGetSymbolAddress((void**)&cur, g_cur);
    cudaGetSymbolAddress((void**)&off, g_off);
    cudaGetSymbolAddress((void**)&epack, g_epack);

    float* out_logits = (float*)d_out;
    float* out_h = (float*)d_out + (size_t)n * 1000;

    const int lnBlocks = (n + 7) / 8;
    const int nodeBlocks = (n + 7) / 8;     // warp per node, 8 warps/block

    // ---- CSR build (once; reused by both layers) ----
    zero_int2_kernel<<<(n + 255) / 256, 256>>>(deg, cur, n);
    hist_kernel<<<(E + 255) / 256, 256>>>(dst, deg, E);
    scan_kernel<<<1, 1024>>>(deg, off, n);
    scatter_kernel<<<(E + 255) / 256, 256>>>(src, dst, eattr, off, cur, epack, E);

    // ---- fused transpose of all 7 weights -> fp16 ----
    {
        TransDescs td;
        auto set = [&](int i, const float* in, __half* out, int Kreal, int Kpad, int N, int& cum) {
            td.d[i].in = in; td.d[i].out = out;
            td.d[i].Kreal = Kreal; td.d[i].Kpad = Kpad; td.d[i].N = N;
            td.d[i].blkStart = cum; td.d[i].nx = (N + 31) / 32;
            cum += td.d[i].nx * ((Kpad + 31) / 32);
        };
        int cum = 0;
        set(0, Wl1,    wth + WTH_L1,            32, 64, DIM, cum);
        set(1, Wr1,    wth + WTH_L1 + 256 * 64, 32, 64, DIM, cum);
        set(2, W_down, wth + WTH_DN,  DIM, DIM, DIM, cum);
        set(3, Wl2,    wth + WTH_L2,  DIM, DIM, DIM, cum);
        set(4, Wr2,    wth + WTH_L2 + 256 * 256, DIM, DIM, DIM, cum);
        set(5, W_up,   wth + WTH_UP,  DIM, DIM, DIM, cum);
        set(6, W_cls,  wth + WTH_CLS, DIM, DIM, 1000, cum);
        td.total = cum;
        transpose_all_kernel<<<cum, dim3(32, 8)>>>(td);
    }

    // ---- input projection (fp32 math, fp16 out, K padded to 64) ----
    inproj_kernel<<<(n + 7) / 8, 256>>>(x_gnn, W_in, b_in, h0h, n);

    // ---- GAT layer 1 ----
    launch_tgemm(h0h, wth + WTH_L1, nullptr, xlr, n, 512, 64);
    gatln_kernel<<<nodeBlocks, 256>>>(xlr, off, epack, We1, att1, bg1,
                                      nullptr, ln1_g, ln1_b, h1, h1h, n);

    // ---- bottleneck down ----
    launch_tgemm(h1h, wth + WTH_DN, nullptr, tmp, n, DIM, DIM);
    ln_kernel<<<lnBlocks, 256>>>(tmp, nullptr, lnd_g, lnd_b, z, zh, n);

    // ---- GAT layer 2 (residual z inside fused gather-LN) ----
    launch_tgemm(zh, wth + WTH_L2, nullptr, xlr, n, 512, DIM);
    gatln_kernel<<<nodeBlocks, 256>>>(xlr, off, epack, We2, att2, bg2,
                                      z, ln2_g, ln2_b, nullptr, z2h, n);

    // ---- up projection + final LN ----
    launch_tgemm(z2h, wth + WTH_UP, nullptr, tmp, n, DIM, DIM);
    ln_kernel<<<lnBlocks, 256>>>(tmp, h1, lnu_g, lnu_b, out_h, outh, n);

    // ---- classifier ----
    launch_tgemm(outh, wth + WTH_CLS, b_cls, out_logits, n, 1000, DIM);
}

// round 10
// speedup vs baseline: 4.8733x; 1.0879x over previous
#include <cuda_runtime.h>
#include <cuda_fp16.h>
#include <math.h>
#include <stdint.h>

// ---------------- problem constants ----------------
#define NMAX 20000
#define EMAX 320000
#define DIM 256
#define HEADS 8

// ---------------- scratch ----------------
__device__ __align__(16) __half g_xlr[NMAX * 512];      // fp16: [n,0:256]=xl, [n,256:512]=xr
__device__ __align__(16) float g_h1[NMAX * DIM];
__device__ __align__(16) float g_z[NMAX * DIM];
__device__ __align__(16) float g_tmp[NMAX * DIM];
// fp16 activation copies (GEMM A operands)
__device__ __align__(16) __half g_h0h[NMAX * 64];
__device__ __align__(16) __half g_h1h[NMAX * DIM];
__device__ __align__(16) __half g_zh[NMAX * DIM];
__device__ __align__(16) __half g_z2h[NMAX * DIM];
__device__ __align__(16) __half g_outh[NMAX * DIM];
// CSR by dst
__device__ int   g_deg[NMAX];
__device__ int   g_cur[NMAX];
__device__ int   g_off[NMAX + 1];
__device__ int2  g_epack[EMAX];            // .x = src, .y = float bits of edge_attr
// fp16 transposed weights
#define WTH_L1  0
#define WTH_DN  32768
#define WTH_L2  98304
#define WTH_UP  229376
#define WTH_CLS 294912
#define WTH_TOTAL (294912 + 256000)
__device__ __align__(16) __half g_wth[WTH_TOTAL];

// ---------------- helpers ----------------
__device__ __forceinline__ float warpReduceSum(float v) {
#pragma unroll
    for (int o = 16; o > 0; o >>= 1) v += __shfl_xor_sync(0xffffffffu, v, o);
    return v;
}

__device__ __forceinline__ float leaky(float v) { return v > 0.f ? v : 0.2f * v; }

__device__ __forceinline__ uint32_t smem_u32(const void* p) {
    uint32_t a;
    asm("{ .reg .u64 t; cvta.to.shared.u64 t, %1; cvt.u32.u64 %0, t; }" : "=r"(a) : "l"(p));
    return a;
}

__device__ __forceinline__ void cpasync16(uint32_t dst, const void* src, bool valid) {
    int sz = valid ? 16 : 0;
    asm volatile("cp.async.cg.shared.global [%0], [%1], 16, %2;"
                 :: "r"(dst), "l"(src), "r"(sz));
}
__device__ __forceinline__ void cpasync_commit() { asm volatile("cp.async.commit_group;"); }
__device__ __forceinline__ void cpasync_wait0() { asm volatile("cp.async.wait_group 0;"); }

#define LDMATRIX_X4(r0, r1, r2, r3, addr) \
    asm volatile("ldmatrix.sync.aligned.m8n8.x4.shared.b16 {%0,%1,%2,%3}, [%4];" \
                 : "=r"(r0), "=r"(r1), "=r"(r2), "=r"(r3) : "r"(addr))

// ---------------- CSR build ----------------
__global__ void zero_int2_kernel(int* __restrict__ a, int* __restrict__ b, int n) {
    int i = blockIdx.x * blockDim.x + threadIdx.x;
    if (i < n) { a[i] = 0; b[i] = 0; }
}

__global__ void hist_kernel(const int* __restrict__ dst, int* __restrict__ deg, int E) {
    int e = blockIdx.x * blockDim.x + threadIdx.x;
    if (e < E) atomicAdd(&deg[dst[e]], 1);
}

__global__ void scan_kernel(const int* __restrict__ deg, int* __restrict__ off, int n) {
    __shared__ int warp_sums[32];
    __shared__ int carry_s;
    int tid = threadIdx.x;                    // 1024 threads, single block
    if (tid == 0) carry_s = 0;
    __syncthreads();
    for (int base = 0; base < n; base += 1024) {
        int i = base + tid;
        int v = (i < n) ? deg[i] : 0;
        int x = v;
#pragma unroll
        for (int o = 1; o < 32; o <<= 1) {
            int y = __shfl_up_sync(0xffffffffu, x, o);
            if ((tid & 31) >= o) x += y;
        }
        if ((tid & 31) == 31) warp_sums[tid >> 5] = x;
        __syncthreads();
        if (tid < 32) {
            int s = warp_sums[tid];
#pragma unroll
            for (int o = 1; o < 32; o <<= 1) {
                int y = __shfl_up_sync(0xffffffffu, s, o);
                if (tid >= o) s += y;
            }
            warp_sums[tid] = s;
        }
        __syncthreads();
        int incl = x + ((tid >= 32) ? warp_sums[(tid >> 5) - 1] : 0);
        if (i < n) off[i] = carry_s + incl - v;
        __syncthreads();
        if (tid == 1023) carry_s += incl;
        __syncthreads();
    }
    if (tid == 0) off[n] = carry_s;
}

__global__ void scatter_kernel(const int* __restrict__ src, const int* __restrict__ dst,
                               const float* __restrict__ ea, const int* __restrict__ off,
                               int* __restrict__ cur, int2* __restrict__ epack, int E) {
    int e = blockIdx.x * blockDim.x + threadIdx.x;
    if (e >= E) return;
    int d = dst[e];
    int pos = off[d] + atomicAdd(&cur[d], 1);
    epack[pos] = make_int2(src[e], __float_as_int(ea[e]));
}

// ---------------- fused transpose-all: in[Kreal,N] fp32 -> out[N,Kpad] fp16 ----------------
struct TransDesc { const float* in; __half* out; int Kreal, Kpad, N, blkStart, nx; };
struct TransDescs { TransDesc d[7]; int total; };

__global__ void transpose_all_kernel(TransDescs td) {
    __shared__ float t[32][33];
    int bid = blockIdx.x;
    int di = 0;
#pragma unroll
    for (int i = 1; i < 7; i++) if (bid >= td.d[i].blkStart) di = i;
    const TransDesc& D = td.d[di];
    int rem = bid - D.blkStart;
    int bx = (rem % D.nx) * 32, by = (rem / D.nx) * 32;
    int x = bx + threadIdx.x;        // n
    int y = by + threadIdx.y;        // k
#pragma unroll
    for (int i = 0; i < 32; i += 8)
        t[threadIdx.y + i][threadIdx.x] =
            (x < D.N && y + i < D.Kreal) ? D.in[(size_t)(y + i) * D.N + x] : 0.f;
    __syncthreads();
    x = by + threadIdx.x;            // k
    y = bx + threadIdx.y;            // n
#pragma unroll
    for (int i = 0; i < 32; i += 8)
        if (x < D.Kpad && y + i < D.N)
            D.out[(size_t)(y + i) * D.Kpad + x] = __float2half(t[threadIdx.x][threadIdx.y + i]);
}

// ---------------- fp16 mma.sync GEMM: out = A[M,K] @ WT[N,K]^T (+bias), fp32 accum ------
// Output either fp32 (C32) or fp16 (C16) — exactly one non-null.
#define SWW 36
#define CHUNK_WORDS (128 * SWW)

extern __shared__ uint32_t g_dynsmem_u[];

__global__ __launch_bounds__(256)
void mma_gemm_h(const __half* __restrict__ A, const __half* __restrict__ WT,
                const float* __restrict__ bias, float* __restrict__ C32,
                __half* __restrict__ C16, int M, int N, int K) {
    const int tid = threadIdx.x;
    const int wid = tid >> 5, lane = tid & 31;
    const int gid = lane >> 2, tig = lane & 3;
    const int wm = (wid >> 2) * 64, wn = (wid & 3) * 32;
    const int m0 = blockIdx.y * 128, n0 = blockIdx.x * 128;

    float acc[4][4][4];
#pragma unroll
    for (int mi = 0; mi < 4; mi++)
#pragma unroll
        for (int ni = 0; ni < 4; ni++)
#pragma unroll
            for (int q = 0; q < 4; q++) acc[mi][ni][q] = 0.f;

    const int nc = (K + 63) >> 6;
    uint32_t aAddr[2], bAddr[2];
    aAddr[0] = smem_u32(g_dynsmem_u);
    bAddr[0] = aAddr[0] + CHUNK_WORDS * 4;
    aAddr[1] = aAddr[0] + 2 * CHUNK_WORDS * 4;
    bAddr[1] = aAddr[0] + 3 * CHUNK_WORDS * 4;

    const uint32_t aOff = (uint32_t)((wm + (lane & 15)) * 144 + (lane >> 4) * 16);
    const uint32_t bOff = (uint32_t)((wn + (lane & 7) + ((lane >> 4) << 3)) * 144
                                     + ((lane >> 3) & 1) * 16);

    auto issue = [&](int c, int b) {
        int k0 = c << 6;
        int Kc = K - k0; if (Kc > 64) Kc = 64;
#pragma unroll
        for (int i = 0; i < 4; i++) {
            int idx = tid + i * 256;
            int row = idx >> 3, q = idx & 7;
            uint32_t soff = (uint32_t)(row * 144 + q * 16);
            bool kv = (q * 8) < Kc;
            cpasync16(aAddr[b] + soff, A + (size_t)(m0 + row) * K + k0 + q * 8,
                      kv && (m0 + row < M));
            cpasync16(bAddr[b] + soff, WT + (size_t)(n0 + row) * K + k0 + q * 8,
                      kv && (n0 + row < N));
        }
        cpasync_commit();
    };

    issue(0, 0);
    for (int c = 0; c < nc; c++) {
        int cur = c & 1;
        cpasync_wait0();
        __syncthreads();
        if (c + 1 < nc) issue(c + 1, cur ^ 1);
        uint32_t aB = aAddr[cur] + aOff;
        uint32_t bB = bAddr[cur] + bOff;
        int Kc = K - (c << 6); if (Kc > 64) Kc = 64;
#pragma unroll
        for (int ks = 0; ks < 4; ks++) {
            if (ks * 16 < Kc) {
                uint32_t af[4][4], bf[4][2];
#pragma unroll
                for (int mi = 0; mi < 4; mi++)
                    LDMATRIX_X4(af[mi][0], af[mi][1], af[mi][2], af[mi][3],
                                aB + mi * 16 * 144 + ks * 32);
#pragma unroll
                for (int np = 0; np < 2; np++)
                    LDMATRIX_X4(bf[2 * np][0], bf[2 * np][1], bf[2 * np + 1][0], bf[2 * np + 1][1],
                                bB + np * 16 * 144 + ks * 32);
#pragma unroll
                for (int mi = 0; mi < 4; mi++)
#pragma unroll
                    for (int ni = 0; ni < 4; ni++) {
                        asm volatile(
                            "mma.sync.aligned.m16n8k16.row.col.f32.f16.f16.f32 "
                            "{%0,%1,%2,%3}, {%4,%5,%6,%7}, {%8,%9}, {%0,%1,%2,%3};"
                            : "+f"(acc[mi][ni][0]), "+f"(acc[mi][ni][1]),
                              "+f"(acc[mi][ni][2]), "+f"(acc[mi][ni][3])
                            : "r"(af[mi][0]), "r"(af[mi][1]), "r"(af[mi][2]), "r"(af[mi][3]),
                              "r"(bf[ni][0]), "r"(bf[ni][1]));
                    }
            }
        }
        __syncthreads();
    }

#pragma unroll
    for (int mi = 0; mi < 4; mi++) {
        int r0 = m0 + wm + mi * 16 + gid;
        int r1 = r0 + 8;
#pragma unroll
        for (int ni = 0; ni < 4; ni++) {
            int col = n0 + wn + ni * 8 + tig * 2;
            if (col >= N) continue;
            if (C16) {
                if (r0 < M)
                    *(__half2*)(C16 + (size_t)r0 * N + col) =
                        __floats2half2_rn(acc[mi][ni][0], acc[mi][ni][1]);
                if (r1 < M)
                    *(__half2*)(C16 + (size_t)r1 * N + col) =
                        __floats2half2_rn(acc[mi][ni][2], acc[mi][ni][3]);
            } else {
                float bx = 0.f, by = 0.f;
                if (bias) { bx = bias[col]; by = bias[col + 1]; }
                if (r0 < M)
                    *(float2*)(C32 + (size_t)r0 * N + col) =
                        make_float2(acc[mi][ni][0] + bx, acc[mi][ni][1] + by);
                if (r1 < M)
                    *(float2*)(C32 + (size_t)r1 * N + col) =
                        make_float2(acc[mi][ni][2] + bx, acc[mi][ni][3] + by);
            }
        }
    }
}

// ---------------- input projection (K=18, N=32, fp32 math, fp16 out padded to 64) ------
__global__ void inproj_kernel(const float* __restrict__ x, const float* __restrict__ W,
                              const float* __restrict__ b, __half* __restrict__ h0h, int n) {
    __shared__ float sW[18 * 32];
    __shared__ float sb[32];
    int tid = threadIdx.x;
    for (int i = tid; i < 18 * 32; i += 256) sW[i] = W[i];
    if (tid < 32) sb[tid] = b[tid];
    __syncthreads();
    int row = blockIdx.x * 8 + (tid >> 5);
    int col = tid & 31;
    if (row >= n) return;
    const float* xr = x + (size_t)row * 18;
    float v = sb[col];
#pragma unroll
    for (int k = 0; k < 18; k++) v += xr[k] * sW[k * 32 + col];
    h0h[(size_t)row * 64 + col] = __float2half(v);
    h0h[(size_t)row * 64 + 32 + col] = __float2half(0.f);
}

// ---------------- fused CSR gather GAT + LayerNorm (fp16 xlr): warp per dst node --------
// lane holds 8 contiguous dims [8*lane .. 8*lane+7]; head = lane>>2 (4 lanes/head).
__global__ void gatln_kernel(const __half* __restrict__ xlr,
                             const int* __restrict__ off, const int2* __restrict__ epack,
                             const float* __restrict__ We, const float* __restrict__ att,
                             const float* __restrict__ bias, const float* __restrict__ res,
                             const float* __restrict__ lng, const float* __restrict__ lnb,
                             float* __restrict__ out32, __half* __restrict__ out16, int n) {
    int d = (blockIdx.x * blockDim.x + threadIdx.x) >> 5;
    int lane = threadIdx.x & 31;
    if (d >= n) return;
    float r[8], w[8], t[8];
    {
        uint4 rv = ((const uint4*)(xlr + (size_t)d * 512 + 256))[lane];
        const __half2* hp = (const __half2*)&rv;
#pragma unroll
        for (int k = 0; k < 4; k++) {
            float2 f = __half22float2(hp[k]);
            r[2 * k] = f.x; r[2 * k + 1] = f.y;
        }
        float4 wa = ((const float4*)We)[2 * lane], wb = ((const float4*)We)[2 * lane + 1];
        w[0] = wa.x; w[1] = wa.y; w[2] = wa.z; w[3] = wa.w;
        w[4] = wb.x; w[5] = wb.y; w[6] = wb.z; w[7] = wb.w;
        float4 ta = ((const float4*)att)[2 * lane], tb = ((const float4*)att)[2 * lane + 1];
        t[0] = ta.x; t[1] = ta.y; t[2] = ta.z; t[3] = ta.w;
        t[4] = tb.x; t[5] = tb.y; t[6] = tb.z; t[7] = tb.w;
    }
    float acc[8];
#pragma unroll
    for (int k = 0; k < 8; k++) acc[k] = 0.f;
    float ss = 0.f;
    int beg = off[d], cnt = off[d + 1] - beg;
    const int2* ep = epack + beg;
    if (cnt > 0) {
        int2 pk = ep[0];
        uint4 lv = ((const uint4*)(xlr + (size_t)pk.x * 512))[lane];
        float aa = __int_as_float(pk.y);
        for (int i = 0; i < cnt; i++) {
            uint4 cv = lv;
            float ca = aa;
            if (i + 1 < cnt) {                 // prefetch next edge's src row
                int2 p2 = ep[i + 1];
                lv = ((const uint4*)(xlr + (size_t)p2.x * 512))[lane];
                aa = __int_as_float(p2.y);
            }
            float l[8];
            const __half2* hp = (const __half2*)&cv;
#pragma unroll
            for (int k = 0; k < 4; k++) {
                float2 f = __half22float2(hp[k]);
                l[2 * k] = f.x; l[2 * k + 1] = f.y;
            }
            float p = 0.f;
#pragma unroll
            for (int k = 0; k < 8; k++) p += leaky(l[k] + r[k] + ca * w[k]) * t[k];
            p += __shfl_xor_sync(0xffffffffu, p, 1);
            p += __shfl_xor_sync(0xffffffffu, p, 2);
            float e = __expf(p);
#pragma unroll
            for (int k = 0; k < 8; k++) acc[k] += e * l[k];
            ss += e;
        }
    }
    float iv = 1.f / (ss + 1e-16f);
    float v[8];
    {
        float4 ba = ((const float4*)bias)[2 * lane], bb = ((const float4*)bias)[2 * lane + 1];
        v[0] = acc[0] * iv + ba.x; v[1] = acc[1] * iv + ba.y;
        v[2] = acc[2] * iv + ba.z; v[3] = acc[3] * iv + ba.w;
        v[4] = acc[4] * iv + bb.x; v[5] = acc[5] * iv + bb.y;
        v[6] = acc[6] * iv + bb.z; v[7] = acc[7] * iv + bb.w;
    }
    if (res) {
        float4 ra = ((const float4*)(res + (size_t)d * DIM))[2 * lane];
        float4 rb = ((const float4*)(res + (size_t)d * DIM))[2 * lane + 1];
        v[0] += ra.x; v[1] += ra.y; v[2] += ra.z; v[3] += ra.w;
        v[4] += rb.x; v[5] += rb.y; v[6] += rb.z; v[7] += rb.w;
    }
    float sum = 0.f;
#pragma unroll
    for (int k = 0; k < 8; k++) sum += v[k];
    sum = warpReduceSum(sum);
    float mu = sum * (1.f / 256.f);
    float var = 0.f;
#pragma unroll
    for (int k = 0; k < 8; k++) { float dd = v[k] - mu; var += dd * dd; }
    var = warpReduceSum(var) * (1.f / 256.f);
    float inv = rsqrtf(var + 1e-5f);
    float4 ga = ((const float4*)lng)[2 * lane], gb = ((const float4*)lng)[2 * lane + 1];
    float4 ca4 = ((const float4*)lnb)[2 * lane], cb4 = ((const float4*)lnb)[2 * lane + 1];
    float o[8];
    o[0] = (v[0] - mu) * inv * ga.x + ca4.x; o[1] = (v[1] - mu) * inv * ga.y + ca4.y;
    o[2] = (v[2] - mu) * inv * ga.z + ca4.z; o[3] = (v[3] - mu) * inv * ga.w + ca4.w;
    o[4] = (v[4] - mu) * inv * gb.x + cb4.x; o[5] = (v[5] - mu) * inv * gb.y + cb4.y;
    o[6] = (v[6] - mu) * inv * gb.z + cb4.z; o[7] = (v[7] - mu) * inv * gb.w + cb4.w;
    if (out32) {
        float4* op = (float4*)(out32 + (size_t)d * DIM);
        op[2 * lane]     = make_float4(o[0], o[1], o[2], o[3]);
        op[2 * lane + 1] = make_float4(o[4], o[5], o[6], o[7]);
    }
    if (out16) {
        uint4 pk16;
        __half2 h0 = __floats2half2_rn(o[0], o[1]), h1 = __floats2half2_rn(o[2], o[3]);
        __half2 h2 = __floats2half2_rn(o[4], o[5]), h3 = __floats2half2_rn(o[6], o[7]);
        pk16.x = *(uint32_t*)&h0; pk16.y = *(uint32_t*)&h1;
        pk16.z = *(uint32_t*)&h2; pk16.w = *(uint32_t*)&h3;
        ((uint4*)(out16 + (size_t)d * DIM))[lane] = pk16;
    }
}

// ---------------- layernorm (dim=256); optional residual; fp32 + fp16 outputs ----------
__global__ void ln_kernel(const float* __restrict__ x, const float* __restrict__ res,
                          const float* __restrict__ g, const float* __restrict__ b,
                          float* __restrict__ out32, __half* __restrict__ out16, int n) {
    int row = blockIdx.x * 8 + (threadIdx.x >> 5);
    int lane = threadIdx.x & 31;
    if (row >= n) return;
    const float4* xr4 = (const float4*)(x + (size_t)row * DIM);
    const float4* rs4 = res ? (const float4*)(res + (size_t)row * DIM) : nullptr;
    float4 v[2];
    float sum = 0.f;
#pragma unroll
    for (int k = 0; k < 2; k++) {
        int q = k * 32 + lane;
        float4 t = xr4[q];
        if (rs4) { float4 r = rs4[q]; t.x += r.x; t.y += r.y; t.z += r.z; t.w += r.w; }
        v[k] = t;
        sum += t.x + t.y + t.z + t.w;
    }
    sum = warpReduceSum(sum);
    float mu = sum * (1.f / 256.f);
    float var = 0.f;
#pragma unroll
    for (int k = 0; k < 2; k++) {
        float dx = v[k].x - mu, dy = v[k].y - mu, dz = v[k].z - mu, dw = v[k].w - mu;
        var += dx * dx + dy * dy + dz * dz + dw * dw;
    }
    var = warpReduceSum(var) * (1.f / 256.f);
    float inv = rsqrtf(var + 1e-5f);
    const float4* g4 = (const float4*)g;
    const float4* b4 = (const float4*)b;
#pragma unroll
    for (int k = 0; k < 2; k++) {
        int q = k * 32 + lane;
        float4 gg = g4[q], bb = b4[q];
        float4 o = make_float4((v[k].x - mu) * inv * gg.x + bb.x,
                               (v[k].y - mu) * inv * gg.y + bb.y,
                               (v[k].z - mu) * inv * gg.z + bb.z,
                               (v[k].w - mu) * inv * gg.w + bb.w);
        if (out32) ((float4*)(out32 + (size_t)row * DIM))[q] = o;
        if (out16) {
            __half2* o16 = (__half2*)(out16 + (size_t)row * DIM);
            o16[q * 2]     = __floats2half2_rn(o.x, o.y);
            o16[q * 2 + 1] = __floats2half2_rn(o.z, o.w);
        }
    }
}

// ---------------- host ----------------
#define DYN_SMEM (4 * CHUNK_WORDS * sizeof(uint32_t))   // 73728 bytes

static inline void launch_tgemm32(const __half* A, const __half* WT, const float* bias,
                                  float* C, int M, int N, int K) {
    dim3 grid((N + 127) / 128, (M + 127) / 128);
    mma_gemm_h<<<grid, 256, DYN_SMEM>>>(A, WT, bias, C, nullptr, M, N, K);
}
static inline void launch_tgemm16(const __half* A, const __half* WT, __half* C,
                                  int M, int N, int K) {
    dim3 grid((N + 127) / 128, (M + 127) / 128);
    mma_gemm_h<<<grid, 256, DYN_SMEM>>>(A, WT, nullptr, nullptr, C, M, N, K);
}

extern "C" void kernel_launch(void* const* d_in, const int* in_sizes, int n_in,
                              void* d_out, int out_size) {
    cudaFuncSetAttribute(mma_gemm_h, cudaFuncAttributeMaxDynamicSharedMemorySize, DYN_SMEM);

    const float* x_gnn = (const float*)d_in[0];
    const int*   eidx  = (const int*)d_in[1];
    const float* eattr = (const float*)d_in[2];
    const float* W_in  = (const float*)d_in[3];
    const float* b_in  = (const float*)d_in[4];
    const float* Wl1   = (const float*)d_in[5];
    const float* Wr1   = (const float*)d_in[6];
    const float* We1   = (const float*)d_in[7];
    const float* att1  = (const float*)d_in[8];
    const float* bg1   = (const float*)d_in[9];
    const float* ln1_g = (const float*)d_in[10];
    const float* ln1_b = (const float*)d_in[11];
    const float* W_down= (const float*)d_in[12];
    const float* lnd_g = (const float*)d_in[13];
    const float* lnd_b = (const float*)d_in[14];
    const float* Wl2   = (const float*)d_in[15];
    const float* Wr2   = (const float*)d_in[16];
    const float* We2   = (const float*)d_in[17];
    const float* att2  = (const float*)d_in[18];
    const float* bg2   = (const float*)d_in[19];
    const float* ln2_g = (const float*)d_in[20];
    const float* ln2_b = (const float*)d_in[21];
    const float* W_up  = (const float*)d_in[22];
    const float* lnu_g = (const float*)d_in[23];
    const float* lnu_b = (const float*)d_in[24];
    const float* W_cls = (const float*)d_in[25];
    const float* b_cls = (const float*)d_in[26];

    const int n = in_sizes[0] / 18;        // 20000
    const int E = in_sizes[1] / 2;         // 320000
    const int* src = eidx;
    const int* dst = eidx + E;

    float *h1, *z, *tmp;
    __half *xlr, *h0h, *h1h, *zh, *z2h, *outh, *wth;
    int *deg, *cur, *off;
    int2 *epack;
    cudaGetSymbolAddress((void**)&xlr, g_xlr);
    cudaGetSymbolAddress((void**)&h1, g_h1);
    cudaGetSymbolAddress((void**)&z, g_z);
    cudaGetSymbolAddress((void**)&tmp, g_tmp);
    cudaGetSymbolAddress((void**)&h0h, g_h0h);
    cudaGetSymbolAddress((void**)&h1h, g_h1h);
    cudaGetSymbolAddress((void**)&zh, g_zh);
    cudaGetSymbolAddress((void**)&z2h, g_z2h);
    cudaGetSymbolAddress((void**)&outh, g_outh);
    cudaGetSymbolAddress((void**)&wth, g_wth);
    cudaGetSymbolAddress((void**)&deg, g_deg);
    cudaGetSymbolAddress((void**)&cur, g_cur);
    cudaGetSymbolAddress((void**)&off, g_off);
    cudaGetSymbolAddress((void**)&epack, g_epack);

    float* out_logits = (float*)d_out;
    float* out_h = (float*)d_out + (size_t)n * 1000;

    const int lnBlocks = (n + 7) / 8;
    const int nodeBlocks = (n + 7) / 8;

    // ---- CSR build (once; reused by both layers) ----
    zero_int2_kernel<<<(n + 255) / 256, 256>>>(deg, cur, n);
    hist_kernel<<<(E + 255) / 256, 256>>>(dst, deg, E);
    scan_kernel<<<1, 1024>>>(deg, off, n);
    scatter_kernel<<<(E + 255) / 256, 256>>>(src, dst, eattr, off, cur, epack, E);

    // ---- fused transpose of all 7 weights -> fp16 ----
    {
        TransDescs td;
        auto set = [&](int i, const float* in, __half* out, int Kreal, int Kpad, int N, int& cum) {
            td.d[i].in = in; td.d[i].out = out;
            td.d[i].Kreal = Kreal; td.d[i].Kpad = Kpad; td.d[i].N = N;
            td.d[i].blkStart = cum; td.d[i].nx = (N + 31) / 32;
            cum += td.d[i].nx * ((Kpad + 31) / 32);
        };
        int cum = 0;
        set(0, Wl1,    wth + WTH_L1,            32, 64, DIM, cum);
        set(1, Wr1,    wth + WTH_L1 + 256 * 64, 32, 64, DIM, cum);
        set(2, W_down, wth + WTH_DN,  DIM, DIM, DIM, cum);
        set(3, Wl2,    wth + WTH_L2,  DIM, DIM, DIM, cum);
        set(4, Wr2,    wth + WTH_L2 + 256 * 256, DIM, DIM, DIM, cum);
        set(5, W_up,   wth + WTH_UP,  DIM, DIM, DIM, cum);
        set(6, W_cls,  wth + WTH_CLS, DIM, DIM, 1000, cum);
        td.total = cum;
        transpose_all_kernel<<<cum, dim3(32, 8)>>>(td);
    }

    // ---- input projection (fp32 math, fp16 out, K padded to 64) ----
    inproj_kernel<<<(n + 7) / 8, 256>>>(x_gnn, W_in, b_in, h0h, n);

    // ---- GAT layer 1 ----
    launch_tgemm16(h0h, wth + WTH_L1, xlr, n, 512, 64);
    gatln_kernel<<<nodeBlocks, 256>>>(xlr, off, epack, We1, att1, bg1,
                                      nullptr, ln1_g, ln1_b, h1, h1h, n);

    // ---- bottleneck down ----
    launch_tgemm32(h1h, wth + WTH_DN, nullptr, tmp, n, DIM, DIM);
    ln_kernel<<<lnBlocks, 256>>>(tmp, nullptr, lnd_g, lnd_b, z, zh, n);

    // ---- GAT layer 2 (residual z inside fused gather-LN) ----
    launch_tgemm16(zh, wth + WTH_L2, xlr, n, 512, DIM);
    gatln_kernel<<<nodeBlocks, 256>>>(xlr, off, epack, We2, att2, bg2,
                                      z, ln2_g, ln2_b, nullptr, z2h, n);

    // ---- up projection + final LN ----
    launch_tgemm32(z2h, wth + WTH_UP, nullptr, tmp, n, DIM, DIM);
    ln_kernel<<<lnBlocks, 256>>>(tmp, h1, lnu_g, lnu_b, out_h, outh, n);

    // ---- classifier ----
    launch_tgemm32(outh, wth + WTH_CLS, b_cls, out_logits, n, 1000, DIM);
}

// round 11
// speedup vs baseline: 4.9727x; 1.0204x over previous
#include <cuda_runtime.h>
#include <cuda_fp16.h>
#include <math.h>
#include <stdint.h>

// ---------------- problem constants ----------------
#define NMAX 20000
#define EMAX 320000
#define DIM 256
#define HEADS 8

// ---------------- scratch ----------------
__device__ __align__(16) __half g_xlr[NMAX * 512];      // fp16: [n,0:256]=xl, [n,256:512]=xr
__device__ __align__(16) float g_h1[NMAX * DIM];
__device__ __align__(16) float g_z[NMAX * DIM];
__device__ __align__(16) float g_tmp[NMAX * DIM];
// fp16 activation copies (GEMM A operands)
__device__ __align__(16) __half g_h0h[NMAX * 64];
__device__ __align__(16) __half g_h1h[NMAX * DIM];
__device__ __align__(16) __half g_zh[NMAX * DIM];
__device__ __align__(16) __half g_z2h[NMAX * DIM];
__device__ __align__(16) __half g_outh[NMAX * DIM];
// CSR by dst
__device__ int   g_deg[NMAX];
__device__ int   g_cur[NMAX];
__device__ int   g_off[NMAX + 1];
__device__ int2  g_epack[EMAX];            // .x = src, .y = float bits of edge_attr
// fp16 transposed weights
#define WTH_L1  0
#define WTH_DN  32768
#define WTH_L2  98304
#define WTH_UP  229376
#define WTH_CLS 294912
#define WTH_TOTAL (294912 + 256000)
__device__ __align__(16) __half g_wth[WTH_TOTAL];

// ---------------- helpers ----------------
__device__ __forceinline__ float warpReduceSum(float v) {
#pragma unroll
    for (int o = 16; o > 0; o >>= 1) v += __shfl_xor_sync(0xffffffffu, v, o);
    return v;
}

__device__ __forceinline__ float leaky(float v) { return v > 0.f ? v : 0.2f * v; }

__device__ __forceinline__ uint32_t smem_u32(const void* p) {
    uint32_t a;
    asm("{ .reg .u64 t; cvta.to.shared.u64 t, %1; cvt.u32.u64 %0, t; }" : "=r"(a) : "l"(p));
    return a;
}

__device__ __forceinline__ void cpasync16(uint32_t dst, const void* src, bool valid) {
    int sz = valid ? 16 : 0;
    asm volatile("cp.async.cg.shared.global [%0], [%1], 16, %2;"
                 :: "r"(dst), "l"(src), "r"(sz));
}
__device__ __forceinline__ void cpasync_commit() { asm volatile("cp.async.commit_group;"); }
__device__ __forceinline__ void cpasync_wait0() { asm volatile("cp.async.wait_group 0;"); }

#define LDMATRIX_X4(r0, r1, r2, r3, addr) \
    asm volatile("ldmatrix.sync.aligned.m8n8.x4.shared.b16 {%0,%1,%2,%3}, [%4];" \
                 : "=r"(r0), "=r"(r1), "=r"(r2), "=r"(r3) : "r"(addr))

// ---------------- fused prologue: zero(deg,cur) + transpose-all + inproj ----------------
struct TransDesc { const float* in; __half* out; int Kreal, Kpad, N, blkStart, nx; };
struct PrologueArgs {
    TransDesc d[7];
    int tcum;                 // total transpose blocks
    int zb;                   // zero blocks
    int* deg; int* cur;
    const float* x; const float* W_in; const float* b_in; __half* h0h;
    int n;
};

__global__ void prologue_kernel(PrologueArgs pa) {
    __shared__ float sbuf[32 * 33];
    int bid = blockIdx.x;
    int tid = threadIdx.x;
    if (bid < pa.zb) {
        // zero deg and cur (2n ints)
        int i = bid * 256 + tid;
        int n2 = pa.n * 2;
        if (i < n2) {
            if (i < pa.n) pa.deg[i] = 0;
            else pa.cur[i - pa.n] = 0;
        }
        return;
    }
    bid -= pa.zb;
    if (bid < pa.tcum) {
        // transpose: in[Kreal,N] fp32 -> out[N,Kpad] fp16
        float (*t)[33] = (float(*)[33])sbuf;
        int di = 0;
#pragma unroll
        for (int i = 1; i < 7; i++) if (bid >= pa.d[i].blkStart) di = i;
        const TransDesc& D = pa.d[di];
        int rem = bid - D.blkStart;
        int bx = (rem % D.nx) * 32, by = (rem / D.nx) * 32;
        int tx = tid & 31, ty = tid >> 5;
        int x = bx + tx, y = by + ty;
#pragma unroll
        for (int i = 0; i < 32; i += 8)
            t[ty + i][tx] = (x < D.N && y + i < D.Kreal) ? D.in[(size_t)(y + i) * D.N + x] : 0.f;
        __syncthreads();
        x = by + tx;            // k
        y = bx + ty;            // n
#pragma unroll
        for (int i = 0; i < 32; i += 8)
            if (x < D.Kpad && y + i < D.N)
                D.out[(size_t)(y + i) * D.Kpad + x] = __float2half(t[tx][ty + i]);
        return;
    }
    bid -= pa.tcum;
    // input projection: 8 rows per block
    {
        float* sW = sbuf;            // 576 floats
        float* sb = sbuf + 576;      // 32 floats
        for (int i = tid; i < 18 * 32; i += 256) sW[i] = pa.W_in[i];
        if (tid < 32) sb[tid] = pa.b_in[tid];
        __syncthreads();
        int row = bid * 8 + (tid >> 5);
        int col = tid & 31;
        if (row >= pa.n) return;
        const float* xr = pa.x + (size_t)row * 18;
        float v = sb[col];
#pragma unroll
        for (int k = 0; k < 18; k++) v += xr[k] * sW[k * 32 + col];
        pa.h0h[(size_t)row * 64 + col] = __float2half(v);
        pa.h0h[(size_t)row * 64 + 32 + col] = __float2half(0.f);
    }
}

// ---------------- CSR build ----------------
__global__ void hist_kernel(const int* __restrict__ dst, int* __restrict__ deg, int E) {
    int e = blockIdx.x * blockDim.x + threadIdx.x;
    if (e < E) atomicAdd(&deg[dst[e]], 1);
}

__global__ void scan_kernel(const int* __restrict__ deg, int* __restrict__ off, int n) {
    __shared__ int warp_sums[32];
    __shared__ int carry_s;
    int tid = threadIdx.x;                    // 1024 threads, single block
    if (tid == 0) carry_s = 0;
    __syncthreads();
    for (int base = 0; base < n; base += 1024) {
        int i = base + tid;
        int v = (i < n) ? deg[i] : 0;
        int x = v;
#pragma unroll
        for (int o = 1; o < 32; o <<= 1) {
            int y = __shfl_up_sync(0xffffffffu, x, o);
            if ((tid & 31) >= o) x += y;
        }
        if ((tid & 31) == 31) warp_sums[tid >> 5] = x;
        __syncthreads();
        if (tid < 32) {
            int s = warp_sums[tid];
#pragma unroll
            for (int o = 1; o < 32; o <<= 1) {
                int y = __shfl_up_sync(0xffffffffu, s, o);
                if (tid >= o) s += y;
            }
            warp_sums[tid] = s;
        }
        __syncthreads();
        int incl = x + ((tid >= 32) ? warp_sums[(tid >> 5) - 1] : 0);
        if (i < n) off[i] = carry_s + incl - v;
        __syncthreads();
        if (tid == 1023) carry_s += incl;
        __syncthreads();
    }
    if (tid == 0) off[n] = carry_s;
}

__global__ void scatter_kernel(const int* __restrict__ src, const int* __restrict__ dst,
                               const float* __restrict__ ea, const int* __restrict__ off,
                               int* __restrict__ cur, int2* __restrict__ epack, int E) {
    int e = blockIdx.x * blockDim.x + threadIdx.x;
    if (e >= E) return;
    int d = dst[e];
    int pos = off[d] + atomicAdd(&cur[d], 1);
    epack[pos] = make_int2(src[e], __float_as_int(ea[e]));
}

// ---------------- fp16 mma.sync GEMM: out = A[M,K] @ WT[N,K]^T (+bias), fp32 accum ------
#define SWW 36
#define CHUNK_WORDS (128 * SWW)

extern __shared__ uint32_t g_dynsmem_u[];

__global__ __launch_bounds__(256)
void mma_gemm_h(const __half* __restrict__ A, const __half* __restrict__ WT,
                const float* __restrict__ bias, float* __restrict__ C32,
                __half* __restrict__ C16, int M, int N, int K) {
    const int tid = threadIdx.x;
    const int wid = tid >> 5, lane = tid & 31;
    const int gid = lane >> 2, tig = lane & 3;
    const int wm = (wid >> 2) * 64, wn = (wid & 3) * 32;
    const int m0 = blockIdx.y * 128, n0 = blockIdx.x * 128;

    float acc[4][4][4];
#pragma unroll
    for (int mi = 0; mi < 4; mi++)
#pragma unroll
        for (int ni = 0; ni < 4; ni++)
#pragma unroll
            for (int q = 0; q < 4; q++) acc[mi][ni][q] = 0.f;

    const int nc = (K + 63) >> 6;
    uint32_t aAddr[2], bAddr[2];
    aAddr[0] = smem_u32(g_dynsmem_u);
    bAddr[0] = aAddr[0] + CHUNK_WORDS * 4;
    aAddr[1] = aAddr[0] + 2 * CHUNK_WORDS * 4;
    bAddr[1] = aAddr[0] + 3 * CHUNK_WORDS * 4;

    const uint32_t aOff = (uint32_t)((wm + (lane & 15)) * 144 + (lane >> 4) * 16);
    const uint32_t bOff = (uint32_t)((wn + (lane & 7) + ((lane >> 4) << 3)) * 144
                                     + ((lane >> 3) & 1) * 16);

    auto issue = [&](int c, int b) {
        int k0 = c << 6;
        int Kc = K - k0; if (Kc > 64) Kc = 64;
#pragma unroll
        for (int i = 0; i < 4; i++) {
            int idx = tid + i * 256;
            int row = idx >> 3, q = idx & 7;
            uint32_t soff = (uint32_t)(row * 144 + q * 16);
            bool kv = (q * 8) < Kc;
            cpasync16(aAddr[b] + soff, A + (size_t)(m0 + row) * K + k0 + q * 8,
                      kv && (m0 + row < M));
            cpasync16(bAddr[b] + soff, WT + (size_t)(n0 + row) * K + k0 + q * 8,
                      kv && (n0 + row < N));
        }
        cpasync_commit();
    };

    issue(0, 0);
    for (int c = 0; c < nc; c++) {
        int cur = c & 1;
        cpasync_wait0();
        __syncthreads();                 // orders: data visible AND prev-iter reads complete
        if (c + 1 < nc) issue(c + 1, cur ^ 1);
        uint32_t aB = aAddr[cur] + aOff;
        uint32_t bB = bAddr[cur] + bOff;
        int Kc = K - (c << 6); if (Kc > 64) Kc = 64;
#pragma unroll
        for (int ks = 0; ks < 4; ks++) {
            if (ks * 16 < Kc) {
                uint32_t af[4][4], bf[4][2];
#pragma unroll
                for (int mi = 0; mi < 4; mi++)
                    LDMATRIX_X4(af[mi][0], af[mi][1], af[mi][2], af[mi][3],
                                aB + mi * 16 * 144 + ks * 32);
#pragma unroll
                for (int np = 0; np < 2; np++)
                    LDMATRIX_X4(bf[2 * np][0], bf[2 * np][1], bf[2 * np + 1][0], bf[2 * np + 1][1],
                                bB + np * 16 * 144 + ks * 32);
#pragma unroll
                for (int mi = 0; mi < 4; mi++)
#pragma unroll
                    for (int ni = 0; ni < 4; ni++) {
                        asm volatile(
                            "mma.sync.aligned.m16n8k16.row.col.f32.f16.f16.f32 "
                            "{%0,%1,%2,%3}, {%4,%5,%6,%7}, {%8,%9}, {%0,%1,%2,%3};"
                            : "+f"(acc[mi][ni][0]), "+f"(acc[mi][ni][1]),
                              "+f"(acc[mi][ni][2]), "+f"(acc[mi][ni][3])
                            : "r"(af[mi][0]), "r"(af[mi][1]), "r"(af[mi][2]), "r"(af[mi][3]),
                              "r"(bf[ni][0]), "r"(bf[ni][1]));
                    }
            }
        }
        // no trailing barrier: next iteration's top barrier orders buffer reuse
    }

#pragma unroll
    for (int mi = 0; mi < 4; mi++) {
        int r0 = m0 + wm + mi * 16 + gid;
        int r1 = r0 + 8;
#pragma unroll
        for (int ni = 0; ni < 4; ni++) {
            int col = n0 + wn + ni * 8 + tig * 2;
            if (col >= N) continue;
            if (C16) {
                if (r0 < M)
                    *(__half2*)(C16 + (size_t)r0 * N + col) =
                        __floats2half2_rn(acc[mi][ni][0], acc[mi][ni][1]);
                if (r1 < M)
                    *(__half2*)(C16 + (size_t)r1 * N + col) =
                        __floats2half2_rn(acc[mi][ni][2], acc[mi][ni][3]);
            } else {
                float bx = 0.f, by = 0.f;
                if (bias) { bx = bias[col]; by = bias[col + 1]; }
                if (r0 < M)
                    *(float2*)(C32 + (size_t)r0 * N + col) =
                        make_float2(acc[mi][ni][0] + bx, acc[mi][ni][1] + by);
                if (r1 < M)
                    *(float2*)(C32 + (size_t)r1 * N + col) =
                        make_float2(acc[mi][ni][2] + bx, acc[mi][ni][3] + by);
            }
        }
    }
}

// ---------------- fused CSR gather GAT + LayerNorm (fp16 xlr): warp per dst node --------
__global__ void gatln_kernel(const __half* __restrict__ xlr,
                             const int* __restrict__ off, const int2* __restrict__ epack,
                             const float* __restrict__ We, const float* __restrict__ att,
                             const float* __restrict__ bias, const float* __restrict__ res,
                             const float* __restrict__ lng, const float* __restrict__ lnb,
                             float* __restrict__ out32, __half* __restrict__ out16, int n) {
    int d = (blockIdx.x * blockDim.x + threadIdx.x) >> 5;
    int lane = threadIdx.x & 31;
    if (d >= n) return;
    float r[8], w[8], t[8];
    {
        uint4 rv = ((const uint4*)(xlr + (size_t)d * 512 + 256))[lane];
        const __half2* hp = (const __half2*)&rv;
#pragma unroll
        for (int k = 0; k < 4; k++) {
            float2 f = __half22float2(hp[k]);
            r[2 * k] = f.x; r[2 * k + 1] = f.y;
        }
        float4 wa = ((const float4*)We)[2 * lane], wb = ((const float4*)We)[2 * lane + 1];
        w[0] = wa.x; w[1] = wa.y; w[2] = wa.z; w[3] = wa.w;
        w[4] = wb.x; w[5] = wb.y; w[6] = wb.z; w[7] = wb.w;
        float4 ta = ((const float4*)att)[2 * lane], tb = ((const float4*)att)[2 * lane + 1];
        t[0] = ta.x; t[1] = ta.y; t[2] = ta.z; t[3] = ta.w;
        t[4] = tb.x; t[5] = tb.y; t[6] = tb.z; t[7] = tb.w;
    }
    float acc[8];
#pragma unroll
    for (int k = 0; k < 8; k++) acc[k] = 0.f;
    float ss = 0.f;
    int beg = off[d], cnt = off[d + 1] - beg;
    const int2* ep = epack + beg;
    if (cnt > 0) {
        int2 pk = ep[0];
        uint4 lv = ((const uint4*)(xlr + (size_t)pk.x * 512))[lane];
        float aa = __int_as_float(pk.y);
        for (int i = 0; i < cnt; i++) {
            uint4 cv = lv;
            float ca = aa;
            if (i + 1 < cnt) {                 // prefetch next edge's src row
                int2 p2 = ep[i + 1];
                lv = ((const uint4*)(xlr + (size_t)p2.x * 512))[lane];
                aa = __int_as_float(p2.y);
            }
            float l[8];
            const __half2* hp = (const __half2*)&cv;
#pragma unroll
            for (int k = 0; k < 4; k++) {
                float2 f = __half22float2(hp[k]);
                l[2 * k] = f.x; l[2 * k + 1] = f.y;
            }
            float p = 0.f;
#pragma unroll
            for (int k = 0; k < 8; k++) p += leaky(l[k] + r[k] + ca * w[k]) * t[k];
            p += __shfl_xor_sync(0xffffffffu, p, 1);
            p += __shfl_xor_sync(0xffffffffu, p, 2);
            float e = __expf(p);
#pragma unroll
            for (int k = 0; k < 8; k++) acc[k] += e * l[k];
            ss += e;
        }
    }
    float iv = 1.f / (ss + 1e-16f);
    float v[8];
    {
        float4 ba = ((const float4*)bias)[2 * lane], bb = ((const float4*)bias)[2 * lane + 1];
        v[0] = acc[0] * iv + ba.x; v[1] = acc[1] * iv + ba.y;
        v[2] = acc[2] * iv + ba.z; v[3] = acc[3] * iv + ba.w;
        v[4] = acc[4] * iv + bb.x; v[5] = acc[5] * iv + bb.y;
        v[6] = acc[6] * iv + bb.z; v[7] = acc[7] * iv + bb.w;
    }
    if (res) {
        float4 ra = ((const float4*)(res + (size_t)d * DIM))[2 * lane];
        float4 rb = ((const float4*)(res + (size_t)d * DIM))[2 * lane + 1];
        v[0] += ra.x; v[1] += ra.y; v[2] += ra.z; v[3] += ra.w;
        v[4] += rb.x; v[5] += rb.y; v[6] += rb.z; v[7] += rb.w;
    }
    float sum = 0.f;
#pragma unroll
    for (int k = 0; k < 8; k++) sum += v[k];
    sum = warpReduceSum(sum);
    float mu = sum * (1.f / 256.f);
    float var = 0.f;
#pragma unroll
    for (int k = 0; k < 8; k++) { float dd = v[k] - mu; var += dd * dd; }
    var = warpReduceSum(var) * (1.f / 256.f);
    float inv = rsqrtf(var + 1e-5f);
    float4 ga = ((const float4*)lng)[2 * lane], gb = ((const float4*)lng)[2 * lane + 1];
    float4 ca4 = ((const float4*)lnb)[2 * lane], cb4 = ((const float4*)lnb)[2 * lane + 1];
    float o[8];
    o[0] = (v[0] - mu) * inv * ga.x + ca4.x; o[1] = (v[1] - mu) * inv * ga.y + ca4.y;
    o[2] = (v[2] - mu) * inv * ga.z + ca4.z; o[3] = (v[3] - mu) * inv * ga.w + ca4.w;
    o[4] = (v[4] - mu) * inv * gb.x + cb4.x; o[5] = (v[5] - mu) * inv * gb.y + cb4.y;
    o[6] = (v[6] - mu) * inv * gb.z + cb4.z; o[7] = (v[7] - mu) * inv * gb.w + cb4.w;
    if (out32) {
        float4* op = (float4*)(out32 + (size_t)d * DIM);
        op[2 * lane]     = make_float4(o[0], o[1], o[2], o[3]);
        op[2 * lane + 1] = make_float4(o[4], o[5], o[6], o[7]);
    }
    if (out16) {
        uint4 pk16;
        __half2 h0 = __floats2half2_rn(o[0], o[1]), h1 = __floats2half2_rn(o[2], o[3]);
        __half2 h2 = __floats2half2_rn(o[4], o[5]), h3 = __floats2half2_rn(o[6], o[7]);
        pk16.x = *(uint32_t*)&h0; pk16.y = *(uint32_t*)&h1;
        pk16.z = *(uint32_t*)&h2; pk16.w = *(uint32_t*)&h3;
        ((uint4*)(out16 + (size_t)d * DIM))[lane] = pk16;
    }
}

// ---------------- layernorm (dim=256); optional residual; fp32 + fp16 outputs ----------
__global__ void ln_kernel(const float* __restrict__ x, const float* __restrict__ res,
                          const float* __restrict__ g, const float* __restrict__ b,
                          float* __restrict__ out32, __half* __restrict__ out16, int n) {
    int row = blockIdx.x * 8 + (threadIdx.x >> 5);
    int lane = threadIdx.x & 31;
    if (row >= n) return;
    const float4* xr4 = (const float4*)(x + (size_t)row * DIM);
    const float4* rs4 = res ? (const float4*)(res + (size_t)row * DIM) : nullptr;
    float4 v[2];
    float sum = 0.f;
#pragma unroll
    for (int k = 0; k < 2; k++) {
        int q = k * 32 + lane;
        float4 t = xr4[q];
        if (rs4) { float4 r = rs4[q]; t.x += r.x; t.y += r.y; t.z += r.z; t.w += r.w; }
        v[k] = t;
        sum += t.x + t.y + t.z + t.w;
    }
    sum = warpReduceSum(sum);
    float mu = sum * (1.f / 256.f);
    float var = 0.f;
#pragma unroll
    for (int k = 0; k < 2; k++) {
        float dx = v[k].x - mu, dy = v[k].y - mu, dz = v[k].z - mu, dw = v[k].w - mu;
        var += dx * dx + dy * dy + dz * dz + dw * dw;
    }
    var = warpReduceSum(var) * (1.f / 256.f);
    float inv = rsqrtf(var + 1e-5f);
    const float4* g4 = (const float4*)g;
    const float4* b4 = (const float4*)b;
#pragma unroll
    for (int k = 0; k < 2; k++) {
        int q = k * 32 + lane;
        float4 gg = g4[q], bb = b4[q];
        float4 o = make_float4((v[k].x - mu) * inv * gg.x + bb.x,
                               (v[k].y - mu) * inv * gg.y + bb.y,
                               (v[k].z - mu) * inv * gg.z + bb.z,
                               (v[k].w - mu) * inv * gg.w + bb.w);
        if (out32) ((float4*)(out32 + (size_t)row * DIM))[q] = o;
        if (out16) {
            __half2* o16 = (__half2*)(out16 + (size_t)row * DIM);
            o16[q * 2]     = __floats2half2_rn(o.x, o.y);
            o16[q * 2 + 1] = __floats2half2_rn(o.z, o.w);
        }
    }
}

// ---------------- host ----------------
#define DYN_SMEM (4 * CHUNK_WORDS * sizeof(uint32_t))   // 73728 bytes

static inline void launch_tgemm32(const __half* A, const __half* WT, const float* bias,
                                  float* C, int M, int N, int K) {
    dim3 grid((N + 127) / 128, (M + 127) / 128);
    mma_gemm_h<<<grid, 256, DYN_SMEM>>>(A, WT, bias, C, nullptr, M, N, K);
}
static inline void launch_tgemm16(const __half* A, const __half* WT, __half* C,
                                  int M, int N, int K) {
    dim3 grid((N + 127) / 128, (M + 127) / 128);
    mma_gemm_h<<<grid, 256, DYN_SMEM>>>(A, WT, nullptr, nullptr, C, M, N, K);
}

extern "C" void kernel_launch(void* const* d_in, const int* in_sizes, int n_in,
                              void* d_out, int out_size) {
    cudaFuncSetAttribute(mma_gemm_h, cudaFuncAttributeMaxDynamicSharedMemorySize, DYN_SMEM);

    const float* x_gnn = (const float*)d_in[0];
    const int*   eidx  = (const int*)d_in[1];
    const float* eattr = (const float*)d_in[2];
    const float* W_in  = (const float*)d_in[3];
    const float* b_in  = (const float*)d_in[4];
    const float* Wl1   = (const float*)d_in[5];
    const float* Wr1   = (const float*)d_in[6];
    const float* We1   = (const float*)d_in[7];
    const float* att1  = (const float*)d_in[8];
    const float* bg1   = (const float*)d_in[9];
    const float* ln1_g = (const float*)d_in[10];
    const float* ln1_b = (const float*)d_in[11];
    const float* W_down= (const float*)d_in[12];
    const float* lnd_g = (const float*)d_in[13];
    const float* lnd_b = (const float*)d_in[14];
    const float* Wl2   = (const float*)d_in[15];
    const float* Wr2   = (const float*)d_in[16];
    const float* We2   = (const float*)d_in[17];
    const float* att2  = (const float*)d_in[18];
    const float* bg2   = (const float*)d_in[19];
    const float* ln2_g = (const float*)d_in[20];
    const float* ln2_b = (const float*)d_in[21];
    const float* W_up  = (const float*)d_in[22];
    const float* lnu_g = (const float*)d_in[23];
    const float* lnu_b = (const float*)d_in[24];
    const float* W_cls = (const float*)d_in[25];
    const float* b_cls = (const float*)d_in[26];

    const int n = in_sizes[0] / 18;        // 20000
    const int E = in_sizes[1] / 2;         // 320000
    const int* src = eidx;
    const int* dst = eidx + E;

    float *h1, *z, *tmp;
    __half *xlr, *h0h, *h1h, *zh, *z2h, *outh, *wth;
    int *deg, *cur, *off;
    int2 *epack;
    cudaGetSymbolAddress((void**)&xlr, g_xlr);
    cudaGetSymbolAddress((void**)&h1, g_h1);
    cudaGetSymbolAddress((void**)&z, g_z);
    cudaGetSymbolAddress((void**)&tmp, g_tmp);
    cudaGetSymbolAddress((void**)&h0h, g_h0h);
    cudaGetSymbolAddress((void**)&h1h, g_h1h);
    cudaGetSymbolAddress((void**)&zh, g_zh);
    cudaGetSymbolAddress((void**)&z2h, g_z2h);
    cudaGetSymbolAddress((void**)&outh, g_outh);
    cudaGetSymbolAddress((void**)&wth, g_wth);
    cudaGetSymbolAddress((void**)&deg, g_deg);
    cudaGetSymbolAddress((void**)&cur, g_cur);
    cudaGetSymbolAddress((void**)&off, g_off);
    cudaGetSymbolAddress((void**)&epack, g_epack);

    float* out_logits = (float*)d_out;
    float* out_h = (float*)d_out + (size_t)n * 1000;

    const int lnBlocks = (n + 7) / 8;
    const int nodeBlocks = (n + 7) / 8;

    // ---- fused prologue: zero(deg,cur) + weight transposes + input projection ----
    {
        PrologueArgs pa;
        auto set = [&](int i, const float* in, __half* out, int Kreal, int Kpad, int N, int& cum) {
            pa.d[i].in = in; pa.d[i].out = out;
            pa.d[i].Kreal = Kreal; pa.d[i].Kpad = Kpad; pa.d[i].N = N;
            pa.d[i].blkStart = cum; pa.d[i].nx = (N + 31) / 32;
            cum += pa.d[i].nx * ((Kpad + 31) / 32);
        };
        int cum = 0;
        set(0, Wl1,    wth + WTH_L1,            32, 64, DIM, cum);
        set(1, Wr1,    wth + WTH_L1 + 256 * 64, 32, 64, DIM, cum);
        set(2, W_down, wth + WTH_DN,  DIM, DIM, DIM, cum);
        set(3, Wl2,    wth + WTH_L2,  DIM, DIM, DIM, cum);
        set(4, Wr2,    wth + WTH_L2 + 256 * 256, DIM, DIM, DIM, cum);
        set(5, W_up,   wth + WTH_UP,  DIM, DIM, DIM, cum);
        set(6, W_cls,  wth + WTH_CLS, DIM, DIM, 1000, cum);
        pa.tcum = cum;
        pa.zb = (2 * n + 255) / 256;
        pa.deg = deg; pa.cur = cur;
        pa.x = x_gnn; pa.W_in = W_in; pa.b_in = b_in; pa.h0h = h0h;
        pa.n = n;
        int total = pa.zb + cum + (n + 7) / 8;
        prologue_kernel<<<total, 256>>>(pa);
    }

    // ---- GAT layer 1 GEMM (independent of CSR) ----
    launch_tgemm16(h0h, wth + WTH_L1, xlr, n, 512, 64);

    // ---- CSR build ----
    hist_kernel<<<(E + 255) / 256, 256>>>(dst, deg, E);
    scan_kernel<<<1, 1024>>>(deg, off, n);
    scatter_kernel<<<(E + 255) / 256, 256>>>(src, dst, eattr, off, cur, epack, E);

    // ---- GAT layer 1 gather+LN (launch #5 -> profiled) ----
    gatln_kernel<<<nodeBlocks, 256>>>(xlr, off, epack, We1, att1, bg1,
                                      nullptr, ln1_g, ln1_b, h1, h1h, n);

    // ---- bottleneck down ----
    launch_tgemm32(h1h, wth + WTH_DN, nullptr, tmp, n, DIM, DIM);
    ln_kernel<<<lnBlocks, 256>>>(tmp, nullptr, lnd_g, lnd_b, z, zh, n);

    // ---- GAT layer 2 (residual z inside fused gather-LN) ----
    launch_tgemm16(zh, wth + WTH_L2, xlr, n, 512, DIM);
    gatln_kernel<<<nodeBlocks, 256>>>(xlr, off, epack, We2, att2, bg2,
                                      z, ln2_g, ln2_b, nullptr, z2h, n);

    // ---- up projection + final LN ----
    launch_tgemm32(z2h, wth + WTH_UP, nullptr, tmp, n, DIM, DIM);
    ln_kernel<<<lnBlocks, 256>>>(tmp, h1, lnu_g, lnu_b, out_h, outh, n);

    // ---- classifier ----
    launch_tgemm32(outh, wth + WTH_CLS, b_cls, out_logits, n, 1000, DIM);
}

// round 12
// speedup vs baseline: 5.1216x; 1.0299x over previous
#include <cuda_runtime.h>
#include <cuda_fp16.h>
#include <math.h>
#include <stdint.h>

// ---------------- problem constants ----------------
#define NMAX 20000
#define EMAX 320000
#define DIM 256
#define HEADS 8

// ---------------- scratch ----------------
__device__ __align__(16) __half g_xlr[NMAX * 512];      // fp16: [n,0:256]=xl, [n,256:512]=xr
__device__ __align__(16) float g_h1[NMAX * DIM];
__device__ __align__(16) float g_z[NMAX * DIM];
__device__ __align__(16) float g_tmp[NMAX * DIM];
// fp16 activation copies (GEMM A operands)
__device__ __align__(16) __half g_h0h[NMAX * 64];
__device__ __align__(16) __half g_h1h[NMAX * DIM];
__device__ __align__(16) __half g_zh[NMAX * DIM];
__device__ __align__(16) __half g_z2h[NMAX * DIM];
__device__ __align__(16) __half g_outh[NMAX * DIM];
// CSR by dst
__device__ int   g_deg[NMAX];
__device__ int   g_cur[NMAX];
__device__ int   g_off[NMAX + 1];
__device__ int   g_bsum[32];
__device__ int2  g_epack[EMAX];            // .x = src, .y = float bits of edge_attr
// fp16 transposed weights
#define WTH_L1  0
#define WTH_DN  32768
#define WTH_L2  98304
#define WTH_UP  229376
#define WTH_CLS 294912
#define WTH_TOTAL (294912 + 256000)
__device__ __align__(16) __half g_wth[WTH_TOTAL];

#define SCAN_CHUNK 2048

// ---------------- helpers ----------------
__device__ __forceinline__ float warpReduceSum(float v) {
#pragma unroll
    for (int o = 16; o > 0; o >>= 1) v += __shfl_xor_sync(0xffffffffu, v, o);
    return v;
}

__device__ __forceinline__ float leaky(float v) { return v > 0.f ? v : 0.2f * v; }

__device__ __forceinline__ uint32_t smem_u32(const void* p) {
    uint32_t a;
    asm("{ .reg .u64 t; cvta.to.shared.u64 t, %1; cvt.u32.u64 %0, t; }" : "=r"(a) : "l"(p));
    return a;
}

__device__ __forceinline__ void cpasync16(uint32_t dst, const void* src, bool valid) {
    int sz = valid ? 16 : 0;
    asm volatile("cp.async.cg.shared.global [%0], [%1], 16, %2;"
                 :: "r"(dst), "l"(src), "r"(sz));
}
__device__ __forceinline__ void cpasync_commit() { asm volatile("cp.async.commit_group;"); }
__device__ __forceinline__ void cpasync_wait0() { asm volatile("cp.async.wait_group 0;"); }

#define LDMATRIX_X4(r0, r1, r2, r3, addr) \
    asm volatile("ldmatrix.sync.aligned.m8n8.x4.shared.b16 {%0,%1,%2,%3}, [%4];" \
                 : "=r"(r0), "=r"(r1), "=r"(r2), "=r"(r3) : "r"(addr))

// ---------------- fused prologue: zero(deg,cur) + transpose-all + inproj ----------------
struct TransDesc { const float* in; __half* out; int Kreal, Kpad, N, blkStart, nx; };
struct PrologueArgs {
    TransDesc d[7];
    int tcum;
    int zb;
    int* deg; int* cur;
    const float* x; const float* W_in; const float* b_in; __half* h0h;
    int n;
};

__global__ void prologue_kernel(PrologueArgs pa) {
    __shared__ float sbuf[32 * 33];
    int bid = blockIdx.x;
    int tid = threadIdx.x;
    if (bid < pa.zb) {
        int i = bid * 256 + tid;
        int n2 = pa.n * 2;
        if (i < n2) {
            if (i < pa.n) pa.deg[i] = 0;
            else pa.cur[i - pa.n] = 0;
        }
        return;
    }
    bid -= pa.zb;
    if (bid < pa.tcum) {
        float (*t)[33] = (float(*)[33])sbuf;
        int di = 0;
#pragma unroll
        for (int i = 1; i < 7; i++) if (bid >= pa.d[i].blkStart) di = i;
        const TransDesc& D = pa.d[di];
        int rem = bid - D.blkStart;
        int bx = (rem % D.nx) * 32, by = (rem / D.nx) * 32;
        int tx = tid & 31, ty = tid >> 5;
        int x = bx + tx, y = by + ty;
#pragma unroll
        for (int i = 0; i < 32; i += 8)
            t[ty + i][tx] = (x < D.N && y + i < D.Kreal) ? D.in[(size_t)(y + i) * D.N + x] : 0.f;
        __syncthreads();
        x = by + tx;
        y = bx + ty;
#pragma unroll
        for (int i = 0; i < 32; i += 8)
            if (x < D.Kpad && y + i < D.N)
                D.out[(size_t)(y + i) * D.Kpad + x] = __float2half(t[tx][ty + i]);
        return;
    }
    bid -= pa.tcum;
    {
        float* sW = sbuf;
        float* sb = sbuf + 576;
        for (int i = tid; i < 18 * 32; i += 256) sW[i] = pa.W_in[i];
        if (tid < 32) sb[tid] = pa.b_in[tid];
        __syncthreads();
        int row = bid * 8 + (tid >> 5);
        int col = tid & 31;
        if (row >= pa.n) return;
        const float* xr = pa.x + (size_t)row * 18;
        float v = sb[col];
#pragma unroll
        for (int k = 0; k < 18; k++) v += xr[k] * sW[k * 32 + col];
        pa.h0h[(size_t)row * 64 + col] = __float2half(v);
        pa.h0h[(size_t)row * 64 + 32 + col] = __float2half(0.f);
    }
}

// ---------------- CSR build ----------------
__global__ void hist_kernel(const int* __restrict__ dst, int* __restrict__ deg, int E) {
    int e = blockIdx.x * blockDim.x + threadIdx.x;
    if (e < E) atomicAdd(&deg[dst[e]], 1);
}

// parallel scan stage 1: per-chunk exclusive scan (chunk = 2048, 256 thr x 8 elems)
__global__ void scan_part_kernel(const int* __restrict__ deg, int* __restrict__ off,
                                 int* __restrict__ bsum, int n) {
    __shared__ int wsum[8];
    int b = blockIdx.x, tid = threadIdx.x;
    int base = b * SCAN_CHUNK + tid * 8;
    int v[8], e[8];
    int s = 0;
#pragma unroll
    for (int k = 0; k < 8; k++) {
        int i = base + k;
        v[k] = (i < n) ? deg[i] : 0;
        e[k] = s;
        s += v[k];
    }
    // warp inclusive scan of thread totals
    int x = s;
#pragma unroll
    for (int o = 1; o < 32; o <<= 1) {
        int y = __shfl_up_sync(0xffffffffu, x, o);
        if ((tid & 31) >= o) x += y;
    }
    if ((tid & 31) == 31) wsum[tid >> 5] = x;
    __syncthreads();
    if (tid < 8) {
        int t = wsum[tid];
#pragma unroll
        for (int o = 1; o < 8; o <<= 1) {
            int y = __shfl_up_sync(0xffu, t, o);
            if (tid >= o) t += y;
        }
        wsum[tid] = t;
    }
    __syncthreads();
    int thrOff = (x - s) + ((tid >= 32) ? wsum[(tid >> 5) - 1] : 0);
#pragma unroll
    for (int k = 0; k < 8; k++) {
        int i = base + k;
        if (i < n) off[i] = thrOff + e[k];
    }
    if (tid == 255) bsum[b] = thrOff + s;
}

// parallel scan stage 2: add chunk-prefix; off[n] = E
__global__ void scan_fix_kernel(int* __restrict__ off, const int* __restrict__ bsum,
                                int n, int E) {
    __shared__ int pre_s;
    int b = blockIdx.x, tid = threadIdx.x;
    if (tid < 32) {
        int v = (tid < b) ? bsum[tid] : 0;
#pragma unroll
        for (int o = 16; o > 0; o >>= 1) v += __shfl_xor_sync(0xffffffffu, v, o);
        if (tid == 0) pre_s = v;
    }
    __syncthreads();
    int pre = pre_s;
    if (pre != 0) {
        int base = b * SCAN_CHUNK + tid;
#pragma unroll
        for (int k = 0; k < 8; k++) {
            int i = base + k * 256;
            if (i < n) off[i] += pre;
        }
    }
    if (b == 0 && tid == 0) off[n] = E;
}

__global__ void scatter_kernel(const int* __restrict__ src, const int* __restrict__ dst,
                               const float* __restrict__ ea, const int* __restrict__ off,
                               int* __restrict__ cur, int2* __restrict__ epack, int E) {
    int e = blockIdx.x * blockDim.x + threadIdx.x;
    if (e >= E) return;
    int d = dst[e];
    int pos = off[d] + atomicAdd(&cur[d], 1);
    epack[pos] = make_int2(src[e], __float_as_int(ea[e]));
}

// ---------------- fp16 mma.sync GEMM: out = A[M,K] @ WT[N,K]^T (+bias), fp32 accum ------
#define SWW 36
#define CHUNK_WORDS (128 * SWW)

extern __shared__ uint32_t g_dynsmem_u[];

__global__ __launch_bounds__(256)
void mma_gemm_h(const __half* __restrict__ A, const __half* __restrict__ WT,
                const float* __restrict__ bias, float* __restrict__ C32,
                __half* __restrict__ C16, int M, int N, int K) {
    const int tid = threadIdx.x;
    const int wid = tid >> 5, lane = tid & 31;
    const int gid = lane >> 2, tig = lane & 3;
    const int wm = (wid >> 2) * 64, wn = (wid & 3) * 32;
    const int m0 = blockIdx.y * 128, n0 = blockIdx.x * 128;

    float acc[4][4][4];
#pragma unroll
    for (int mi = 0; mi < 4; mi++)
#pragma unroll
        for (int ni = 0; ni < 4; ni++)
#pragma unroll
            for (int q = 0; q < 4; q++) acc[mi][ni][q] = 0.f;

    const int nc = (K + 63) >> 6;
    uint32_t aAddr[2], bAddr[2];
    aAddr[0] = smem_u32(g_dynsmem_u);
    bAddr[0] = aAddr[0] + CHUNK_WORDS * 4;
    aAddr[1] = aAddr[0] + 2 * CHUNK_WORDS * 4;
    bAddr[1] = aAddr[0] + 3 * CHUNK_WORDS * 4;

    const uint32_t aOff = (uint32_t)((wm + (lane & 15)) * 144 + (lane >> 4) * 16);
    const uint32_t bOff = (uint32_t)((wn + (lane & 7) + ((lane >> 4) << 3)) * 144
                                     + ((lane >> 3) & 1) * 16);

    auto issue = [&](int c, int b) {
        int k0 = c << 6;
        int Kc = K - k0; if (Kc > 64) Kc = 64;
#pragma unroll
        for (int i = 0; i < 4; i++) {
            int idx = tid + i * 256;
            int row = idx >> 3, q = idx & 7;
            uint32_t soff = (uint32_t)(row * 144 + q * 16);
            bool kv = (q * 8) < Kc;
            cpasync16(aAddr[b] + soff, A + (size_t)(m0 + row) * K + k0 + q * 8,
                      kv && (m0 + row < M));
            cpasync16(bAddr[b] + soff, WT + (size_t)(n0 + row) * K + k0 + q * 8,
                      kv && (n0 + row < N));
        }
        cpasync_commit();
    };

    issue(0, 0);
    for (int c = 0; c < nc; c++) {
        int cur = c & 1;
        cpasync_wait0();
        __syncthreads();
        if (c + 1 < nc) issue(c + 1, cur ^ 1);
        uint32_t aB = aAddr[cur] + aOff;
        uint32_t bB = bAddr[cur] + bOff;
        int Kc = K - (c << 6); if (Kc > 64) Kc = 64;
#pragma unroll
        for (int ks = 0; ks < 4; ks++) {
            if (ks * 16 < Kc) {
                uint32_t af[4][4], bf[4][2];
#pragma unroll
                for (int mi = 0; mi < 4; mi++)
                    LDMATRIX_X4(af[mi][0], af[mi][1], af[mi][2], af[mi][3],
                                aB + mi * 16 * 144 + ks * 32);
#pragma unroll
                for (int np = 0; np < 2; np++)
                    LDMATRIX_X4(bf[2 * np][0], bf[2 * np][1], bf[2 * np + 1][0], bf[2 * np + 1][1],
                                bB + np * 16 * 144 + ks * 32);
#pragma unroll
                for (int mi = 0; mi < 4; mi++)
#pragma unroll
                    for (int ni = 0; ni < 4; ni++) {
                        asm volatile(
                            "mma.sync.aligned.m16n8k16.row.col.f32.f16.f16.f32 "
                            "{%0,%1,%2,%3}, {%4,%5,%6,%7}, {%8,%9}, {%0,%1,%2,%3};"
                            : "+f"(acc[mi][ni][0]), "+f"(acc[mi][ni][1]),
                              "+f"(acc[mi][ni][2]), "+f"(acc[mi][ni][3])
                            : "r"(af[mi][0]), "r"(af[mi][1]), "r"(af[mi][2]), "r"(af[mi][3]),
                              "r"(bf[ni][0]), "r"(bf[ni][1]));
                    }
            }
        }
    }

#pragma unroll
    for (int mi = 0; mi < 4; mi++) {
        int r0 = m0 + wm + mi * 16 + gid;
        int r1 = r0 + 8;
#pragma unroll
        for (int ni = 0; ni < 4; ni++) {
            int col = n0 + wn + ni * 8 + tig * 2;
            if (col >= N) continue;
            if (C16) {
                if (r0 < M)
                    *(__half2*)(C16 + (size_t)r0 * N + col) =
                        __floats2half2_rn(acc[mi][ni][0], acc[mi][ni][1]);
                if (r1 < M)
                    *(__half2*)(C16 + (size_t)r1 * N + col) =
                        __floats2half2_rn(acc[mi][ni][2], acc[mi][ni][3]);
            } else {
                float bx = 0.f, by = 0.f;
                if (bias) { bx = bias[col]; by = bias[col + 1]; }
                if (r0 < M)
                    *(float2*)(C32 + (size_t)r0 * N + col) =
                        make_float2(acc[mi][ni][0] + bx, acc[mi][ni][1] + by);
                if (r1 < M)
                    *(float2*)(C32 + (size_t)r1 * N + col) =
                        make_float2(acc[mi][ni][2] + bx, acc[mi][ni][3] + by);
            }
        }
    }
}

// ---------------- fused CSR gather GAT + LayerNorm (fp16 xlr): warp per dst node --------
__global__ void gatln_kernel(const __half* __restrict__ xlr,
                             const int* __restrict__ off, const int2* __restrict__ epack,
                             const float* __restrict__ We, const float* __restrict__ att,
                             const float* __restrict__ bias, const float* __restrict__ res,
                             const float* __restrict__ lng, const float* __restrict__ lnb,
                             float* __restrict__ out32, __half* __restrict__ out16, int n) {
    int d = (blockIdx.x * blockDim.x + threadIdx.x) >> 5;
    int lane = threadIdx.x & 31;
    if (d >= n) return;
    float r[8], w[8], t[8];
    {
        uint4 rv = ((const uint4*)(xlr + (size_t)d * 512 + 256))[lane];
        const __half2* hp = (const __half2*)&rv;
#pragma unroll
        for (int k = 0; k < 4; k++) {
            float2 f = __half22float2(hp[k]);
            r[2 * k] = f.x; r[2 * k + 1] = f.y;
        }
        float4 wa = ((const float4*)We)[2 * lane], wb = ((const float4*)We)[2 * lane + 1];
        w[0] = wa.x; w[1] = wa.y; w[2] = wa.z; w[3] = wa.w;
        w[4] = wb.x; w[5] = wb.y; w[6] = wb.z; w[7] = wb.w;
        float4 ta = ((const float4*)att)[2 * lane], tb = ((const float4*)att)[2 * lane + 1];
        t[0] = ta.x; t[1] = ta.y; t[2] = ta.z; t[3] = ta.w;
        t[4] = tb.x; t[5] = tb.y; t[6] = tb.z; t[7] = tb.w;
    }
    float acc[8];
#pragma unroll
    for (int k = 0; k < 8; k++) acc[k] = 0.f;
    float ss = 0.f;
    int beg = off[d], cnt = off[d + 1] - beg;
    const int2* ep = epack + beg;
    if (cnt > 0) {
        int2 pk = ep[0];
        uint4 lv = ((const uint4*)(xlr + (size_t)pk.x * 512))[lane];
        float aa = __int_as_float(pk.y);
        for (int i = 0; i < cnt; i++) {
            uint4 cv = lv;
            float ca = aa;
            if (i + 1 < cnt) {
                int2 p2 = ep[i + 1];
                lv = ((const uint4*)(xlr + (size_t)p2.x * 512))[lane];
                aa = __int_as_float(p2.y);
            }
            float l[8];
            const __half2* hp = (const __half2*)&cv;
#pragma unroll
            for (int k = 0; k < 4; k++) {
                float2 f = __half22float2(hp[k]);
                l[2 * k] = f.x; l[2 * k + 1] = f.y;
            }
            float p = 0.f;
#pragma unroll
            for (int k = 0; k < 8; k++) p += leaky(l[k] + r[k] + ca * w[k]) * t[k];
            p += __shfl_xor_sync(0xffffffffu, p, 1);
            p += __shfl_xor_sync(0xffffffffu, p, 2);
            float e = __expf(p);
#pragma unroll
            for (int k = 0; k < 8; k++) acc[k] += e * l[k];
            ss += e;
        }
    }
    float iv = 1.f / (ss + 1e-16f);
    float v[8];
    {
        float4 ba = ((const float4*)bias)[2 * lane], bb = ((const float4*)bias)[2 * lane + 1];
        v[0] = acc[0] * iv + ba.x; v[1] = acc[1] * iv + ba.y;
        v[2] = acc[2] * iv + ba.z; v[3] = acc[3] * iv + ba.w;
        v[4] = acc[4] * iv + bb.x; v[5] = acc[5] * iv + bb.y;
        v[6] = acc[6] * iv + bb.z; v[7] = acc[7] * iv + bb.w;
    }
    if (res) {
        float4 ra = ((const float4*)(res + (size_t)d * DIM))[2 * lane];
        float4 rb = ((const float4*)(res + (size_t)d * DIM))[2 * lane + 1];
        v[0] += ra.x; v[1] += ra.y; v[2] += ra.z; v[3] += ra.w;
        v[4] += rb.x; v[5] += rb.y; v[6] += rb.z; v[7] += rb.w;
    }
    float sum = 0.f;
#pragma unroll
    for (int k = 0; k < 8; k++) sum += v[k];
    sum = warpReduceSum(sum);
    float mu = sum * (1.f / 256.f);
    float var = 0.f;
#pragma unroll
    for (int k = 0; k < 8; k++) { float dd = v[k] - mu; var += dd * dd; }
    var = warpReduceSum(var) * (1.f / 256.f);
    float inv = rsqrtf(var + 1e-5f);
    float4 ga = ((const float4*)lng)[2 * lane], gb = ((const float4*)lng)[2 * lane + 1];
    float4 ca4 = ((const float4*)lnb)[2 * lane], cb4 = ((const float4*)lnb)[2 * lane + 1];
    float o[8];
    o[0] = (v[0] - mu) * inv * ga.x + ca4.x; o[1] = (v[1] - mu) * inv * ga.y + ca4.y;
    o[2] = (v[2] - mu) * inv * ga.z + ca4.z; o[3] = (v[3] - mu) * inv * ga.w + ca4.w;
    o[4] = (v[4] - mu) * inv * gb.x + cb4.x; o[5] = (v[5] - mu) * inv * gb.y + cb4.y;
    o[6] = (v[6] - mu) * inv * gb.z + cb4.z; o[7] = (v[7] - mu) * inv * gb.w + cb4.w;
    if (out32) {
        float4* op = (float4*)(out32 + (size_t)d * DIM);
        op[2 * lane]     = make_float4(o[0], o[1], o[2], o[3]);
        op[2 * lane + 1] = make_float4(o[4], o[5], o[6], o[7]);
    }
    if (out16) {
        uint4 pk16;
        __half2 h0 = __floats2half2_rn(o[0], o[1]), h1 = __floats2half2_rn(o[2], o[3]);
        __half2 h2 = __floats2half2_rn(o[4], o[5]), h3 = __floats2half2_rn(o[6], o[7]);
        pk16.x = *(uint32_t*)&h0; pk16.y = *(uint32_t*)&h1;
        pk16.z = *(uint32_t*)&h2; pk16.w = *(uint32_t*)&h3;
        ((uint4*)(out16 + (size_t)d * DIM))[lane] = pk16;
    }
}

// ---------------- layernorm (dim=256); optional residual; fp32 + fp16 outputs ----------
__global__ void ln_kernel(const float* __restrict__ x, const float* __restrict__ res,
                          const float* __restrict__ g, const float* __restrict__ b,
                          float* __restrict__ out32, __half* __restrict__ out16, int n) {
    int row = blockIdx.x * 8 + (threadIdx.x >> 5);
    int lane = threadIdx.x & 31;
    if (row >= n) return;
    const float4* xr4 = (const float4*)(x + (size_t)row * DIM);
    const float4* rs4 = res ? (const float4*)(res + (size_t)row * DIM) : nullptr;
    float4 v[2];
    float sum = 0.f;
#pragma unroll
    for (int k = 0; k < 2; k++) {
        int q = k * 32 + lane;
        float4 t = xr4[q];
        if (rs4) { float4 r = rs4[q]; t.x += r.x; t.y += r.y; t.z += r.z; t.w += r.w; }
        v[k] = t;
        sum += t.x + t.y + t.z + t.w;
    }
    sum = warpReduceSum(sum);
    float mu = sum * (1.f / 256.f);
    float var = 0.f;
#pragma unroll
    for (int k = 0; k < 2; k++) {
        float dx = v[k].x - mu, dy = v[k].y - mu, dz = v[k].z - mu, dw = v[k].w - mu;
        var += dx * dx + dy * dy + dz * dz + dw * dw;
    }
    var = warpReduceSum(var) * (1.f / 256.f);
    float inv = rsqrtf(var + 1e-5f);
    const float4* g4 = (const float4*)g;
    const float4* b4 = (const float4*)b;
#pragma unroll
    for (int k = 0; k < 2; k++) {
        int q = k * 32 + lane;
        float4 gg = g4[q], bb = b4[q];
        float4 o = make_float4((v[k].x - mu) * inv * gg.x + bb.x,
                               (v[k].y - mu) * inv * gg.y + bb.y,
                               (v[k].z - mu) * inv * gg.z + bb.z,
                               (v[k].w - mu) * inv * gg.w + bb.w);
        if (out32) ((float4*)(out32 + (size_t)row * DIM))[q] = o;
        if (out16) {
            __half2* o16 = (__half2*)(out16 + (size_t)row * DIM);
            o16[q * 2]     = __floats2half2_rn(o.x, o.y);
            o16[q * 2 + 1] = __floats2half2_rn(o.z, o.w);
        }
    }
}

// ---------------- host ----------------
#define DYN_SMEM (4 * CHUNK_WORDS * sizeof(uint32_t))   // 73728 bytes

static inline void launch_tgemm32(const __half* A, const __half* WT, const float* bias,
                                  float* C, int M, int N, int K) {
    dim3 grid((N + 127) / 128, (M + 127) / 128);
    mma_gemm_h<<<grid, 256, DYN_SMEM>>>(A, WT, bias, C, nullptr, M, N, K);
}
static inline void launch_tgemm16(const __half* A, const __half* WT, __half* C,
                                  int M, int N, int K) {
    dim3 grid((N + 127) / 128, (M + 127) / 128);
    mma_gemm_h<<<grid, 256, DYN_SMEM>>>(A, WT, nullptr, nullptr, C, M, N, K);
}

extern "C" void kernel_launch(void* const* d_in, const int* in_sizes, int n_in,
                              void* d_out, int out_size) {
    cudaFuncSetAttribute(mma_gemm_h, cudaFuncAttributeMaxDynamicSharedMemorySize, DYN_SMEM);

    const float* x_gnn = (const float*)d_in[0];
    const int*   eidx  = (const int*)d_in[1];
    const float* eattr = (const float*)d_in[2];
    const float* W_in  = (const float*)d_in[3];
    const float* b_in  = (const float*)d_in[4];
    const float* Wl1   = (const float*)d_in[5];
    const float* Wr1   = (const float*)d_in[6];
    const float* We1   = (const float*)d_in[7];
    const float* att1  = (const float*)d_in[8];
    const float* bg1   = (const float*)d_in[9];
    const float* ln1_g = (const float*)d_in[10];
    const float* ln1_b = (const float*)d_in[11];
    const float* W_down= (const float*)d_in[12];
    const float* lnd_g = (const float*)d_in[13];
    const float* lnd_b = (const float*)d_in[14];
    const float* Wl2   = (const float*)d_in[15];
    const float* Wr2   = (const float*)d_in[16];
    const float* We2   = (const float*)d_in[17];
    const float* att2  = (const float*)d_in[18];
    const float* bg2   = (const float*)d_in[19];
    const float* ln2_g = (const float*)d_in[20];
    const float* ln2_b = (const float*)d_in[21];
    const float* W_up  = (const float*)d_in[22];
    const float* lnu_g = (const float*)d_in[23];
    const float* lnu_b = (const float*)d_in[24];
    const float* W_cls = (const float*)d_in[25];
    const float* b_cls = (const float*)d_in[26];

    const int n = in_sizes[0] / 18;        // 20000
    const int E = in_sizes[1] / 2;         // 320000
    const int* src = eidx;
    const int* dst = eidx + E;

    float *h1, *z, *tmp;
    __half *xlr, *h0h, *h1h, *zh, *z2h, *outh, *wth;
    int *deg, *cur, *off, *bsum;
    int2 *epack;
    cudaGetSymbolAddress((void**)&xlr, g_xlr);
    cudaGetSymbolAddress((void**)&h1, g_h1);
    cudaGetSymbolAddress((void**)&z, g_z);
    cudaGetSymbolAddress((void**)&tmp, g_tmp);
    cudaGetSymbolAddress((void**)&h0h, g_h0h);
    cudaGetSymbolAddress((void**)&h1h, g_h1h);
    cudaGetSymbolAddress((void**)&zh, g_zh);
    cudaGetSymbolAddress((void**)&z2h, g_z2h);
    cudaGetSymbolAddress((void**)&outh, g_outh);
    cudaGetSymbolAddress((void**)&wth, g_wth);
    cudaGetSymbolAddress((void**)&deg, g_deg);
    cudaGetSymbolAddress((void**)&cur, g_cur);
    cudaGetSymbolAddress((void**)&off, g_off);
    cudaGetSymbolAddress((void**)&bsum, g_bsum);
    cudaGetSymbolAddress((void**)&epack, g_epack);

    float* out_logits = (float*)d_out;
    float* out_h = (float*)d_out + (size_t)n * 1000;

    const int lnBlocks = (n + 7) / 8;
    const int nodeBlocks = (n + 7) / 8;
    const int scanBlocks = (n + SCAN_CHUNK - 1) / SCAN_CHUNK;   // 10

    // ---- fused prologue: zero(deg,cur) + weight transposes + input projection ----
    {
        PrologueArgs pa;
        auto set = [&](int i, const float* in, __half* out, int Kreal, int Kpad, int N, int& cum) {
            pa.d[i].in = in; pa.d[i].out = out;
            pa.d[i].Kreal = Kreal; pa.d[i].Kpad = Kpad; pa.d[i].N = N;
            pa.d[i].blkStart = cum; pa.d[i].nx = (N + 31) / 32;
            cum += pa.d[i].nx * ((Kpad + 31) / 32);
        };
        int cum = 0;
        set(0, Wl1,    wth + WTH_L1,            32, 64, DIM, cum);
        set(1, Wr1,    wth + WTH_L1 + 256 * 64, 32, 64, DIM, cum);
        set(2, W_down, wth + WTH_DN,  DIM, DIM, DIM, cum);
        set(3, Wl2,    wth + WTH_L2,  DIM, DIM, DIM, cum);
        set(4, Wr2,    wth + WTH_L2 + 256 * 256, DIM, DIM, DIM, cum);
        set(5, W_up,   wth + WTH_UP,  DIM, DIM, DIM, cum);
        set(6, W_cls,  wth + WTH_CLS, DIM, DIM, 1000, cum);
        pa.tcum = cum;
        pa.zb = (2 * n + 255) / 256;
        pa.deg = deg; pa.cur = cur;
        pa.x = x_gnn; pa.W_in = W_in; pa.b_in = b_in; pa.h0h = h0h;
        pa.n = n;
        int total = pa.zb + cum + (n + 7) / 8;
        prologue_kernel<<<total, 256>>>(pa);
    }

    // ---- GAT layer 1 GEMM (independent of CSR) ----
    launch_tgemm16(h0h, wth + WTH_L1, xlr, n, 512, 64);

    // ---- CSR build (parallel scan) ----
    hist_kernel<<<(E + 255) / 256, 256>>>(dst, deg, E);
    scan_part_kernel<<<scanBlocks, 256>>>(deg, off, bsum, n);
    scan_fix_kernel<<<scanBlocks, 256>>>(off, bsum, n, E);
    scatter_kernel<<<(E + 255) / 256, 256>>>(src, dst, eattr, off, cur, epack, E);

    // ---- GAT layer 1 gather+LN ----
    gatln_kernel<<<nodeBlocks, 256>>>(xlr, off, epack, We1, att1, bg1,
                                      nullptr, ln1_g, ln1_b, h1, h1h, n);

    // ---- bottleneck down ----
    launch_tgemm32(h1h, wth + WTH_DN, nullptr, tmp, n, DIM, DIM);
    ln_kernel<<<lnBlocks, 256>>>(tmp, nullptr, lnd_g, lnd_b, z, zh, n);

    // ---- GAT layer 2 (residual z inside fused gather-LN) ----
    launch_tgemm16(zh, wth + WTH_L2, xlr, n, 512, DIM);
    gatln_kernel<<<nodeBlocks, 256>>>(xlr, off, epack, We2, att2, bg2,
                                      z, ln2_g, ln2_b, nullptr, z2h, n);

    // ---- up projection + final LN ----
    launch_tgemm32(z2h, wth + WTH_UP, nullptr, tmp, n, DIM, DIM);
    ln_kernel<<<lnBlocks, 256>>>(tmp, h1, lnu_g, lnu_b, out_h, outh, n);

    // ---- classifier ----
    launch_tgemm32(outh, wth + WTH_CLS, b_cls, out_logits, n, 1000, DIM);
}